// round 1
// baseline (speedup 1.0000x reference)
#include <cuda_runtime.h>
#include <math.h>
#include <stdint.h>

// Problem constants
#define NS 2048          // nodes per domain
#define DD 256           // feature dim
#define NF 4096          // concat features for supcon
#define NELEM ((size_t)NS*(size_t)NS)

// ----------------------------------------------------------------------------
// Static device scratch (allocation-free rule)
// ----------------------------------------------------------------------------
__device__ float g_x0s[NS*DD];
__device__ float g_x0t[NS*DD];
__device__ float g_x1s[NS*DD];
__device__ float g_x1t[NS*DD];
__device__ float g_x2s[NS*DD];
__device__ float g_x2t[NS*DD];
__device__ float g_q[NS*DD];
__device__ float g_k[NS*DD];
__device__ float g_v[NS*DD];
__device__ float g_vw[NS*DD];
__device__ float g_S[NS*NS];                 // 16 MB: scores, then affinity M
__device__ float g_L[(size_t)NF*(size_t)NF]; // 64 MB: supcon logits
__device__ float g_fn[NF*DD];
__device__ float g_rowinv[NS];
__device__ float g_r[NS];
__device__ float g_c[NS];
__device__ float g_stats[2];                 // mu, inv(std+1e-5)
__device__ double g_dacc[4];                 // sum, sumsq, match, supcon
__device__ int   g_hist[16];

// ----------------------------------------------------------------------------
// Block reduction helpers (blockDim.x == 256, 1-D)
// ----------------------------------------------------------------------------
__device__ __forceinline__ float bsum256(float v, float* red){
    int tid = threadIdx.x;
    red[tid] = v; __syncthreads();
    #pragma unroll
    for (int off = 128; off > 0; off >>= 1){
        if (tid < off) red[tid] += red[tid + off];
        __syncthreads();
    }
    float r = red[0]; __syncthreads();
    return r;
}
__device__ __forceinline__ float bmax256(float v, float* red){
    int tid = threadIdx.x;
    red[tid] = v; __syncthreads();
    #pragma unroll
    for (int off = 128; off > 0; off >>= 1){
        if (tid < off) red[tid] = fmaxf(red[tid], red[tid + off]);
        __syncthreads();
    }
    float r = red[0]; __syncthreads();
    return r;
}

// ----------------------------------------------------------------------------
// head_in: y = LN(ReLU(LN(x@w1+b1)) @ w2 + b2), 4 rows per block
// ----------------------------------------------------------------------------
__global__ __launch_bounds__(256)
void head_kernel(const float* __restrict__ X,
                 const float* __restrict__ W1, const float* __restrict__ B1,
                 const float* __restrict__ W2, const float* __restrict__ B2,
                 float* __restrict__ O){
    __shared__ float Xs[4][DD];
    __shared__ float Hs[4][DD];
    __shared__ float red[256];
    int tid = threadIdx.x;
    int row0 = blockIdx.x * 4;

    #pragma unroll
    for (int r = 0; r < 4; r++)
        Xs[r][tid] = X[(size_t)(row0 + r)*DD + tid];
    __syncthreads();

    float acc[4] = {0.f,0.f,0.f,0.f};
    for (int k = 0; k < DD; k++){
        float w = W1[k*DD + tid];
        #pragma unroll
        for (int r = 0; r < 4; r++) acc[r] += Xs[r][k] * w;
    }
    float bb = B1[tid];
    #pragma unroll
    for (int r = 0; r < 4; r++) acc[r] += bb;

    // LN + ReLU per row
    for (int r = 0; r < 4; r++){
        float s  = bsum256(acc[r], red);
        float ss = bsum256(acc[r]*acc[r], red);
        float m  = s * (1.f/DD);
        float var = ss * (1.f/DD) - m*m;
        float h = (acc[r] - m) * rsqrtf(var + 1e-5f);
        Hs[r][tid] = fmaxf(h, 0.f);
    }
    __syncthreads();

    float acc2[4] = {0.f,0.f,0.f,0.f};
    for (int k = 0; k < DD; k++){
        float w = W2[k*DD + tid];
        #pragma unroll
        for (int r = 0; r < 4; r++) acc2[r] += Hs[r][k] * w;
    }
    float bb2 = B2[tid];
    #pragma unroll
    for (int r = 0; r < 4; r++) acc2[r] += bb2;

    for (int r = 0; r < 4; r++){
        float s  = bsum256(acc2[r], red);
        float ss = bsum256(acc2[r]*acc2[r], red);
        float m  = s * (1.f/DD);
        float var = ss * (1.f/DD) - m*m;
        O[(size_t)(row0 + r)*DD + tid] = (acc2[r] - m) * rsqrtf(var + 1e-5f);
    }
}

// ----------------------------------------------------------------------------
// C[M,256] = A[M,256] @ W[256,256]   (8 rows per block, 256 blocks at M=2048)
// ----------------------------------------------------------------------------
__global__ __launch_bounds__(256)
void gemm_aw(const float* __restrict__ A, const float* __restrict__ W,
             float* __restrict__ C, int M){
    __shared__ float Xs[8][DD];
    int tid = threadIdx.x;
    int row0 = blockIdx.x * 8;
    #pragma unroll
    for (int r = 0; r < 8; r++)
        Xs[r][tid] = A[(size_t)(row0 + r)*DD + tid];
    __syncthreads();
    float acc[8] = {0,0,0,0,0,0,0,0};
    #pragma unroll 4
    for (int k = 0; k < DD; k++){
        float w = W[k*DD + tid];
        #pragma unroll
        for (int r = 0; r < 8; r++) acc[r] += Xs[r][k] * w;
    }
    #pragma unroll
    for (int r = 0; r < 8; r++)
        C[(size_t)(row0 + r)*DD + tid] = acc[r];
}

// ----------------------------------------------------------------------------
// NT GEMM: C[M,N] = scale * A[M,K] @ B[N,K]^T   (128x128x16 tiles, 8x8/thread)
// M,N multiples of 128, K multiple of 16
// ----------------------------------------------------------------------------
__global__ __launch_bounds__(256, 2)
void gemm_nt(const float* __restrict__ A, const float* __restrict__ B,
             float* __restrict__ C, int M, int N, int K, float scale){
    __shared__ float As[16][128];
    __shared__ float Bs[16][128];
    int tid = threadIdx.x;
    int tx = tid & 15, ty = tid >> 4;
    int row0 = blockIdx.y * 128, col0 = blockIdx.x * 128;

    float acc[8][8];
    #pragma unroll
    for (int i = 0; i < 8; i++)
        #pragma unroll
        for (int j = 0; j < 8; j++) acc[i][j] = 0.f;

    for (int kc = 0; kc < K; kc += 16){
        #pragma unroll
        for (int t = 0; t < 2; t++){
            int lin = tid + t*256;           // 0..511 float4 slots
            int r   = lin >> 2;              // 0..127
            int c4  = (lin & 3) << 2;        // 0,4,8,12
            float4 va = *(const float4*)(A + (size_t)(row0 + r)*K + kc + c4);
            As[c4+0][r]=va.x; As[c4+1][r]=va.y; As[c4+2][r]=va.z; As[c4+3][r]=va.w;
            float4 vb = *(const float4*)(B + (size_t)(col0 + r)*K + kc + c4);
            Bs[c4+0][r]=vb.x; Bs[c4+1][r]=vb.y; Bs[c4+2][r]=vb.z; Bs[c4+3][r]=vb.w;
        }
        __syncthreads();
        #pragma unroll
        for (int kk = 0; kk < 16; kk++){
            float a[8], b[8];
            *(float4*)(a)   = *(const float4*)&As[kk][ty*8];
            *(float4*)(a+4) = *(const float4*)&As[kk][ty*8+4];
            *(float4*)(b)   = *(const float4*)&Bs[kk][tx*8];
            *(float4*)(b+4) = *(const float4*)&Bs[kk][tx*8+4];
            #pragma unroll
            for (int i = 0; i < 8; i++)
                #pragma unroll
                for (int j = 0; j < 8; j++)
                    acc[i][j] += a[i]*b[j];
        }
        __syncthreads();
    }
    #pragma unroll
    for (int i = 0; i < 8; i++){
        float* cp = C + (size_t)(row0 + ty*8 + i)*N + col0 + tx*8;
        float4 o0 = make_float4(acc[i][0]*scale, acc[i][1]*scale, acc[i][2]*scale, acc[i][3]*scale);
        float4 o1 = make_float4(acc[i][4]*scale, acc[i][5]*scale, acc[i][6]*scale, acc[i][7]*scale);
        *(float4*)cp = o0;
        *(float4*)(cp+4) = o1;
    }
}

// ----------------------------------------------------------------------------
// NN GEMM with split-K atomics: C[M,N] += (rs[m]*A[M,K]) @ B[K,N]
// 64x64x16 tiles, 4x4/thread. C must be pre-initialized (residual).
// ----------------------------------------------------------------------------
__global__ __launch_bounds__(256)
void gemm_nn_atomic(const float* __restrict__ A, const float* __restrict__ B,
                    float* C, const float* __restrict__ rs,
                    int M, int N, int K, int Kchunk){
    __shared__ float As[16][64];
    __shared__ float Bs[16][64];
    int tid = threadIdx.x;
    int tx = tid & 15, ty = tid >> 4;
    int row0 = blockIdx.y * 64, col0 = blockIdx.x * 64;
    int k0 = blockIdx.z * Kchunk, k1 = k0 + Kchunk;

    float acc[4][4];
    #pragma unroll
    for (int i = 0; i < 4; i++)
        #pragma unroll
        for (int j = 0; j < 4; j++) acc[i][j] = 0.f;

    int ar = tid >> 2;             // 0..63
    int ac4 = (tid & 3) << 2;      // 0,4,8,12
    float sc = rs ? rs[row0 + ar] : 1.0f;
    int bkr = tid >> 4;            // 0..15
    int bc4 = (tid & 15) << 2;     // 0..60

    for (int kc = k0; kc < k1; kc += 16){
        float4 va = *(const float4*)(A + (size_t)(row0 + ar)*K + kc + ac4);
        As[ac4+0][ar]=va.x*sc; As[ac4+1][ar]=va.y*sc; As[ac4+2][ar]=va.z*sc; As[ac4+3][ar]=va.w*sc;
        float4 vb = *(const float4*)(B + (size_t)(kc + bkr)*N + col0 + bc4);
        Bs[bkr][bc4+0]=vb.x; Bs[bkr][bc4+1]=vb.y; Bs[bkr][bc4+2]=vb.z; Bs[bkr][bc4+3]=vb.w;
        __syncthreads();
        #pragma unroll
        for (int kk = 0; kk < 16; kk++){
            float a[4], b[4];
            *(float4*)a = *(const float4*)&As[kk][ty*4];
            *(float4*)b = *(const float4*)&Bs[kk][tx*4];
            #pragma unroll
            for (int i = 0; i < 4; i++)
                #pragma unroll
                for (int j = 0; j < 4; j++)
                    acc[i][j] += a[i]*b[j];
        }
        __syncthreads();
    }
    #pragma unroll
    for (int i = 0; i < 4; i++)
        #pragma unroll
        for (int j = 0; j < 4; j++)
            atomicAdd(&C[(size_t)(row0 + ty*4 + i)*N + col0 + tx*4 + j], acc[i][j]);
}

// ----------------------------------------------------------------------------
// Row softmax over S (stores exp(s-max), rowinv = 1/sum)
// ----------------------------------------------------------------------------
__global__ __launch_bounds__(256)
void softmax_rows(float* __restrict__ S, float* __restrict__ rowinv, int N){
    __shared__ float red[256];
    int row = blockIdx.x, tid = threadIdx.x;
    float* rp = S + (size_t)row*N;
    float m = -1e30f;
    for (int j = tid; j < N; j += 256) m = fmaxf(m, rp[j]);
    m = bmax256(m, red);
    float s = 0.f;
    for (int j = tid; j < N; j += 256){
        float e = __expf(rp[j] - m);
        rp[j] = e;
        s += e;
    }
    s = bsum256(s, red);
    if (tid == 0) rowinv[row] = 1.0f / s;
}

// ----------------------------------------------------------------------------
// Mean/var reduction of M (4M elements) into doubles
// ----------------------------------------------------------------------------
__global__ __launch_bounds__(256)
void stats_reduce(const float* __restrict__ Mm, double* acc){
    __shared__ float red[256];
    float s = 0.f, ss = 0.f;
    for (size_t idx = (size_t)blockIdx.x*256 + threadIdx.x; idx < NELEM; idx += (size_t)gridDim.x*256){
        float v = Mm[idx];
        s += v; ss += v*v;
    }
    s = bsum256(s, red);
    float ss2 = bsum256(ss, red);
    if (threadIdx.x == 0){
        atomicAdd(acc + 0, (double)s);
        atomicAdd(acc + 1, (double)ss2);
    }
}

__global__ void finalize_stats(const double* acc, float* stats){
    if (threadIdx.x == 0 && blockIdx.x == 0){
        double n = (double)NELEM;
        double mu = acc[0] / n;
        double var = acc[1] / n - mu*mu;
        stats[0] = (float)mu;
        stats[1] = (float)(1.0 / (sqrt(var) + 1e-5));
    }
}

// ----------------------------------------------------------------------------
// Sinkhorn passes (lazy potentials r, c); B_ij = (M_ij - mu)*inv
// ----------------------------------------------------------------------------
__global__ __launch_bounds__(256)
void sink_row(const float* __restrict__ Mm, const float* __restrict__ stats,
              const float* __restrict__ c, float* __restrict__ r){
    __shared__ float red[256];
    int i = blockIdx.x, tid = threadIdx.x;
    float mu = stats[0], inv = stats[1];
    const float* row = Mm + (size_t)i*NS;
    float m = -1e30f;
    for (int j = tid; j < NS; j += 256)
        m = fmaxf(m, (row[j]-mu)*inv - c[j]);
    m = bmax256(m, red);
    float s = 0.f;
    for (int j = tid; j < NS; j += 256)
        s += __expf((row[j]-mu)*inv - c[j] - m);
    s = bsum256(s, red);
    if (tid == 0) r[i] = m + logf(s);
}

__global__ void sink_col(const float* __restrict__ Mm, const float* __restrict__ stats,
                         const float* __restrict__ r, float* __restrict__ c){
    __shared__ float red[32][8];
    int tx = threadIdx.x, ty = threadIdx.y;        // (8,32)
    int j = blockIdx.x*8 + tx;
    float mu = stats[0], inv = stats[1];
    float m = -1e30f;
    for (int i = ty; i < NS; i += 32)
        m = fmaxf(m, (Mm[(size_t)i*NS + j]-mu)*inv - r[i]);
    red[ty][tx] = m; __syncthreads();
    #pragma unroll
    for (int off = 16; off > 0; off >>= 1){
        if (ty < off) red[ty][tx] = fmaxf(red[ty][tx], red[ty+off][tx]);
        __syncthreads();
    }
    m = red[0][tx]; __syncthreads();
    float s = 0.f;
    for (int i = ty; i < NS; i += 32)
        s += __expf((Mm[(size_t)i*NS + j]-mu)*inv - r[i] - m);
    red[ty][tx] = s; __syncthreads();
    #pragma unroll
    for (int off = 16; off > 0; off >>= 1){
        if (ty < off) red[ty][tx] += red[ty+off][tx];
        __syncthreads();
    }
    if (ty == 0) c[j] = m + logf(red[0][tx]);
}

// ----------------------------------------------------------------------------
// Matching loss: sum |exp(B - r - c) - gt|
// ----------------------------------------------------------------------------
__global__ __launch_bounds__(256)
void match_kernel(const float* __restrict__ Mm, const float* __restrict__ r,
                  const float* __restrict__ c, const int* __restrict__ ls,
                  const int* __restrict__ lt, const float* __restrict__ stats,
                  double* acc){
    __shared__ float red[256];
    int i = blockIdx.x, tid = threadIdx.x;
    float mu = stats[0], inv = stats[1];
    float ri = r[i];
    int li = ls[i];
    const float* row = Mm + (size_t)i*NS;
    float s = 0.f;
    for (int j = tid; j < NS; j += 256){
        float p = __expf((row[j]-mu)*inv - ri - c[j]);
        float gt = (li == lt[j]) ? 1.f : 0.f;
        s += fabsf(p - gt);
    }
    s = bsum256(s, red);
    if (tid == 0) atomicAdd(acc + 2, (double)s);
}

// ----------------------------------------------------------------------------
// SupCon: fnorm, histogram, row reduction over logits
// ----------------------------------------------------------------------------
__global__ __launch_bounds__(256)
void fnorm_kernel(const float* __restrict__ s2, const float* __restrict__ t2,
                  float* __restrict__ F){
    __shared__ float red[256];
    int i = blockIdx.x, tid = threadIdx.x;
    const float* src = (i < NS) ? (s2 + (size_t)i*DD) : (t2 + (size_t)(i-NS)*DD);
    float x = src[tid];
    float ss = bsum256(x*x, red);
    F[(size_t)i*DD + tid] = x / (sqrtf(ss) + 1e-8f);
}

__global__ void hist_kernel(const int* __restrict__ ls, const int* __restrict__ lt,
                            int* hist){
    int idx = blockIdx.x*blockDim.x + threadIdx.x;
    if (idx < NF){
        int l = (idx < NS) ? ls[idx] : lt[idx-NS];
        atomicAdd(&hist[l], 1);
    }
}

__global__ __launch_bounds__(256)
void supcon_row(const float* __restrict__ L, const int* __restrict__ ls,
                const int* __restrict__ lt, const int* __restrict__ hist,
                double* acc){
    __shared__ float red[256];
    int i = blockIdx.x, tid = threadIdx.x;
    int li = (i < NS) ? ls[i] : lt[i-NS];
    const float* row = L + (size_t)i*NF;
    float e = 0.f, s = 0.f;
    for (int j = tid; j < NF; j += 256){
        if (j == i) continue;
        float l = row[j];
        e += __expf(l);
        int lj = (j < NS) ? ls[j] : lt[j-NS];
        if (lj == li) s += l;
    }
    e = bsum256(e, red);
    s = bsum256(s, red);
    if (tid == 0){
        float cnt = (float)(hist[li] - 1);
        float loss_i = s / cnt - logf(e);
        atomicAdd(acc + 3, (double)loss_i);
    }
}

__global__ void finalize_kernel(const double* acc, float* out){
    if (threadIdx.x == 0 && blockIdx.x == 0){
        double supcon = -(acc[3] / (double)NF);
        out[0] = (float)(acc[2] + 0.1 * supcon);
    }
}

// ----------------------------------------------------------------------------
// Host driver
// ----------------------------------------------------------------------------
extern "C" void kernel_launch(void* const* d_in, const int* in_sizes, int n_in,
                              void* d_out, int out_size){
    const float* nodes_src = (const float*)d_in[0];
    const float* nodes_tgt = (const float*)d_in[1];
    const int*   labels_src = (const int*)d_in[2];
    const int*   labels_tgt = (const int*)d_in[3];
    const float* w1 = (const float*)d_in[4];
    const float* b1 = (const float*)d_in[5];
    const float* w2 = (const float*)d_in[6];
    const float* b2 = (const float*)d_in[7];
    const float* wq = (const float*)d_in[8];
    const float* wk = (const float*)d_in[9];
    const float* wv = (const float*)d_in[10];
    const float* wo = (const float*)d_in[11];
    const float* cq = (const float*)d_in[12];
    const float* ck = (const float*)d_in[13];
    const float* cv = (const float*)d_in[14];
    const float* co = (const float*)d_in[15];
    const float* Am = (const float*)d_in[16];

    float *x0s,*x0t,*x1s,*x1t,*x2s,*x2t,*qb,*kb,*vb,*vwb,*S,*Lg,*fn,*rowinv,*rv,*cv_,*stats;
    double* dacc; int* hist;
    cudaGetSymbolAddress((void**)&x0s, g_x0s);
    cudaGetSymbolAddress((void**)&x0t, g_x0t);
    cudaGetSymbolAddress((void**)&x1s, g_x1s);
    cudaGetSymbolAddress((void**)&x1t, g_x1t);
    cudaGetSymbolAddress((void**)&x2s, g_x2s);
    cudaGetSymbolAddress((void**)&x2t, g_x2t);
    cudaGetSymbolAddress((void**)&qb,  g_q);
    cudaGetSymbolAddress((void**)&kb,  g_k);
    cudaGetSymbolAddress((void**)&vb,  g_v);
    cudaGetSymbolAddress((void**)&vwb, g_vw);
    cudaGetSymbolAddress((void**)&S,   g_S);
    cudaGetSymbolAddress((void**)&Lg,  g_L);
    cudaGetSymbolAddress((void**)&fn,  g_fn);
    cudaGetSymbolAddress((void**)&rowinv, g_rowinv);
    cudaGetSymbolAddress((void**)&rv,  g_r);
    cudaGetSymbolAddress((void**)&cv_, g_c);
    cudaGetSymbolAddress((void**)&stats, g_stats);
    cudaGetSymbolAddress((void**)&dacc, g_dacc);
    cudaGetSymbolAddress((void**)&hist, g_hist);

    // Reset accumulators (graph-capturable async memsets)
    cudaMemsetAsync(cv_, 0, NS*sizeof(float));
    cudaMemsetAsync(dacc, 0, 4*sizeof(double));
    cudaMemsetAsync(hist, 0, 16*sizeof(int));

    // head_in on both domains
    head_kernel<<<NS/4, 256>>>(nodes_src, w1, b1, w2, b2, x0s);
    head_kernel<<<NS/4, 256>>>(nodes_tgt, w1, b1, w2, b2, x0t);

    // One attention block: out = res + softmax(qin@Wq @ (kvin@Wk)^T / 16) @ (kvin@Wv@Wo)
    auto attn = [&](const float* q_in, const float* kv_in,
                    const float* Wq, const float* Wk, const float* Wv, const float* Wo,
                    const float* res, float* outp){
        gemm_aw<<<NS/8, 256>>>(q_in,  Wq, qb, NS);
        gemm_aw<<<NS/8, 256>>>(kv_in, Wk, kb, NS);
        gemm_aw<<<NS/8, 256>>>(kv_in, Wv, vb, NS);
        gemm_aw<<<NS/8, 256>>>(vb,    Wo, vwb, NS);   // fold Wo: V@Wo
        gemm_nt<<<dim3(NS/128, NS/128), 256>>>(qb, kb, S, NS, NS, DD, 0.0625f);
        softmax_rows<<<NS, 256>>>(S, rowinv, NS);
        cudaMemcpyAsync(outp, res, (size_t)NS*DD*sizeof(float), cudaMemcpyDeviceToDevice);
        gemm_nn_atomic<<<dim3(DD/64, NS/64, 4), 256>>>(S, vwb, outp, rowinv, NS, DD, NS, NS/4);
    };

    // intra-domain
    attn(x0s, x0s, wq, wk, wv, wo, x0s, x1s);
    attn(x0t, x0t, wq, wk, wv, wo, x0t, x1t);
    // cross-domain
    attn(x1s, x1t, cq, ck, cv, co, x1s, x2s);
    attn(x1t, x1s, cq, ck, cv, co, x1t, x2t);

    // affinity M = (src2 @ A) @ tgt2^T  (reuse qb for src2@A)
    gemm_aw<<<NS/8, 256>>>(x2s, Am, qb, NS);
    gemm_nt<<<dim3(NS/128, NS/128), 256>>>(qb, x2t, S, NS, NS, DD, 1.0f);

    // instance norm stats
    stats_reduce<<<2048, 256>>>(S, dacc);
    finalize_stats<<<1, 32>>>(dacc, stats);

    // Sinkhorn (lazy potentials)
    for (int it = 0; it < 10; it++){
        sink_row<<<NS, 256>>>(S, stats, cv_, rv);
        sink_col<<<NS/8, dim3(8,32)>>>(S, stats, rv, cv_);
    }
    match_kernel<<<NS, 256>>>(S, rv, cv_, labels_src, labels_tgt, stats, dacc);

    // SupCon
    fnorm_kernel<<<NF, 256>>>(x2s, x2t, fn);
    hist_kernel<<<16, 256>>>(labels_src, labels_tgt, hist);
    gemm_nt<<<dim3(NF/128, NF/128), 256>>>(fn, fn, Lg, NF, NF, DD, 14.2857142857142857f);
    supcon_row<<<NF, 256>>>(Lg, labels_src, labels_tgt, hist, dacc);

    finalize_kernel<<<1, 32>>>(dacc, (float*)d_out);
}

// round 2
// speedup vs baseline: 1.3469x; 1.3469x over previous
#include <cuda_runtime.h>
#include <math.h>
#include <stdint.h>

#define NS 2048
#define DD 256
#define NF 4096
#define HALF ((size_t)NS*DD)
#define NELEM ((size_t)NS*(size_t)NS)
#define SUPCON_SCALE 14.285714285714286f   // 1/0.07

// ----------------------------------------------------------------------------
// Static device scratch
// ----------------------------------------------------------------------------
__device__ float g_in [NF*DD];
__device__ float g_x0 [NF*DD];
__device__ float g_x1 [NF*DD];
__device__ float g_x2 [NF*DD];
__device__ float g_q  [NF*DD];
__device__ float g_vw [NF*DD];
__device__ float g_fn [NF*DD];
__device__ float g_S0 [NELEM];
__device__ float g_S1 [NELEM];
__device__ float g_Wp [4][DD*DD];   // Wqk_i, Wvo_i, Wqk_c, Wvo_c
__device__ float g_rsum[NF];
__device__ float g_r[NS];
__device__ float g_c[NS];
__device__ float g_esum[NF];
__device__ float g_psum[NF];
__device__ float g_stats[2];
__device__ double g_dacc[4];        // sum, sumsq, match, supcon
__device__ int   g_lab[NF];
__device__ int   g_hist[16];

// ----------------------------------------------------------------------------
// Fast exp: e^x via 2^t with degree-5 polynomial (FMA pipe, no MUFU)
// valid for |x| < ~87; returns 0 below -87.
// ----------------------------------------------------------------------------
__device__ __forceinline__ float fexp(float x){
    float t = x * 1.4426950408889634f;
    float r = rintf(t);
    float f = t - r;
    float p =            1.3333558146e-3f;
    p = fmaf(p, f, 9.6181291076e-3f);
    p = fmaf(p, f, 5.5504108664e-2f);
    p = fmaf(p, f, 2.4022650696e-1f);
    p = fmaf(p, f, 6.9314718056e-1f);
    p = fmaf(p, f, 1.0f);
    float res = __int_as_float(__float_as_int(p) + (((int)r) << 23));
    return (x < -87.0f) ? 0.0f : res;
}

// ----------------------------------------------------------------------------
// Block reductions (blockDim.x == 256)
// ----------------------------------------------------------------------------
__device__ __forceinline__ float bsum256(float v, float* red){
    int tid = threadIdx.x;
    red[tid] = v; __syncthreads();
    #pragma unroll
    for (int off = 128; off > 0; off >>= 1){
        if (tid < off) red[tid] += red[tid + off];
        __syncthreads();
    }
    float r = red[0]; __syncthreads();
    return r;
}

// ----------------------------------------------------------------------------
// gemm_aw (tiny: used only for 256x256 weight precompute)  C = A@W
// ----------------------------------------------------------------------------
__global__ __launch_bounds__(256)
void gemm_aw(const float* __restrict__ A, const float* __restrict__ W,
             float* __restrict__ C, int M){
    __shared__ float Xs[8][DD];
    int tid = threadIdx.x;
    int row0 = blockIdx.x * 8;
    #pragma unroll
    for (int r = 0; r < 8; r++)
        Xs[r][tid] = A[(size_t)(row0 + r)*DD + tid];
    __syncthreads();
    float acc[8] = {0,0,0,0,0,0,0,0};
    #pragma unroll 4
    for (int k = 0; k < DD; k++){
        float w = W[k*DD + tid];
        #pragma unroll
        for (int r = 0; r < 8; r++) acc[r] += Xs[r][k] * w;
    }
    #pragma unroll
    for (int r = 0; r < 8; r++)
        C[(size_t)(row0 + r)*DD + tid] = acc[r];
}

// ----------------------------------------------------------------------------
// gemm_nt (plain; used for 256x256 Wq@Wk^T precompute): C = scale*A@B^T
// ----------------------------------------------------------------------------
__global__ __launch_bounds__(256, 2)
void gemm_nt(const float* __restrict__ A, const float* __restrict__ B,
             float* __restrict__ C, int M, int N, int K, float scale){
    __shared__ float As[16][128];
    __shared__ float Bs[16][128];
    int tid = threadIdx.x;
    int tx = tid & 15, ty = tid >> 4;
    int row0 = blockIdx.y * 128, col0 = blockIdx.x * 128;
    float acc[8][8];
    #pragma unroll
    for (int i = 0; i < 8; i++)
        #pragma unroll
        for (int j = 0; j < 8; j++) acc[i][j] = 0.f;
    for (int kc = 0; kc < K; kc += 16){
        #pragma unroll
        for (int t = 0; t < 2; t++){
            int lin = tid + t*256;
            int r = lin >> 2, c4 = (lin & 3) << 2;
            float4 va = *(const float4*)(A + (size_t)(row0 + r)*K + kc + c4);
            As[c4+0][r]=va.x; As[c4+1][r]=va.y; As[c4+2][r]=va.z; As[c4+3][r]=va.w;
            float4 vb = *(const float4*)(B + (size_t)(col0 + r)*K + kc + c4);
            Bs[c4+0][r]=vb.x; Bs[c4+1][r]=vb.y; Bs[c4+2][r]=vb.z; Bs[c4+3][r]=vb.w;
        }
        __syncthreads();
        #pragma unroll
        for (int kk = 0; kk < 16; kk++){
            float a[8], b[8];
            *(float4*)(a)   = *(const float4*)&As[kk][ty*8];
            *(float4*)(a+4) = *(const float4*)&As[kk][ty*8+4];
            *(float4*)(b)   = *(const float4*)&Bs[kk][tx*8];
            *(float4*)(b+4) = *(const float4*)&Bs[kk][tx*8+4];
            #pragma unroll
            for (int i = 0; i < 8; i++)
                #pragma unroll
                for (int j = 0; j < 8; j++)
                    acc[i][j] += a[i]*b[j];
        }
        __syncthreads();
    }
    #pragma unroll
    for (int i = 0; i < 8; i++){
        float* cp = C + (size_t)(row0 + ty*8 + i)*N + col0 + tx*8;
        float4 o0 = make_float4(acc[i][0]*scale, acc[i][1]*scale, acc[i][2]*scale, acc[i][3]*scale);
        float4 o1 = make_float4(acc[i][4]*scale, acc[i][5]*scale, acc[i][6]*scale, acc[i][7]*scale);
        *(float4*)cp = o0; *(float4*)(cp+4) = o1;
    }
}

// ----------------------------------------------------------------------------
// gemm_nn: C = A[M,K]@B[K,N] (+bias). 64x64 tile, 4x4/thread. M%64==0, N%64==0, K%16==0
// ----------------------------------------------------------------------------
__global__ __launch_bounds__(256, 3)
void gemm_nn(const float* __restrict__ A, const float* __restrict__ B,
             const float* __restrict__ bias, float* __restrict__ C,
             int M, int N, int K){
    __shared__ float As[16][64];
    __shared__ float Bs[16][64];
    int tid = threadIdx.x;
    int tx = tid & 15, ty = tid >> 4;
    int row0 = blockIdx.y * 64, col0 = blockIdx.x * 64;
    int ar = tid >> 2, ac4 = (tid & 3) << 2;
    int bkr = tid >> 4, bc4 = (tid & 15) << 2;
    float acc[4][4];
    #pragma unroll
    for (int i = 0; i < 4; i++)
        #pragma unroll
        for (int j = 0; j < 4; j++) acc[i][j] = 0.f;
    for (int kc = 0; kc < K; kc += 16){
        float4 va = *(const float4*)(A + (size_t)(row0+ar)*K + kc + ac4);
        As[ac4+0][ar]=va.x; As[ac4+1][ar]=va.y; As[ac4+2][ar]=va.z; As[ac4+3][ar]=va.w;
        float4 vb = *(const float4*)(B + (size_t)(kc+bkr)*N + col0 + bc4);
        *(float4*)&Bs[bkr][bc4] = vb;
        __syncthreads();
        #pragma unroll
        for (int kk = 0; kk < 16; kk++){
            float a[4], b[4];
            *(float4*)a = *(const float4*)&As[kk][ty*4];
            *(float4*)b = *(const float4*)&Bs[kk][tx*4];
            #pragma unroll
            for (int i = 0; i < 4; i++)
                #pragma unroll
                for (int j = 0; j < 4; j++)
                    acc[i][j] += a[i]*b[j];
        }
        __syncthreads();
    }
    #pragma unroll
    for (int i = 0; i < 4; i++){
        float bv[4];
        #pragma unroll
        for (int j = 0; j < 4; j++)
            bv[j] = bias ? bias[col0 + tx*4 + j] : 0.f;
        float4 o = make_float4(acc[i][0]+bv[0], acc[i][1]+bv[1], acc[i][2]+bv[2], acc[i][3]+bv[3]);
        *(float4*)(C + (size_t)(row0 + ty*4 + i)*N + col0 + tx*4) = o;
    }
}

// ----------------------------------------------------------------------------
// gemm_pv: out = res + (diag(1/rs) * S) @ B    (z in {0,1} picks the pair)
// S: [2048,2048], B: [2048,256]. 64x64 tiles.
// ----------------------------------------------------------------------------
__global__ __launch_bounds__(256, 3)
void gemm_pv(const float* __restrict__ S0, const float* __restrict__ B0,
             const float* __restrict__ S1, const float* __restrict__ B1,
             const float* __restrict__ rsum,
             const float* __restrict__ res, float* __restrict__ out){
    __shared__ float As[16][64];
    __shared__ float Bs[16][64];
    int z = blockIdx.z;
    const float* A = z ? S1 : S0;
    const float* B = z ? B1 : B0;
    const float* rs = rsum + z*NS;
    const float* R  = res + (size_t)z*HALF;
    float* O        = out + (size_t)z*HALF;

    int tid = threadIdx.x;
    int tx = tid & 15, ty = tid >> 4;
    int row0 = blockIdx.y * 64, col0 = blockIdx.x * 64;
    int ar = tid >> 2, ac4 = (tid & 3) << 2;
    int bkr = tid >> 4, bc4 = (tid & 15) << 2;
    float sc = 1.0f / rs[row0 + ar];
    float acc[4][4];
    #pragma unroll
    for (int i = 0; i < 4; i++)
        #pragma unroll
        for (int j = 0; j < 4; j++) acc[i][j] = 0.f;
    for (int kc = 0; kc < NS; kc += 16){
        float4 va = *(const float4*)(A + (size_t)(row0+ar)*NS + kc + ac4);
        As[ac4+0][ar]=va.x*sc; As[ac4+1][ar]=va.y*sc; As[ac4+2][ar]=va.z*sc; As[ac4+3][ar]=va.w*sc;
        float4 vb = *(const float4*)(B + (size_t)(kc+bkr)*DD + col0 + bc4);
        *(float4*)&Bs[bkr][bc4] = vb;
        __syncthreads();
        #pragma unroll
        for (int kk = 0; kk < 16; kk++){
            float a[4], b[4];
            *(float4*)a = *(const float4*)&As[kk][ty*4];
            *(float4*)b = *(const float4*)&Bs[kk][tx*4];
            #pragma unroll
            for (int i = 0; i < 4; i++)
                #pragma unroll
                for (int j = 0; j < 4; j++)
                    acc[i][j] += a[i]*b[j];
        }
        __syncthreads();
    }
    #pragma unroll
    for (int i = 0; i < 4; i++){
        size_t off = (size_t)(row0 + ty*4 + i)*DD + col0 + tx*4;
        float4 rv = *(const float4*)(R + off);
        float4 o = make_float4(acc[i][0]+rv.x, acc[i][1]+rv.y, acc[i][2]+rv.z, acc[i][3]+rv.w);
        *(float4*)(O + off) = o;
    }
}

// ----------------------------------------------------------------------------
// nt_exp: C = exp(A@B^T), row sums accumulated to rsum (z picks pair). K=256.
// ----------------------------------------------------------------------------
__global__ __launch_bounds__(256, 2)
void nt_exp(const float* __restrict__ A0, const float* __restrict__ B0, float* __restrict__ C0,
            const float* __restrict__ A1, const float* __restrict__ B1, float* __restrict__ C1,
            float* __restrict__ rsum){
    __shared__ float As[16][128];
    __shared__ float Bs[16][128];
    __shared__ float rowE[128];
    int z = blockIdx.z;
    const float* A = z ? A1 : A0;
    const float* B = z ? B1 : B0;
    float* C = z ? C1 : C0;
    float* rs = rsum + z*NS;

    int tid = threadIdx.x;
    int tx = tid & 15, ty = tid >> 4;
    int row0 = blockIdx.y * 128, col0 = blockIdx.x * 128;
    float acc[8][8];
    #pragma unroll
    for (int i = 0; i < 8; i++)
        #pragma unroll
        for (int j = 0; j < 8; j++) acc[i][j] = 0.f;
    for (int kc = 0; kc < DD; kc += 16){
        #pragma unroll
        for (int t = 0; t < 2; t++){
            int lin = tid + t*256;
            int r = lin >> 2, c4 = (lin & 3) << 2;
            float4 va = *(const float4*)(A + (size_t)(row0 + r)*DD + kc + c4);
            As[c4+0][r]=va.x; As[c4+1][r]=va.y; As[c4+2][r]=va.z; As[c4+3][r]=va.w;
            float4 vb = *(const float4*)(B + (size_t)(col0 + r)*DD + kc + c4);
            Bs[c4+0][r]=vb.x; Bs[c4+1][r]=vb.y; Bs[c4+2][r]=vb.z; Bs[c4+3][r]=vb.w;
        }
        __syncthreads();
        #pragma unroll
        for (int kk = 0; kk < 16; kk++){
            float a[8], b[8];
            *(float4*)(a)   = *(const float4*)&As[kk][ty*8];
            *(float4*)(a+4) = *(const float4*)&As[kk][ty*8+4];
            *(float4*)(b)   = *(const float4*)&Bs[kk][tx*8];
            *(float4*)(b+4) = *(const float4*)&Bs[kk][tx*8+4];
            #pragma unroll
            for (int i = 0; i < 8; i++)
                #pragma unroll
                for (int j = 0; j < 8; j++)
                    acc[i][j] += a[i]*b[j];
        }
        __syncthreads();
    }
    if (tid < 128) rowE[tid] = 0.f;
    __syncthreads();
    #pragma unroll
    for (int i = 0; i < 8; i++){
        float e[8];
        float part = 0.f;
        #pragma unroll
        for (int j = 0; j < 8; j++){ e[j] = fexp(acc[i][j]); part += e[j]; }
        float* cp = C + (size_t)(row0 + ty*8 + i)*NS + col0 + tx*8;
        *(float4*)cp     = make_float4(e[0],e[1],e[2],e[3]);
        *(float4*)(cp+4) = make_float4(e[4],e[5],e[6],e[7]);
        atomicAdd(&rowE[ty*8 + i], part);
    }
    __syncthreads();
    if (tid < 128) atomicAdd(&rs[row0 + tid], rowE[tid]);
}

// ----------------------------------------------------------------------------
// nt_stats: C = A@B^T, accumulates sum & sumsq into dacc[0..1]. K=256.
// ----------------------------------------------------------------------------
__global__ __launch_bounds__(256, 2)
void nt_stats(const float* __restrict__ A, const float* __restrict__ B,
              float* __restrict__ C, double* dacc){
    __shared__ float As[16][128];
    __shared__ float Bs[16][128];
    int tid = threadIdx.x;
    int tx = tid & 15, ty = tid >> 4;
    int row0 = blockIdx.y * 128, col0 = blockIdx.x * 128;
    float acc[8][8];
    #pragma unroll
    for (int i = 0; i < 8; i++)
        #pragma unroll
        for (int j = 0; j < 8; j++) acc[i][j] = 0.f;
    for (int kc = 0; kc < DD; kc += 16){
        #pragma unroll
        for (int t = 0; t < 2; t++){
            int lin = tid + t*256;
            int r = lin >> 2, c4 = (lin & 3) << 2;
            float4 va = *(const float4*)(A + (size_t)(row0 + r)*DD + kc + c4);
            As[c4+0][r]=va.x; As[c4+1][r]=va.y; As[c4+2][r]=va.z; As[c4+3][r]=va.w;
            float4 vb = *(const float4*)(B + (size_t)(col0 + r)*DD + kc + c4);
            Bs[c4+0][r]=vb.x; Bs[c4+1][r]=vb.y; Bs[c4+2][r]=vb.z; Bs[c4+3][r]=vb.w;
        }
        __syncthreads();
        #pragma unroll
        for (int kk = 0; kk < 16; kk++){
            float a[8], b[8];
            *(float4*)(a)   = *(const float4*)&As[kk][ty*8];
            *(float4*)(a+4) = *(const float4*)&As[kk][ty*8+4];
            *(float4*)(b)   = *(const float4*)&Bs[kk][tx*8];
            *(float4*)(b+4) = *(const float4*)&Bs[kk][tx*8+4];
            #pragma unroll
            for (int i = 0; i < 8; i++)
                #pragma unroll
                for (int j = 0; j < 8; j++)
                    acc[i][j] += a[i]*b[j];
        }
        __syncthreads();
    }
    float s = 0.f, ss = 0.f;
    #pragma unroll
    for (int i = 0; i < 8; i++){
        float* cp = C + (size_t)(row0 + ty*8 + i)*NS + col0 + tx*8;
        *(float4*)cp     = make_float4(acc[i][0],acc[i][1],acc[i][2],acc[i][3]);
        *(float4*)(cp+4) = make_float4(acc[i][4],acc[i][5],acc[i][6],acc[i][7]);
        #pragma unroll
        for (int j = 0; j < 8; j++){ s += acc[i][j]; ss += acc[i][j]*acc[i][j]; }
    }
    float* red = &As[0][0];
    float bs  = bsum256(s,  red);
    float bss = bsum256(ss, red);
    if (tid == 0){
        atomicAdd(dacc + 0, (double)bs);
        atomicAdd(dacc + 1, (double)bss);
    }
}

// ----------------------------------------------------------------------------
// nt_supcon: triangular fn@fn^T with fused SupCon row/col accumulation.
// No logits matrix materialized. blocks with bx<by exit.
// ----------------------------------------------------------------------------
__global__ __launch_bounds__(256, 2)
void nt_supcon(const float* __restrict__ F, const int* __restrict__ lab,
               float* __restrict__ esum, float* __restrict__ psum){
    int bx = blockIdx.x, by = blockIdx.y;
    if (bx < by) return;
    __shared__ float As[16][128];
    __shared__ float Bs[16][128];
    __shared__ float rowE[128], rowS[128], colE[128], colS[128];
    __shared__ int labR[128], labC[128];
    int tid = threadIdx.x;
    int tx = tid & 15, ty = tid >> 4;
    int row0 = by * 128, col0 = bx * 128;
    if (tid < 128){ labR[tid] = lab[row0 + tid]; labC[tid] = lab[col0 + tid]; }
    float acc[8][8];
    #pragma unroll
    for (int i = 0; i < 8; i++)
        #pragma unroll
        for (int j = 0; j < 8; j++) acc[i][j] = 0.f;
    for (int kc = 0; kc < DD; kc += 16){
        #pragma unroll
        for (int t = 0; t < 2; t++){
            int lin = tid + t*256;
            int r = lin >> 2, c4 = (lin & 3) << 2;
            float4 va = *(const float4*)(F + (size_t)(row0 + r)*DD + kc + c4);
            As[c4+0][r]=va.x; As[c4+1][r]=va.y; As[c4+2][r]=va.z; As[c4+3][r]=va.w;
            float4 vb = *(const float4*)(F + (size_t)(col0 + r)*DD + kc + c4);
            Bs[c4+0][r]=vb.x; Bs[c4+1][r]=vb.y; Bs[c4+2][r]=vb.z; Bs[c4+3][r]=vb.w;
        }
        __syncthreads();
        #pragma unroll
        for (int kk = 0; kk < 16; kk++){
            float a[8], b[8];
            *(float4*)(a)   = *(const float4*)&As[kk][ty*8];
            *(float4*)(a+4) = *(const float4*)&As[kk][ty*8+4];
            *(float4*)(b)   = *(const float4*)&Bs[kk][tx*8];
            *(float4*)(b+4) = *(const float4*)&Bs[kk][tx*8+4];
            #pragma unroll
            for (int i = 0; i < 8; i++)
                #pragma unroll
                for (int j = 0; j < 8; j++)
                    acc[i][j] += a[i]*b[j];
        }
        __syncthreads();
    }
    if (tid < 128){ rowE[tid]=0.f; rowS[tid]=0.f; colE[tid]=0.f; colS[tid]=0.f; }
    __syncthreads();
    bool diag = (bx == by);
    // row-side accumulation (every block)
    #pragma unroll
    for (int i = 0; i < 8; i++){
        int gr = row0 + ty*8 + i;
        int lr = labR[ty*8 + i];
        float pe = 0.f, ps = 0.f;
        #pragma unroll
        for (int j = 0; j < 8; j++){
            int gc = col0 + tx*8 + j;
            if (diag && gr == gc) continue;
            float l = acc[i][j] * SUPCON_SCALE;
            pe += fexp(l);
            if (labC[tx*8 + j] == lr) ps += l;
        }
        atomicAdd(&rowE[ty*8 + i], pe);
        atomicAdd(&rowS[ty*8 + i], ps);
    }
    // col-side accumulation (strict off-diagonal blocks: symmetry)
    if (!diag){
        #pragma unroll
        for (int j = 0; j < 8; j++){
            int lc = labC[tx*8 + j];
            float pe = 0.f, ps = 0.f;
            #pragma unroll
            for (int i = 0; i < 8; i++){
                float l = acc[i][j] * SUPCON_SCALE;
                pe += fexp(l);
                if (labR[ty*8 + i] == lc) ps += l;
            }
            atomicAdd(&colE[tx*8 + j], pe);
            atomicAdd(&colS[tx*8 + j], ps);
        }
    }
    __syncthreads();
    if (tid < 128){
        atomicAdd(&esum[row0 + tid], rowE[tid]);
        atomicAdd(&psum[row0 + tid], rowS[tid]);
        if (!diag){
            atomicAdd(&esum[col0 + tid], colE[tid]);
            atomicAdd(&psum[col0 + tid], colS[tid]);
        }
    }
}

// ----------------------------------------------------------------------------
// LayerNorm (optionally + ReLU), in-place, one block per row of 256
// ----------------------------------------------------------------------------
__global__ __launch_bounds__(256)
void ln_kernel(float* __restrict__ X, int relu){
    __shared__ float red[256];
    int i = blockIdx.x, tid = threadIdx.x;
    float v = X[(size_t)i*DD + tid];
    float s  = bsum256(v, red);
    float ss = bsum256(v*v, red);
    float m = s * (1.f/DD);
    float var = ss * (1.f/DD) - m*m;
    float o = (v - m) * rsqrtf(var + 1e-5f);
    if (relu) o = fmaxf(o, 0.f);
    X[(size_t)i*DD + tid] = o;
}

__global__ void finalize_stats(const double* acc, float* stats){
    if (threadIdx.x == 0 && blockIdx.x == 0){
        double n = (double)NELEM;
        double mu = acc[0] / n;
        double var = acc[1] / n - mu*mu;
        stats[0] = (float)mu;
        stats[1] = (float)(1.0 / (sqrt(var) + 1e-5));
    }
}

// ----------------------------------------------------------------------------
// Sinkhorn passes: single-pass LSE (no max shift; args bounded), fast exp
// ----------------------------------------------------------------------------
__global__ __launch_bounds__(256)
void sink_row(const float* __restrict__ Mm, const float* __restrict__ stats,
              const float* __restrict__ c, float* __restrict__ r){
    __shared__ float red[256];
    int i = blockIdx.x, tid = threadIdx.x;
    float inv = stats[1];
    float muinv = stats[0]*inv;
    const float* row = Mm + (size_t)i*NS;
    float s = 0.f;
    for (int j = tid; j < NS; j += 256)
        s += fexp(fmaf(row[j], inv, -muinv - c[j]));
    s = bsum256(s, red);
    if (tid == 0) r[i] = logf(s);
}

__global__ void sink_col(const float* __restrict__ Mm, const float* __restrict__ stats,
                         const float* __restrict__ r, float* __restrict__ c){
    __shared__ float red[32][8];
    int tx = threadIdx.x, ty = threadIdx.y;  // (8,32)
    int j = blockIdx.x*8 + tx;
    float inv = stats[1];
    float muinv = stats[0]*inv;
    float s = 0.f;
    for (int i = ty; i < NS; i += 32)
        s += fexp(fmaf(Mm[(size_t)i*NS + j], inv, -muinv - r[i]));
    red[ty][tx] = s; __syncthreads();
    #pragma unroll
    for (int off = 16; off > 0; off >>= 1){
        if (ty < off) red[ty][tx] += red[ty+off][tx];
        __syncthreads();
    }
    if (ty == 0) c[j] = logf(red[0][tx]);
}

__global__ __launch_bounds__(256)
void match_kernel(const float* __restrict__ Mm, const float* __restrict__ r,
                  const float* __restrict__ c, const int* __restrict__ lab,
                  const float* __restrict__ stats, double* acc){
    __shared__ float red[256];
    int i = blockIdx.x, tid = threadIdx.x;
    float inv = stats[1];
    float muinv = stats[0]*inv;
    float ri = r[i];
    int li = lab[i];
    const float* row = Mm + (size_t)i*NS;
    float s = 0.f;
    for (int j = tid; j < NS; j += 256){
        float p = fexp(fmaf(row[j], inv, -muinv - ri - c[j]));
        float gt = (li == lab[NS + j]) ? 1.f : 0.f;
        s += fabsf(p - gt);
    }
    s = bsum256(s, red);
    if (tid == 0) atomicAdd(acc + 2, (double)s);
}

// ----------------------------------------------------------------------------
// SupCon support
// ----------------------------------------------------------------------------
__global__ __launch_bounds__(256)
void fnorm_kernel(const float* __restrict__ X, float* __restrict__ F){
    __shared__ float red[256];
    int i = blockIdx.x, tid = threadIdx.x;
    float x = X[(size_t)i*DD + tid];
    float ss = bsum256(x*x, red);
    F[(size_t)i*DD + tid] = x / (sqrtf(ss) + 1e-8f);
}

__global__ void hist_kernel(const int* __restrict__ lab, int* hist){
    int idx = blockIdx.x*blockDim.x + threadIdx.x;
    if (idx < NF) atomicAdd(&hist[lab[idx]], 1);
}

__global__ __launch_bounds__(256)
void supcon_final(const float* __restrict__ esum, const float* __restrict__ psum,
                  const int* __restrict__ lab, const int* __restrict__ hist,
                  double* acc){
    __shared__ float red[256];
    int i = blockIdx.x*256 + threadIdx.x;
    float cnt = (float)(hist[lab[i]] - 1);
    float v = psum[i]/cnt - logf(esum[i]);
    float s = bsum256(v, red);
    if (threadIdx.x == 0) atomicAdd(acc + 3, (double)s);
}

__global__ void finalize_kernel(const double* acc, float* out){
    if (threadIdx.x == 0 && blockIdx.x == 0){
        double supcon = -(acc[3] / (double)NF);
        out[0] = (float)(acc[2] + 0.1 * supcon);
    }
}

// ----------------------------------------------------------------------------
// Host driver
// ----------------------------------------------------------------------------
extern "C" void kernel_launch(void* const* d_in, const int* in_sizes, int n_in,
                              void* d_out, int out_size){
    const float* nodes_src = (const float*)d_in[0];
    const float* nodes_tgt = (const float*)d_in[1];
    const int*   labels_src = (const int*)d_in[2];
    const int*   labels_tgt = (const int*)d_in[3];
    const float* w1 = (const float*)d_in[4];
    const float* b1 = (const float*)d_in[5];
    const float* w2 = (const float*)d_in[6];
    const float* b2 = (const float*)d_in[7];
    const float* wq = (const float*)d_in[8];
    const float* wk = (const float*)d_in[9];
    const float* wv = (const float*)d_in[10];
    const float* wo = (const float*)d_in[11];
    const float* cq = (const float*)d_in[12];
    const float* ck = (const float*)d_in[13];
    const float* cv = (const float*)d_in[14];
    const float* co = (const float*)d_in[15];
    const float* Am = (const float*)d_in[16];

    float *in_,*x0,*x1,*x2,*q,*vw,*fn,*S0,*S1,*Wp,*rsum,*rv,*cvv,*esum,*psum,*stats;
    double* dacc; int *lab, *hist;
    cudaGetSymbolAddress((void**)&in_, g_in);
    cudaGetSymbolAddress((void**)&x0, g_x0);
    cudaGetSymbolAddress((void**)&x1, g_x1);
    cudaGetSymbolAddress((void**)&x2, g_x2);
    cudaGetSymbolAddress((void**)&q,  g_q);
    cudaGetSymbolAddress((void**)&vw, g_vw);
    cudaGetSymbolAddress((void**)&fn, g_fn);
    cudaGetSymbolAddress((void**)&S0, g_S0);
    cudaGetSymbolAddress((void**)&S1, g_S1);
    cudaGetSymbolAddress((void**)&Wp, g_Wp);
    cudaGetSymbolAddress((void**)&rsum, g_rsum);
    cudaGetSymbolAddress((void**)&rv, g_r);
    cudaGetSymbolAddress((void**)&cvv, g_c);
    cudaGetSymbolAddress((void**)&esum, g_esum);
    cudaGetSymbolAddress((void**)&psum, g_psum);
    cudaGetSymbolAddress((void**)&stats, g_stats);
    cudaGetSymbolAddress((void**)&dacc, g_dacc);
    cudaGetSymbolAddress((void**)&lab, g_lab);
    cudaGetSymbolAddress((void**)&hist, g_hist);

    float* Wqk_i = Wp;
    float* Wvo_i = Wp + DD*DD;
    float* Wqk_c = Wp + 2*DD*DD;
    float* Wvo_c = Wp + 3*DD*DD;

    // zeroing + packing
    cudaMemsetAsync(dacc, 0, 4*sizeof(double));
    cudaMemsetAsync(hist, 0, 16*sizeof(int));
    cudaMemsetAsync(cvv, 0, NS*sizeof(float));
    cudaMemsetAsync(esum, 0, NF*sizeof(float));
    cudaMemsetAsync(psum, 0, NF*sizeof(float));
    cudaMemcpyAsync(in_, nodes_src, HALF*sizeof(float), cudaMemcpyDeviceToDevice);
    cudaMemcpyAsync(in_ + HALF, nodes_tgt, HALF*sizeof(float), cudaMemcpyDeviceToDevice);
    cudaMemcpyAsync(lab, labels_src, NS*sizeof(int), cudaMemcpyDeviceToDevice);
    cudaMemcpyAsync(lab + NS, labels_tgt, NS*sizeof(int), cudaMemcpyDeviceToDevice);

    // weight precompute: Wqk = Wq@Wk^T/16, Wvo = Wv@Wo
    gemm_nt<<<dim3(2,2), 256>>>(wq, wk, Wqk_i, DD, DD, DD, 0.0625f);
    gemm_nt<<<dim3(2,2), 256>>>(cq, ck, Wqk_c, DD, DD, DD, 0.0625f);
    gemm_aw<<<DD/8, 256>>>(wv, wo, Wvo_i, DD);
    gemm_aw<<<DD/8, 256>>>(cv, co, Wvo_c, DD);

    // head_in (stacked M=4096): LN(ReLU(LN(X@w1+b1))@w2+b2)
    gemm_nn<<<dim3(DD/64, NF/64), 256>>>(in_, w1, b1, q, NF, DD, DD);
    ln_kernel<<<NF, 256>>>(q, 1);
    gemm_nn<<<dim3(DD/64, NF/64), 256>>>(q, w2, b2, x0, NF, DD, DD);
    ln_kernel<<<NF, 256>>>(x0, 0);

    // ---- intra-domain attention (both domains batched) ----
    gemm_nn<<<dim3(DD/64, NF/64), 256>>>(x0, Wqk_i, nullptr, q,  NF, DD, DD);
    gemm_nn<<<dim3(DD/64, NF/64), 256>>>(x0, Wvo_i, nullptr, vw, NF, DD, DD);
    cudaMemsetAsync(rsum, 0, NF*sizeof(float));
    nt_exp<<<dim3(NS/128, NS/128, 2), 256>>>(q, x0, S0, q + HALF, x0 + HALF, S1, rsum);
    gemm_pv<<<dim3(DD/64, NS/64, 2), 256>>>(S0, vw, S1, vw + HALF, rsum, x0, x1);

    // ---- cross-domain attention ----
    gemm_nn<<<dim3(DD/64, NF/64), 256>>>(x1, Wqk_c, nullptr, q,  NF, DD, DD);
    gemm_nn<<<dim3(DD/64, NF/64), 256>>>(x1, Wvo_c, nullptr, vw, NF, DD, DD);
    cudaMemsetAsync(rsum, 0, NF*sizeof(float));
    nt_exp<<<dim3(NS/128, NS/128, 2), 256>>>(q, x1 + HALF, S0, q + HALF, x1, S1, rsum);
    gemm_pv<<<dim3(DD/64, NS/64, 2), 256>>>(S0, vw + HALF, S1, vw, rsum, x1, x2);

    // ---- affinity M = (src2@A)@tgt2^T with fused stats ----
    gemm_nn<<<dim3(DD/64, NS/64), 256>>>(x2, Am, nullptr, q, NS, DD, DD);
    nt_stats<<<dim3(NS/128, NS/128), 256>>>(q, x2 + HALF, S0, dacc);
    finalize_stats<<<1, 32>>>(dacc, stats);

    // ---- Sinkhorn (lazy potentials, single-pass LSE) ----
    for (int it = 0; it < 10; it++){
        sink_row<<<NS, 256>>>(S0, stats, cvv, rv);
        sink_col<<<NS/8, dim3(8,32)>>>(S0, stats, rv, cvv);
    }
    match_kernel<<<NS, 256>>>(S0, rv, cvv, lab, stats, dacc);

    // ---- SupCon (triangular fused) ----
    fnorm_kernel<<<NF, 256>>>(x2, fn);
    hist_kernel<<<16, 256>>>(lab, hist);
    nt_supcon<<<dim3(NF/128, NF/128), 256>>>(fn, lab, esum, psum);
    supcon_final<<<NF/256, 256>>>(esum, psum, lab, hist, dacc);

    finalize_kernel<<<1, 32>>>(dacc, (float*)d_out);
}

// round 3
// speedup vs baseline: 1.3810x; 1.0253x over previous
#include <cuda_runtime.h>
#include <math.h>
#include <stdint.h>

#define NS 2048
#define DD 256
#define NF 4096
#define HALF ((size_t)NS*DD)
#define NELEM ((size_t)NS*(size_t)NS)
#define SUPCON_SCALE 14.285714285714286f   // 1/0.07

// ----------------------------------------------------------------------------
// Static device scratch
// ----------------------------------------------------------------------------
__device__ float g_in [NF*DD];
__device__ float g_x0 [NF*DD];
__device__ float g_x1 [NF*DD];
__device__ float g_x2 [NF*DD];
__device__ float g_q  [NF*DD];
__device__ float g_vw [NF*DD];
__device__ float g_fn [NF*DD];
__device__ float g_S0 [NELEM];
__device__ float g_S1 [NELEM];
__device__ float g_Wp [4][DD*DD];   // Wqk_i, Wvo_i, Wqk_c, Wvo_c
__device__ float g_rsum[NF];
__device__ float g_r[NS];
__device__ float g_c[NS];
__device__ float g_esum[NF];
__device__ float g_psum[NF];
__device__ float g_stats[2];
__device__ double g_dacc[4];        // sum, sumsq, match, supcon
__device__ int   g_lab[NF];
__device__ int   g_hist[16];

// ----------------------------------------------------------------------------
// Fast exp: e^x via 2^t with degree-5 polynomial (FMA pipe, no MUFU)
// valid for |x| < ~87; returns 0 below -87.
// ----------------------------------------------------------------------------
__device__ __forceinline__ float fexp(float x){
    float t = x * 1.4426950408889634f;
    float r = rintf(t);
    float f = t - r;
    float p =            1.3333558146e-3f;
    p = fmaf(p, f, 9.6181291076e-3f);
    p = fmaf(p, f, 5.5504108664e-2f);
    p = fmaf(p, f, 2.4022650696e-1f);
    p = fmaf(p, f, 6.9314718056e-1f);
    p = fmaf(p, f, 1.0f);
    float res = __int_as_float(__float_as_int(p) + (((int)r) << 23));
    return (x < -87.0f) ? 0.0f : res;
}

// ----------------------------------------------------------------------------
// Block reductions (blockDim.x == 256)
// ----------------------------------------------------------------------------
__device__ __forceinline__ float bsum256(float v, float* red){
    int tid = threadIdx.x;
    red[tid] = v; __syncthreads();
    #pragma unroll
    for (int off = 128; off > 0; off >>= 1){
        if (tid < off) red[tid] += red[tid + off];
        __syncthreads();
    }
    float r = red[0]; __syncthreads();
    return r;
}

// ----------------------------------------------------------------------------
// gemm_aw (tiny: used only for 256x256 weight precompute)  C = A@W
// ----------------------------------------------------------------------------
__global__ __launch_bounds__(256)
void gemm_aw(const float* __restrict__ A, const float* __restrict__ W,
             float* __restrict__ C, int M){
    __shared__ float Xs[8][DD];
    int tid = threadIdx.x;
    int row0 = blockIdx.x * 8;
    #pragma unroll
    for (int r = 0; r < 8; r++)
        Xs[r][tid] = A[(size_t)(row0 + r)*DD + tid];
    __syncthreads();
    float acc[8] = {0,0,0,0,0,0,0,0};
    #pragma unroll 4
    for (int k = 0; k < DD; k++){
        float w = W[k*DD + tid];
        #pragma unroll
        for (int r = 0; r < 8; r++) acc[r] += Xs[r][k] * w;
    }
    #pragma unroll
    for (int r = 0; r < 8; r++)
        C[(size_t)(row0 + r)*DD + tid] = acc[r];
}

// ----------------------------------------------------------------------------
// gemm_nt (plain; used for 256x256 Wq@Wk^T precompute): C = scale*A@B^T
// ----------------------------------------------------------------------------
__global__ __launch_bounds__(256, 2)
void gemm_nt(const float* __restrict__ A, const float* __restrict__ B,
             float* __restrict__ C, int M, int N, int K, float scale){
    __shared__ float As[16][128];
    __shared__ float Bs[16][128];
    int tid = threadIdx.x;
    int tx = tid & 15, ty = tid >> 4;
    int row0 = blockIdx.y * 128, col0 = blockIdx.x * 128;
    float acc[8][8];
    #pragma unroll
    for (int i = 0; i < 8; i++)
        #pragma unroll
        for (int j = 0; j < 8; j++) acc[i][j] = 0.f;
    for (int kc = 0; kc < K; kc += 16){
        #pragma unroll
        for (int t = 0; t < 2; t++){
            int lin = tid + t*256;
            int r = lin >> 2, c4 = (lin & 3) << 2;
            float4 va = *(const float4*)(A + (size_t)(row0 + r)*K + kc + c4);
            As[c4+0][r]=va.x; As[c4+1][r]=va.y; As[c4+2][r]=va.z; As[c4+3][r]=va.w;
            float4 vb = *(const float4*)(B + (size_t)(col0 + r)*K + kc + c4);
            Bs[c4+0][r]=vb.x; Bs[c4+1][r]=vb.y; Bs[c4+2][r]=vb.z; Bs[c4+3][r]=vb.w;
        }
        __syncthreads();
        #pragma unroll
        for (int kk = 0; kk < 16; kk++){
            float a[8], b[8];
            *(float4*)(a)   = *(const float4*)&As[kk][ty*8];
            *(float4*)(a+4) = *(const float4*)&As[kk][ty*8+4];
            *(float4*)(b)   = *(const float4*)&Bs[kk][tx*8];
            *(float4*)(b+4) = *(const float4*)&Bs[kk][tx*8+4];
            #pragma unroll
            for (int i = 0; i < 8; i++)
                #pragma unroll
                for (int j = 0; j < 8; j++)
                    acc[i][j] += a[i]*b[j];
        }
        __syncthreads();
    }
    #pragma unroll
    for (int i = 0; i < 8; i++){
        float* cp = C + (size_t)(row0 + ty*8 + i)*N + col0 + tx*8;
        float4 o0 = make_float4(acc[i][0]*scale, acc[i][1]*scale, acc[i][2]*scale, acc[i][3]*scale);
        float4 o1 = make_float4(acc[i][4]*scale, acc[i][5]*scale, acc[i][6]*scale, acc[i][7]*scale);
        *(float4*)cp = o0; *(float4*)(cp+4) = o1;
    }
}

// ----------------------------------------------------------------------------
// gemm_nn: C = A[M,K]@B[K,N] (+bias). 64x64 tile, 4x4/thread. M%64==0, N%64==0, K%16==0
// ----------------------------------------------------------------------------
__global__ __launch_bounds__(256, 3)
void gemm_nn(const float* __restrict__ A, const float* __restrict__ B,
             const float* __restrict__ bias, float* __restrict__ C,
             int M, int N, int K){
    __shared__ float As[16][64];
    __shared__ float Bs[16][64];
    int tid = threadIdx.x;
    int tx = tid & 15, ty = tid >> 4;
    int row0 = blockIdx.y * 64, col0 = blockIdx.x * 64;
    int ar = tid >> 2, ac4 = (tid & 3) << 2;
    int bkr = tid >> 4, bc4 = (tid & 15) << 2;
    float acc[4][4];
    #pragma unroll
    for (int i = 0; i < 4; i++)
        #pragma unroll
        for (int j = 0; j < 4; j++) acc[i][j] = 0.f;
    for (int kc = 0; kc < K; kc += 16){
        float4 va = *(const float4*)(A + (size_t)(row0+ar)*K + kc + ac4);
        As[ac4+0][ar]=va.x; As[ac4+1][ar]=va.y; As[ac4+2][ar]=va.z; As[ac4+3][ar]=va.w;
        float4 vb = *(const float4*)(B + (size_t)(kc+bkr)*N + col0 + bc4);
        *(float4*)&Bs[bkr][bc4] = vb;
        __syncthreads();
        #pragma unroll
        for (int kk = 0; kk < 16; kk++){
            float a[4], b[4];
            *(float4*)a = *(const float4*)&As[kk][ty*4];
            *(float4*)b = *(const float4*)&Bs[kk][tx*4];
            #pragma unroll
            for (int i = 0; i < 4; i++)
                #pragma unroll
                for (int j = 0; j < 4; j++)
                    acc[i][j] += a[i]*b[j];
        }
        __syncthreads();
    }
    #pragma unroll
    for (int i = 0; i < 4; i++){
        float bv[4];
        #pragma unroll
        for (int j = 0; j < 4; j++)
            bv[j] = bias ? bias[col0 + tx*4 + j] : 0.f;
        float4 o = make_float4(acc[i][0]+bv[0], acc[i][1]+bv[1], acc[i][2]+bv[2], acc[i][3]+bv[3]);
        *(float4*)(C + (size_t)(row0 + ty*4 + i)*N + col0 + tx*4) = o;
    }
}

// ----------------------------------------------------------------------------
// gemm_pv: out = res + (diag(1/rs) * S) @ B    (z in {0,1} picks the pair)
// S: [2048,2048], B: [2048,256]. 64x64 tiles.
// ----------------------------------------------------------------------------
__global__ __launch_bounds__(256, 3)
void gemm_pv(const float* __restrict__ S0, const float* __restrict__ B0,
             const float* __restrict__ S1, const float* __restrict__ B1,
             const float* __restrict__ rsum,
             const float* __restrict__ res, float* __restrict__ out){
    __shared__ float As[16][64];
    __shared__ float Bs[16][64];
    int z = blockIdx.z;
    const float* A = z ? S1 : S0;
    const float* B = z ? B1 : B0;
    const float* rs = rsum + z*NS;
    const float* R  = res + (size_t)z*HALF;
    float* O        = out + (size_t)z*HALF;

    int tid = threadIdx.x;
    int tx = tid & 15, ty = tid >> 4;
    int row0 = blockIdx.y * 64, col0 = blockIdx.x * 64;
    int ar = tid >> 2, ac4 = (tid & 3) << 2;
    int bkr = tid >> 4, bc4 = (tid & 15) << 2;
    float sc = 1.0f / rs[row0 + ar];
    float acc[4][4];
    #pragma unroll
    for (int i = 0; i < 4; i++)
        #pragma unroll
        for (int j = 0; j < 4; j++) acc[i][j] = 0.f;
    for (int kc = 0; kc < NS; kc += 16){
        float4 va = *(const float4*)(A + (size_t)(row0+ar)*NS + kc + ac4);
        As[ac4+0][ar]=va.x*sc; As[ac4+1][ar]=va.y*sc; As[ac4+2][ar]=va.z*sc; As[ac4+3][ar]=va.w*sc;
        float4 vb = *(const float4*)(B + (size_t)(kc+bkr)*DD + col0 + bc4);
        *(float4*)&Bs[bkr][bc4] = vb;
        __syncthreads();
        #pragma unroll
        for (int kk = 0; kk < 16; kk++){
            float a[4], b[4];
            *(float4*)a = *(const float4*)&As[kk][ty*4];
            *(float4*)b = *(const float4*)&Bs[kk][tx*4];
            #pragma unroll
            for (int i = 0; i < 4; i++)
                #pragma unroll
                for (int j = 0; j < 4; j++)
                    acc[i][j] += a[i]*b[j];
        }
        __syncthreads();
    }
    #pragma unroll
    for (int i = 0; i < 4; i++){
        size_t off = (size_t)(row0 + ty*4 + i)*DD + col0 + tx*4;
        float4 rv = *(const float4*)(R + off);
        float4 o = make_float4(acc[i][0]+rv.x, acc[i][1]+rv.y, acc[i][2]+rv.z, acc[i][3]+rv.w);
        *(float4*)(O + off) = o;
    }
}

// ----------------------------------------------------------------------------
// nt_exp: C = exp(A@B^T), row sums accumulated to rsum (z picks pair). K=256.
// ----------------------------------------------------------------------------
__global__ __launch_bounds__(256, 2)
void nt_exp(const float* __restrict__ A0, const float* __restrict__ B0, float* __restrict__ C0,
            const float* __restrict__ A1, const float* __restrict__ B1, float* __restrict__ C1,
            float* __restrict__ rsum){
    __shared__ float As[16][128];
    __shared__ float Bs[16][128];
    __shared__ float rowE[128];
    int z = blockIdx.z;
    const float* A = z ? A1 : A0;
    const float* B = z ? B1 : B0;
    float* C = z ? C1 : C0;
    float* rs = rsum + z*NS;

    int tid = threadIdx.x;
    int tx = tid & 15, ty = tid >> 4;
    int row0 = blockIdx.y * 128, col0 = blockIdx.x * 128;
    float acc[8][8];
    #pragma unroll
    for (int i = 0; i < 8; i++)
        #pragma unroll
        for (int j = 0; j < 8; j++) acc[i][j] = 0.f;
    for (int kc = 0; kc < DD; kc += 16){
        #pragma unroll
        for (int t = 0; t < 2; t++){
            int lin = tid + t*256;
            int r = lin >> 2, c4 = (lin & 3) << 2;
            float4 va = *(const float4*)(A + (size_t)(row0 + r)*DD + kc + c4);
            As[c4+0][r]=va.x; As[c4+1][r]=va.y; As[c4+2][r]=va.z; As[c4+3][r]=va.w;
            float4 vb = *(const float4*)(B + (size_t)(col0 + r)*DD + kc + c4);
            Bs[c4+0][r]=vb.x; Bs[c4+1][r]=vb.y; Bs[c4+2][r]=vb.z; Bs[c4+3][r]=vb.w;
        }
        __syncthreads();
        #pragma unroll
        for (int kk = 0; kk < 16; kk++){
            float a[8], b[8];
            *(float4*)(a)   = *(const float4*)&As[kk][ty*8];
            *(float4*)(a+4) = *(const float4*)&As[kk][ty*8+4];
            *(float4*)(b)   = *(const float4*)&Bs[kk][tx*8];
            *(float4*)(b+4) = *(const float4*)&Bs[kk][tx*8+4];
            #pragma unroll
            for (int i = 0; i < 8; i++)
                #pragma unroll
                for (int j = 0; j < 8; j++)
                    acc[i][j] += a[i]*b[j];
        }
        __syncthreads();
    }
    if (tid < 128) rowE[tid] = 0.f;
    __syncthreads();
    #pragma unroll
    for (int i = 0; i < 8; i++){
        float e[8];
        float part = 0.f;
        #pragma unroll
        for (int j = 0; j < 8; j++){ e[j] = fexp(acc[i][j]); part += e[j]; }
        float* cp = C + (size_t)(row0 + ty*8 + i)*NS + col0 + tx*8;
        *(float4*)cp     = make_float4(e[0],e[1],e[2],e[3]);
        *(float4*)(cp+4) = make_float4(e[4],e[5],e[6],e[7]);
        atomicAdd(&rowE[ty*8 + i], part);
    }
    __syncthreads();
    if (tid < 128) atomicAdd(&rs[row0 + tid], rowE[tid]);
}

// ----------------------------------------------------------------------------
// nt_stats: C = A@B^T, accumulates sum & sumsq into dacc[0..1]. K=256.
// ----------------------------------------------------------------------------
__global__ __launch_bounds__(256, 2)
void nt_stats(const float* __restrict__ A, const float* __restrict__ B,
              float* __restrict__ C, double* dacc){
    __shared__ float As[16][128];
    __shared__ float Bs[16][128];
    int tid = threadIdx.x;
    int tx = tid & 15, ty = tid >> 4;
    int row0 = blockIdx.y * 128, col0 = blockIdx.x * 128;
    float acc[8][8];
    #pragma unroll
    for (int i = 0; i < 8; i++)
        #pragma unroll
        for (int j = 0; j < 8; j++) acc[i][j] = 0.f;
    for (int kc = 0; kc < DD; kc += 16){
        #pragma unroll
        for (int t = 0; t < 2; t++){
            int lin = tid + t*256;
            int r = lin >> 2, c4 = (lin & 3) << 2;
            float4 va = *(const float4*)(A + (size_t)(row0 + r)*DD + kc + c4);
            As[c4+0][r]=va.x; As[c4+1][r]=va.y; As[c4+2][r]=va.z; As[c4+3][r]=va.w;
            float4 vb = *(const float4*)(B + (size_t)(col0 + r)*DD + kc + c4);
            Bs[c4+0][r]=vb.x; Bs[c4+1][r]=vb.y; Bs[c4+2][r]=vb.z; Bs[c4+3][r]=vb.w;
        }
        __syncthreads();
        #pragma unroll
        for (int kk = 0; kk < 16; kk++){
            float a[8], b[8];
            *(float4*)(a)   = *(const float4*)&As[kk][ty*8];
            *(float4*)(a+4) = *(const float4*)&As[kk][ty*8+4];
            *(float4*)(b)   = *(const float4*)&Bs[kk][tx*8];
            *(float4*)(b+4) = *(const float4*)&Bs[kk][tx*8+4];
            #pragma unroll
            for (int i = 0; i < 8; i++)
                #pragma unroll
                for (int j = 0; j < 8; j++)
                    acc[i][j] += a[i]*b[j];
        }
        __syncthreads();
    }
    float s = 0.f, ss = 0.f;
    #pragma unroll
    for (int i = 0; i < 8; i++){
        float* cp = C + (size_t)(row0 + ty*8 + i)*NS + col0 + tx*8;
        *(float4*)cp     = make_float4(acc[i][0],acc[i][1],acc[i][2],acc[i][3]);
        *(float4*)(cp+4) = make_float4(acc[i][4],acc[i][5],acc[i][6],acc[i][7]);
        #pragma unroll
        for (int j = 0; j < 8; j++){ s += acc[i][j]; ss += acc[i][j]*acc[i][j]; }
    }
    float* red = &As[0][0];
    float bs  = bsum256(s,  red);
    float bss = bsum256(ss, red);
    if (tid == 0){
        atomicAdd(dacc + 0, (double)bs);
        atomicAdd(dacc + 1, (double)bss);
    }
}

// ----------------------------------------------------------------------------
// nt_supcon: triangular fn@fn^T with fused SupCon row/col accumulation.
// No logits matrix materialized. blocks with bx<by exit.
// ----------------------------------------------------------------------------
__global__ __launch_bounds__(256, 2)
void nt_supcon(const float* __restrict__ F, const int* __restrict__ lab,
               float* __restrict__ esum, float* __restrict__ psum){
    int bx = blockIdx.x, by = blockIdx.y;
    if (bx < by) return;
    __shared__ float As[16][128];
    __shared__ float Bs[16][128];
    __shared__ float rowE[128], rowS[128], colE[128], colS[128];
    __shared__ int labR[128], labC[128];
    int tid = threadIdx.x;
    int tx = tid & 15, ty = tid >> 4;
    int row0 = by * 128, col0 = bx * 128;
    if (tid < 128){ labR[tid] = lab[row0 + tid]; labC[tid] = lab[col0 + tid]; }
    float acc[8][8];
    #pragma unroll
    for (int i = 0; i < 8; i++)
        #pragma unroll
        for (int j = 0; j < 8; j++) acc[i][j] = 0.f;
    for (int kc = 0; kc < DD; kc += 16){
        #pragma unroll
        for (int t = 0; t < 2; t++){
            int lin = tid + t*256;
            int r = lin >> 2, c4 = (lin & 3) << 2;
            float4 va = *(const float4*)(F + (size_t)(row0 + r)*DD + kc + c4);
            As[c4+0][r]=va.x; As[c4+1][r]=va.y; As[c4+2][r]=va.z; As[c4+3][r]=va.w;
            float4 vb = *(const float4*)(F + (size_t)(col0 + r)*DD + kc + c4);
            Bs[c4+0][r]=vb.x; Bs[c4+1][r]=vb.y; Bs[c4+2][r]=vb.z; Bs[c4+3][r]=vb.w;
        }
        __syncthreads();
        #pragma unroll
        for (int kk = 0; kk < 16; kk++){
            float a[8], b[8];
            *(float4*)(a)   = *(const float4*)&As[kk][ty*8];
            *(float4*)(a+4) = *(const float4*)&As[kk][ty*8+4];
            *(float4*)(b)   = *(const float4*)&Bs[kk][tx*8];
            *(float4*)(b+4) = *(const float4*)&Bs[kk][tx*8+4];
            #pragma unroll
            for (int i = 0; i < 8; i++)
                #pragma unroll
                for (int j = 0; j < 8; j++)
                    acc[i][j] += a[i]*b[j];
        }
        __syncthreads();
    }
    if (tid < 128){ rowE[tid]=0.f; rowS[tid]=0.f; colE[tid]=0.f; colS[tid]=0.f; }
    __syncthreads();
    bool diag = (bx == by);
    // row-side accumulation (every block)
    #pragma unroll
    for (int i = 0; i < 8; i++){
        int gr = row0 + ty*8 + i;
        int lr = labR[ty*8 + i];
        float pe = 0.f, ps = 0.f;
        #pragma unroll
        for (int j = 0; j < 8; j++){
            int gc = col0 + tx*8 + j;
            if (diag && gr == gc) continue;
            float l = acc[i][j] * SUPCON_SCALE;
            pe += fexp(l);
            if (labC[tx*8 + j] == lr) ps += l;
        }
        atomicAdd(&rowE[ty*8 + i], pe);
        atomicAdd(&rowS[ty*8 + i], ps);
    }
    // col-side accumulation (strict off-diagonal blocks: symmetry)
    if (!diag){
        #pragma unroll
        for (int j = 0; j < 8; j++){
            int lc = labC[tx*8 + j];
            float pe = 0.f, ps = 0.f;
            #pragma unroll
            for (int i = 0; i < 8; i++){
                float l = acc[i][j] * SUPCON_SCALE;
                pe += fexp(l);
                if (labR[ty*8 + i] == lc) ps += l;
            }
            atomicAdd(&colE[tx*8 + j], pe);
            atomicAdd(&colS[tx*8 + j], ps);
        }
    }
    __syncthreads();
    if (tid < 128){
        atomicAdd(&esum[row0 + tid], rowE[tid]);
        atomicAdd(&psum[row0 + tid], rowS[tid]);
        if (!diag){
            atomicAdd(&esum[col0 + tid], colE[tid]);
            atomicAdd(&psum[col0 + tid], colS[tid]);
        }
    }
}

// ----------------------------------------------------------------------------
// LayerNorm (optionally + ReLU), in-place, one block per row of 256
// ----------------------------------------------------------------------------
__global__ __launch_bounds__(256)
void ln_kernel(float* __restrict__ X, int relu){
    __shared__ float red[256];
    int i = blockIdx.x, tid = threadIdx.x;
    float v = X[(size_t)i*DD + tid];
    float s  = bsum256(v, red);
    float ss = bsum256(v*v, red);
    float m = s * (1.f/DD);
    float var = ss * (1.f/DD) - m*m;
    float o = (v - m) * rsqrtf(var + 1e-5f);
    if (relu) o = fmaxf(o, 0.f);
    X[(size_t)i*DD + tid] = o;
}

__global__ void finalize_stats(const double* acc, float* stats){
    if (threadIdx.x == 0 && blockIdx.x == 0){
        double n = (double)NELEM;
        double mu = acc[0] / n;
        double var = acc[1] / n - mu*mu;
        stats[0] = (float)mu;
        stats[1] = (float)(1.0 / (sqrt(var) + 1e-5));
    }
}

// ----------------------------------------------------------------------------
// Sinkhorn passes: single-pass LSE (no max shift; args bounded), fast exp
// ----------------------------------------------------------------------------
__global__ __launch_bounds__(256)
void sink_row(const float* __restrict__ Mm, const float* __restrict__ stats,
              const float* __restrict__ c, float* __restrict__ r){
    __shared__ float red[256];
    int i = blockIdx.x, tid = threadIdx.x;
    float inv = stats[1];
    float muinv = stats[0]*inv;
    const float* row = Mm + (size_t)i*NS;
    float s = 0.f;
    for (int j = tid; j < NS; j += 256)
        s += fexp(fmaf(row[j], inv, -muinv - c[j]));
    s = bsum256(s, red);
    if (tid == 0) r[i] = logf(s);
}

__global__ void sink_col(const float* __restrict__ Mm, const float* __restrict__ stats,
                         const float* __restrict__ r, float* __restrict__ c){
    __shared__ float red[32][8];
    int tx = threadIdx.x, ty = threadIdx.y;  // (8,32)
    int j = blockIdx.x*8 + tx;
    float inv = stats[1];
    float muinv = stats[0]*inv;
    float s = 0.f;
    for (int i = ty; i < NS; i += 32)
        s += fexp(fmaf(Mm[(size_t)i*NS + j], inv, -muinv - r[i]));
    red[ty][tx] = s; __syncthreads();
    #pragma unroll
    for (int off = 16; off > 0; off >>= 1){
        if (ty < off) red[ty][tx] += red[ty+off][tx];
        __syncthreads();
    }
    if (ty == 0) c[j] = logf(red[0][tx]);
}

__global__ __launch_bounds__(256)
void match_kernel(const float* __restrict__ Mm, const float* __restrict__ r,
                  const float* __restrict__ c, const int* __restrict__ lab,
                  const float* __restrict__ stats, double* acc){
    __shared__ float red[256];
    int i = blockIdx.x, tid = threadIdx.x;
    float inv = stats[1];
    float muinv = stats[0]*inv;
    float ri = r[i];
    int li = lab[i];
    const float* row = Mm + (size_t)i*NS;
    float s = 0.f;
    for (int j = tid; j < NS; j += 256){
        float p = fexp(fmaf(row[j], inv, -muinv - ri - c[j]));
        float gt = (li == lab[NS + j]) ? 1.f : 0.f;
        s += fabsf(p - gt);
    }
    s = bsum256(s, red);
    if (tid == 0) atomicAdd(acc + 2, (double)s);
}

// ----------------------------------------------------------------------------
// SupCon support
// ----------------------------------------------------------------------------
__global__ __launch_bounds__(256)
void fnorm_kernel(const float* __restrict__ X, float* __restrict__ F){
    __shared__ float red[256];
    int i = blockIdx.x, tid = threadIdx.x;
    float x = X[(size_t)i*DD + tid];
    float ss = bsum256(x*x, red);
    F[(size_t)i*DD + tid] = x / (sqrtf(ss) + 1e-8f);
}

__global__ void hist_kernel(const int* __restrict__ lab, int* hist){
    int idx = blockIdx.x*blockDim.x + threadIdx.x;
    if (idx < NF) atomicAdd(&hist[lab[idx]], 1);
}

__global__ __launch_bounds__(256)
void supcon_final(const float* __restrict__ esum, const float* __restrict__ psum,
                  const int* __restrict__ lab, const int* __restrict__ hist,
                  double* acc){
    __shared__ float red[256];
    int i = blockIdx.x*256 + threadIdx.x;
    float cnt = (float)(hist[lab[i]] - 1);
    float v = psum[i]/cnt - logf(esum[i]);
    float s = bsum256(v, red);
    if (threadIdx.x == 0) atomicAdd(acc + 3, (double)s);
}

__global__ void finalize_kernel(const double* acc, float* out){
    if (threadIdx.x == 0 && blockIdx.x == 0){
        double supcon = -(acc[3] / (double)NF);
        out[0] = (float)(acc[2] + 0.1 * supcon);
    }
}

// ----------------------------------------------------------------------------
// Host driver
// ----------------------------------------------------------------------------
extern "C" void kernel_launch(void* const* d_in, const int* in_sizes, int n_in,
                              void* d_out, int out_size){
    const float* nodes_src = (const float*)d_in[0];
    const float* nodes_tgt = (const float*)d_in[1];
    const int*   labels_src = (const int*)d_in[2];
    const int*   labels_tgt = (const int*)d_in[3];
    const float* w1 = (const float*)d_in[4];
    const float* b1 = (const float*)d_in[5];
    const float* w2 = (const float*)d_in[6];
    const float* b2 = (const float*)d_in[7];
    const float* wq = (const float*)d_in[8];
    const float* wk = (const float*)d_in[9];
    const float* wv = (const float*)d_in[10];
    const float* wo = (const float*)d_in[11];
    const float* cq = (const float*)d_in[12];
    const float* ck = (const float*)d_in[13];
    const float* cv = (const float*)d_in[14];
    const float* co = (const float*)d_in[15];
    const float* Am = (const float*)d_in[16];

    float *in_,*x0,*x1,*x2,*q,*vw,*fn,*S0,*S1,*Wp,*rsum,*rv,*cvv,*esum,*psum,*stats;
    double* dacc; int *lab, *hist;
    cudaGetSymbolAddress((void**)&in_, g_in);
    cudaGetSymbolAddress((void**)&x0, g_x0);
    cudaGetSymbolAddress((void**)&x1, g_x1);
    cudaGetSymbolAddress((void**)&x2, g_x2);
    cudaGetSymbolAddress((void**)&q,  g_q);
    cudaGetSymbolAddress((void**)&vw, g_vw);
    cudaGetSymbolAddress((void**)&fn, g_fn);
    cudaGetSymbolAddress((void**)&S0, g_S0);
    cudaGetSymbolAddress((void**)&S1, g_S1);
    cudaGetSymbolAddress((void**)&Wp, g_Wp);
    cudaGetSymbolAddress((void**)&rsum, g_rsum);
    cudaGetSymbolAddress((void**)&rv, g_r);
    cudaGetSymbolAddress((void**)&cvv, g_c);
    cudaGetSymbolAddress((void**)&esum, g_esum);
    cudaGetSymbolAddress((void**)&psum, g_psum);
    cudaGetSymbolAddress((void**)&stats, g_stats);
    cudaGetSymbolAddress((void**)&dacc, g_dacc);
    cudaGetSymbolAddress((void**)&lab, g_lab);
    cudaGetSymbolAddress((void**)&hist, g_hist);

    float* Wqk_i = Wp;
    float* Wvo_i = Wp + DD*DD;
    float* Wqk_c = Wp + 2*DD*DD;
    float* Wvo_c = Wp + 3*DD*DD;

    // zeroing + packing
    cudaMemsetAsync(dacc, 0, 4*sizeof(double));
    cudaMemsetAsync(hist, 0, 16*sizeof(int));
    cudaMemsetAsync(cvv, 0, NS*sizeof(float));
    cudaMemsetAsync(esum, 0, NF*sizeof(float));
    cudaMemsetAsync(psum, 0, NF*sizeof(float));
    cudaMemcpyAsync(in_, nodes_src, HALF*sizeof(float), cudaMemcpyDeviceToDevice);
    cudaMemcpyAsync(in_ + HALF, nodes_tgt, HALF*sizeof(float), cudaMemcpyDeviceToDevice);
    cudaMemcpyAsync(lab, labels_src, NS*sizeof(int), cudaMemcpyDeviceToDevice);
    cudaMemcpyAsync(lab + NS, labels_tgt, NS*sizeof(int), cudaMemcpyDeviceToDevice);

    // weight precompute: Wqk = Wq@Wk^T/16, Wvo = Wv@Wo
    gemm_nt<<<dim3(2,2), 256>>>(wq, wk, Wqk_i, DD, DD, DD, 0.0625f);
    gemm_nt<<<dim3(2,2), 256>>>(cq, ck, Wqk_c, DD, DD, DD, 0.0625f);
    gemm_aw<<<DD/8, 256>>>(wv, wo, Wvo_i, DD);
    gemm_aw<<<DD/8, 256>>>(cv, co, Wvo_c, DD);

    // head_in (stacked M=4096): LN(ReLU(LN(X@w1+b1))@w2+b2)
    gemm_nn<<<dim3(DD/64, NF/64), 256>>>(in_, w1, b1, q, NF, DD, DD);
    ln_kernel<<<NF, 256>>>(q, 1);
    gemm_nn<<<dim3(DD/64, NF/64), 256>>>(q, w2, b2, x0, NF, DD, DD);
    ln_kernel<<<NF, 256>>>(x0, 0);

    // ---- intra-domain attention (both domains batched) ----
    gemm_nn<<<dim3(DD/64, NF/64), 256>>>(x0, Wqk_i, nullptr, q,  NF, DD, DD);
    gemm_nn<<<dim3(DD/64, NF/64), 256>>>(x0, Wvo_i, nullptr, vw, NF, DD, DD);
    cudaMemsetAsync(rsum, 0, NF*sizeof(float));
    nt_exp<<<dim3(NS/128, NS/128, 2), 256>>>(q, x0, S0, q + HALF, x0 + HALF, S1, rsum);
    gemm_pv<<<dim3(DD/64, NS/64, 2), 256>>>(S0, vw, S1, vw + HALF, rsum, x0, x1);

    // ---- cross-domain attention ----
    gemm_nn<<<dim3(DD/64, NF/64), 256>>>(x1, Wqk_c, nullptr, q,  NF, DD, DD);
    gemm_nn<<<dim3(DD/64, NF/64), 256>>>(x1, Wvo_c, nullptr, vw, NF, DD, DD);
    cudaMemsetAsync(rsum, 0, NF*sizeof(float));
    nt_exp<<<dim3(NS/128, NS/128, 2), 256>>>(q, x1 + HALF, S0, q + HALF, x1, S1, rsum);
    gemm_pv<<<dim3(DD/64, NS/64, 2), 256>>>(S0, vw + HALF, S1, vw, rsum, x1, x2);

    // ---- affinity M = (src2@A)@tgt2^T with fused stats ----
    gemm_nn<<<dim3(DD/64, NS/64), 256>>>(x2, Am, nullptr, q, NS, DD, DD);
    nt_stats<<<dim3(NS/128, NS/128), 256>>>(q, x2 + HALF, S0, dacc);
    finalize_stats<<<1, 32>>>(dacc, stats);

    // ---- Sinkhorn (lazy potentials, single-pass LSE) ----
    for (int it = 0; it < 10; it++){
        sink_row<<<NS, 256>>>(S0, stats, cvv, rv);
        sink_col<<<NS/8, dim3(8,32)>>>(S0, stats, rv, cvv);
    }
    match_kernel<<<NS, 256>>>(S0, rv, cvv, lab, stats, dacc);

    // ---- SupCon (triangular fused) ----
    fnorm_kernel<<<NF, 256>>>(x2, fn);
    hist_kernel<<<16, 256>>>(lab, hist);
    nt_supcon<<<dim3(NF/128, NF/128), 256>>>(fn, lab, esum, psum);
    supcon_final<<<NF/256, 256>>>(esum, psum, lab, hist, dacc);

    finalize_kernel<<<1, 32>>>(dacc, (float*)d_out);
}

// round 5
// speedup vs baseline: 3.0695x; 2.2227x over previous
#include <cuda_runtime.h>
#include <cuda_bf16.h>
#include <math.h>
#include <stdint.h>

#define NS 2048
#define DD 256
#define NF 4096
#define HALF ((long long)NS*DD)
#define NELEM ((long long)NS*NS)
#define SUPCON_SCALE 14.285714285714286f

// ---------------- helpers ----------------
__device__ __forceinline__ uint32_t smem_to_u32(const void* p){
    uint32_t a;
    asm("{ .reg .u64 t; cvta.to.shared.u64 t, %1; cvt.u32.u64 %0, t; }" : "=r"(a) : "l"(p));
    return a;
}
__device__ __forceinline__ void ldsm_x4(uint32_t* r, uint32_t addr){
    asm volatile("ldmatrix.sync.aligned.m8n8.x4.shared.b16 {%0,%1,%2,%3}, [%4];"
        : "=r"(r[0]), "=r"(r[1]), "=r"(r[2]), "=r"(r[3]) : "r"(addr));
}
__device__ __forceinline__ void ldsm_x2(uint32_t* r, uint32_t addr){
    asm volatile("ldmatrix.sync.aligned.m8n8.x2.shared.b16 {%0,%1}, [%2];"
        : "=r"(r[0]), "=r"(r[1]) : "r"(addr));
}
__device__ __forceinline__ void mma16816(float* c, const uint32_t* a, const uint32_t* b){
    asm volatile("mma.sync.aligned.m16n8k16.row.col.f32.bf16.bf16.f32 "
        "{%0,%1,%2,%3}, {%4,%5,%6,%7}, {%8,%9}, {%0,%1,%2,%3};"
        : "+f"(c[0]), "+f"(c[1]), "+f"(c[2]), "+f"(c[3])
        : "r"(a[0]), "r"(a[1]), "r"(a[2]), "r"(a[3]), "r"(b[0]), "r"(b[1]));
}
__device__ __forceinline__ float fexp(float x){
    float t = x * 1.4426950408889634f;
    float r = rintf(t);
    float f = t - r;
    float p =            1.3333558146e-3f;
    p = fmaf(p, f, 9.6181291076e-3f);
    p = fmaf(p, f, 5.5504108664e-2f);
    p = fmaf(p, f, 2.4022650696e-1f);
    p = fmaf(p, f, 6.9314718056e-1f);
    p = fmaf(p, f, 1.0f);
    float res = __int_as_float(__float_as_int(p) + (((int)r) << 23));
    return (x < -87.0f) ? 0.0f : res;
}
__device__ __forceinline__ float bsum256(float v, float* red){
    int tid = threadIdx.x;
    red[tid] = v; __syncthreads();
    #pragma unroll
    for (int o = 128; o > 0; o >>= 1){
        if (tid < o) red[tid] += red[tid + o];
        __syncthreads();
    }
    float r = red[0]; __syncthreads();
    return r;
}

// ---------------- scratch ----------------
__device__ __nv_bfloat16 g_inb[NF*DD], g_h1b[NF*DD], g_x0b[NF*DD], g_x1b[NF*DD], g_x2b[NF*DD];
__device__ __nv_bfloat16 g_qb[NF*DD], g_kb[NF*DD], g_vb[NF*DD], g_vwT[NF*DD], g_fnb[NF*DD];
__device__ __nv_bfloat16 g_Pb[2*NELEM];
__device__ __nv_bfloat16 g_wT[11*DD*DD];
__device__ float g_tf[NF*DD], g_x0[NF*DD], g_x1[NF*DD], g_x2[NF*DD];
__device__ float g_S0[NELEM];
__device__ float g_rsum[NF], g_r[NS], g_c[NS], g_esum[NF], g_psum[NF], g_stats[2];
__device__ double g_dacc[4];
__device__ int g_lab[NF], g_hist[16];

// ============================================================================
// Generic bf16 HMMA NT GEMM, 128x128 tile, 8 warps (2x4), 64x32 warp tiles.
// C = A[M,K] @ B[N,K]^T
// epi: 0 bf16*scale | 1 f32+bias | 2 transposed bf16 | 3 exp+rowsum+bf16
//      4 PV: f32+bf16 = acc/rsum + res | 5 f32 + stats | 6 supcon row-acc
// ============================================================================
__global__ __launch_bounds__(256)
void tc_nt(const __nv_bfloat16* A, int lda, long long azs,
           const __nv_bfloat16* B, int ldb, long long bzs,
           int K, int epi, float scale,
           float* outF, __nv_bfloat16* outB, int ldc, long long czs, int mzoff,
           const float* bias, const float* rsum, float* rsumW,
           const float* resF, double* dacc,
           const int* lab, float* esum, float* psum)
{
    __shared__ __nv_bfloat16 SA[128*72];
    __shared__ __nv_bfloat16 SB[128*72];
    __shared__ float red[256];

    int z = blockIdx.z;
    A += (long long)z * azs;
    B += (long long)z * bzs;
    if (outB) outB += (long long)z * czs;

    int tid = threadIdx.x, wid = tid >> 5, lane = tid & 31;
    int wr = wid >> 2, wc = wid & 3;
    int row0 = blockIdx.y * 128, col0 = blockIdx.x * 128;

    uint32_t sA = smem_to_u32(SA), sB = smem_to_u32(SB);

    float acc[4][4][4];
    #pragma unroll
    for (int mi = 0; mi < 4; mi++)
        #pragma unroll
        for (int ni = 0; ni < 4; ni++)
            #pragma unroll
            for (int q = 0; q < 4; q++) acc[mi][ni][q] = 0.f;

    // ldmatrix lane address components
    int aRow  = wr*64 + (lane & 7) + ((lane >> 3) & 1)*8;  // + mi*16
    int aKoff = (lane >> 4)*8;                             // + ks*16
    int l16   = lane & 15;
    int bRow  = wc*32 + (l16 & 7);                         // + ni*8
    int bKoff = (l16 >> 3)*8;                              // + ks*16

    int nch = K >> 6;
    for (int c = 0; c < nch; c++){
        int kc = c << 6;
        __syncthreads();
        #pragma unroll
        for (int i = 0; i < 4; i++){
            int lin = i*256 + tid;
            int r = lin >> 3, c8 = (lin & 7) << 3;
            *(uint4*)&SA[r*72 + c8] = *(const uint4*)(A + (size_t)(row0+r)*lda + kc + c8);
            *(uint4*)&SB[r*72 + c8] = *(const uint4*)(B + (size_t)(col0+r)*ldb + kc + c8);
        }
        __syncthreads();
        #pragma unroll
        for (int ks = 0; ks < 4; ks++){
            uint32_t af[4][4], bf[4][2];
            #pragma unroll
            for (int mi = 0; mi < 4; mi++)
                ldsm_x4(af[mi], sA + (uint32_t)(((aRow + mi*16)*72 + ks*16 + aKoff) * 2));
            #pragma unroll
            for (int ni = 0; ni < 4; ni++)
                ldsm_x2(bf[ni], sB + (uint32_t)(((bRow + ni*8)*72 + ks*16 + bKoff) * 2));
            #pragma unroll
            for (int mi = 0; mi < 4; mi++)
                #pragma unroll
                for (int ni = 0; ni < 4; ni++)
                    mma16816(acc[mi][ni], af[mi], bf[ni]);
        }
    }

    // ---------------- epilogue ----------------
    int lr = lane >> 2, lc2 = (lane & 3) << 1;
    int colB = col0 + wc*32;
    float s1 = 0.f, s2 = 0.f;

    #pragma unroll
    for (int mi = 0; mi < 4; mi++){
        #pragma unroll
        for (int h = 0; h < 2; h++){
            int r = row0 + wr*64 + mi*16 + lr + h*8;   // row in this z-slice
            if (epi == 0){
                #pragma unroll
                for (int ni = 0; ni < 4; ni++){
                    int cc = colB + ni*8 + lc2;
                    float v0 = acc[mi][ni][h*2+0]*scale, v1 = acc[mi][ni][h*2+1]*scale;
                    *(__nv_bfloat162*)(outB + (size_t)r*ldc + cc) = __floats2bfloat162_rn(v0, v1);
                }
            } else if (epi == 1){
                #pragma unroll
                for (int ni = 0; ni < 4; ni++){
                    int cc = colB + ni*8 + lc2;
                    float2 o = make_float2(acc[mi][ni][h*2+0] + bias[cc],
                                           acc[mi][ni][h*2+1] + bias[cc+1]);
                    *(float2*)(outF + (size_t)r*ldc + cc) = o;
                }
            } else if (epi == 2){
                #pragma unroll
                for (int ni = 0; ni < 4; ni++){
                    int cc = colB + ni*8 + lc2;
                    outB[(size_t)cc*ldc + r]     = __float2bfloat16(acc[mi][ni][h*2+0]);
                    outB[(size_t)(cc+1)*ldc + r] = __float2bfloat16(acc[mi][ni][h*2+1]);
                }
            } else if (epi == 3){
                float part = 0.f;
                #pragma unroll
                for (int ni = 0; ni < 4; ni++){
                    int cc = colB + ni*8 + lc2;
                    float e0 = fexp(acc[mi][ni][h*2+0]), e1 = fexp(acc[mi][ni][h*2+1]);
                    part += e0 + e1;
                    *(__nv_bfloat162*)(outB + (size_t)r*ldc + cc) = __floats2bfloat162_rn(e0, e1);
                }
                part += __shfl_xor_sync(0xffffffffu, part, 1);
                part += __shfl_xor_sync(0xffffffffu, part, 2);
                if ((lane & 3) == 0) atomicAdd(&rsumW[z*mzoff + r], part);
            } else if (epi == 4){
                int mg = z*mzoff + r;
                float rinv = 1.0f / rsum[mg];
                #pragma unroll
                for (int ni = 0; ni < 4; ni++){
                    int cc = colB + ni*8 + lc2;
                    float v0 = fmaf(acc[mi][ni][h*2+0], rinv, resF[(size_t)mg*ldc + cc]);
                    float v1 = fmaf(acc[mi][ni][h*2+1], rinv, resF[(size_t)mg*ldc + cc+1]);
                    *(float2*)(outF + (size_t)mg*ldc + cc) = make_float2(v0, v1);
                    *(__nv_bfloat162*)(outB + (size_t)mg*ldc + cc) = __floats2bfloat162_rn(v0, v1);
                }
            } else if (epi == 5){
                #pragma unroll
                for (int ni = 0; ni < 4; ni++){
                    int cc = colB + ni*8 + lc2;
                    float v0 = acc[mi][ni][h*2+0], v1 = acc[mi][ni][h*2+1];
                    *(float2*)(outF + (size_t)r*ldc + cc) = make_float2(v0, v1);
                    s1 += v0 + v1; s2 += v0*v0 + v1*v1;
                }
            } else {
                int rlab = lab[r];
                float pe = 0.f, ps = 0.f;
                #pragma unroll
                for (int ni = 0; ni < 4; ni++){
                    int cc = colB + ni*8 + lc2;
                    float l0 = acc[mi][ni][h*2+0]*scale, l1 = acc[mi][ni][h*2+1]*scale;
                    if (cc != r){
                        pe += fexp(l0);
                        if (lab[cc] == rlab) ps += l0;
                    }
                    if (cc+1 != r){
                        pe += fexp(l1);
                        if (lab[cc+1] == rlab) ps += l1;
                    }
                }
                pe += __shfl_xor_sync(0xffffffffu, pe, 1);
                pe += __shfl_xor_sync(0xffffffffu, pe, 2);
                ps += __shfl_xor_sync(0xffffffffu, ps, 1);
                ps += __shfl_xor_sync(0xffffffffu, ps, 2);
                if ((lane & 3) == 0){
                    atomicAdd(&esum[r], pe);
                    atomicAdd(&psum[r], ps);
                }
            }
        }
    }
    if (epi == 5){
        float bs = bsum256(s1, red), bss = bsum256(s2, red);
        if (tid == 0){ atomicAdd(dacc, (double)bs); atomicAdd(dacc+1, (double)bss); }
    }
}

// ---------------- small kernels ----------------
__global__ __launch_bounds__(256)
void cvt_in(const float* __restrict__ a, const float* __restrict__ b, __nv_bfloat16* __restrict__ o){
    int i = blockIdx.x, t = threadIdx.x;
    const float* src = (i < NS) ? a + (size_t)i*DD : b + (size_t)(i-NS)*DD;
    o[(size_t)i*DD + t] = __float2bfloat16(src[t]);
}
struct P11 { const float* p[11]; };
__global__ __launch_bounds__(256)
void cvtT11(P11 s, __nv_bfloat16* __restrict__ o){
    int w = blockIdx.y, n = blockIdx.x, k = threadIdx.x;
    o[(size_t)w*DD*DD + (size_t)n*DD + k] = __float2bfloat16(s.p[w][(size_t)k*DD + n]);
}
__global__ __launch_bounds__(256)
void ln_kernel(const float* __restrict__ X, float* __restrict__ outF,
               __nv_bfloat16* __restrict__ outB, int relu){
    __shared__ float red[256];
    int i = blockIdx.x, t = threadIdx.x;
    float v = X[(size_t)i*DD + t];
    float s  = bsum256(v, red);
    float ss = bsum256(v*v, red);
    float m = s*(1.f/DD);
    float var = ss*(1.f/DD) - m*m;
    float o = (v - m) * rsqrtf(var + 1e-5f);
    if (relu) o = fmaxf(o, 0.f);
    if (outF) outF[(size_t)i*DD + t] = o;
    outB[(size_t)i*DD + t] = __float2bfloat16(o);
}
__global__ __launch_bounds__(256)
void fnorm_kernel(const float* __restrict__ X, __nv_bfloat16* __restrict__ F){
    __shared__ float red[256];
    int i = blockIdx.x, t = threadIdx.x;
    float x = X[(size_t)i*DD + t];
    float ss = bsum256(x*x, red);
    F[(size_t)i*DD + t] = __float2bfloat16(x / (sqrtf(ss) + 1e-8f));
}
__global__ void finalize_stats(const double* acc, float* st){
    if (threadIdx.x == 0 && blockIdx.x == 0){
        double n = (double)NELEM;
        double mu = acc[0] / n;
        double var = acc[1] / n - mu*mu;
        st[0] = (float)mu;
        st[1] = (float)(1.0 / (sqrt(var) + 1e-5));
    }
}
__global__ __launch_bounds__(256)
void sink_row(const float* __restrict__ Mm, const float* __restrict__ st,
              const float* __restrict__ c, float* __restrict__ r){
    __shared__ float red[256];
    int i = blockIdx.x, t = threadIdx.x;
    float inv = st[1], muinv = st[0]*inv;
    const float* row = Mm + (size_t)i*NS;
    float s = 0.f;
    for (int j = t; j < NS; j += 256)
        s += fexp(fmaf(row[j], inv, -muinv - c[j]));
    s = bsum256(s, red);
    if (t == 0) r[i] = logf(s);
}
__global__ void sink_col(const float* __restrict__ Mm, const float* __restrict__ st,
                         const float* __restrict__ r, float* __restrict__ c){
    __shared__ float red[32][8];
    int tx = threadIdx.x, ty = threadIdx.y;
    int j = blockIdx.x*8 + tx;
    float inv = st[1], muinv = st[0]*inv;
    float s = 0.f;
    for (int i = ty; i < NS; i += 32)
        s += fexp(fmaf(Mm[(size_t)i*NS + j], inv, -muinv - r[i]));
    red[ty][tx] = s; __syncthreads();
    #pragma unroll
    for (int o = 16; o > 0; o >>= 1){
        if (ty < o) red[ty][tx] += red[ty+o][tx];
        __syncthreads();
    }
    if (ty == 0) c[j] = logf(red[0][tx]);
}
__global__ __launch_bounds__(256)
void match_kernel(const float* __restrict__ Mm, const float* __restrict__ r,
                  const float* __restrict__ c, const int* __restrict__ lab,
                  const float* __restrict__ st, double* acc){
    __shared__ float red[256];
    int i = blockIdx.x, t = threadIdx.x;
    float inv = st[1], muinv = st[0]*inv;
    float ri = r[i];
    int li = lab[i];
    const float* row = Mm + (size_t)i*NS;
    float s = 0.f;
    for (int j = t; j < NS; j += 256){
        float p = fexp(fmaf(row[j], inv, -muinv - ri - c[j]));
        float gt = (li == lab[NS + j]) ? 1.f : 0.f;
        s += fabsf(p - gt);
    }
    s = bsum256(s, red);
    if (t == 0) atomicAdd(acc + 2, (double)s);
}
__global__ void hist_kernel(const int* __restrict__ lab, int* h){
    int i = blockIdx.x*blockDim.x + threadIdx.x;
    if (i < NF) atomicAdd(&h[lab[i]], 1);
}
__global__ __launch_bounds__(256)
void supcon_final(const float* __restrict__ es, const float* __restrict__ ps,
                  const int* __restrict__ lab, const int* __restrict__ h, double* acc){
    __shared__ float red[256];
    int i = blockIdx.x*256 + threadIdx.x;
    float cnt = (float)(h[lab[i]] - 1);
    float v = ps[i]/cnt - logf(es[i]);
    float s = bsum256(v, red);
    if (threadIdx.x == 0) atomicAdd(acc + 3, (double)s);
}
__global__ void finalize_kernel(const double* acc, float* out){
    if (threadIdx.x == 0 && blockIdx.x == 0)
        out[0] = (float)(acc[2] + 0.1 * (-(acc[3] / (double)NF)));
}

// ---------------- host ----------------
extern "C" void kernel_launch(void* const* d_in, const int* in_sizes, int n_in,
                              void* d_out, int out_size){
    const float *nodes_src=(const float*)d_in[0], *nodes_tgt=(const float*)d_in[1];
    const int *labels_src=(const int*)d_in[2], *labels_tgt=(const int*)d_in[3];
    const float *w1=(const float*)d_in[4], *b1=(const float*)d_in[5];
    const float *w2=(const float*)d_in[6], *b2=(const float*)d_in[7];
    const float *wq=(const float*)d_in[8], *wk=(const float*)d_in[9];
    const float *wv=(const float*)d_in[10], *wo=(const float*)d_in[11];
    const float *cq=(const float*)d_in[12], *ck=(const float*)d_in[13];
    const float *cv=(const float*)d_in[14], *co=(const float*)d_in[15];
    const float *Am=(const float*)d_in[16];

    __nv_bfloat16 *inb,*h1b,*x0b,*x1b,*x2b,*qb,*kb,*vb,*vwT,*fnb,*Pb,*wT;
    float *tf,*x0,*x1,*x2,*S0,*rsum,*rv,*cvv,*esum,*psum,*stats;
    double* dacc; int *lab,*hist;
    cudaGetSymbolAddress((void**)&inb,g_inb); cudaGetSymbolAddress((void**)&h1b,g_h1b);
    cudaGetSymbolAddress((void**)&x0b,g_x0b); cudaGetSymbolAddress((void**)&x1b,g_x1b);
    cudaGetSymbolAddress((void**)&x2b,g_x2b); cudaGetSymbolAddress((void**)&qb,g_qb);
    cudaGetSymbolAddress((void**)&kb,g_kb);   cudaGetSymbolAddress((void**)&vb,g_vb);
    cudaGetSymbolAddress((void**)&vwT,g_vwT); cudaGetSymbolAddress((void**)&fnb,g_fnb);
    cudaGetSymbolAddress((void**)&Pb,g_Pb);   cudaGetSymbolAddress((void**)&wT,g_wT);
    cudaGetSymbolAddress((void**)&tf,g_tf);   cudaGetSymbolAddress((void**)&x0,g_x0);
    cudaGetSymbolAddress((void**)&x1,g_x1);   cudaGetSymbolAddress((void**)&x2,g_x2);
    cudaGetSymbolAddress((void**)&S0,g_S0);   cudaGetSymbolAddress((void**)&rsum,g_rsum);
    cudaGetSymbolAddress((void**)&rv,g_r);    cudaGetSymbolAddress((void**)&cvv,g_c);
    cudaGetSymbolAddress((void**)&esum,g_esum); cudaGetSymbolAddress((void**)&psum,g_psum);
    cudaGetSymbolAddress((void**)&stats,g_stats); cudaGetSymbolAddress((void**)&dacc,g_dacc);
    cudaGetSymbolAddress((void**)&lab,g_lab); cudaGetSymbolAddress((void**)&hist,g_hist);

    const int WSZ = DD*DD;
    __nv_bfloat16 *w1T=wT, *w2T=wT+WSZ, *wqT=wT+2*WSZ, *wkT=wT+3*WSZ, *wvT=wT+4*WSZ,
                  *woT=wT+5*WSZ, *cqT=wT+6*WSZ, *ckT=wT+7*WSZ, *cvT=wT+8*WSZ,
                  *coT=wT+9*WSZ, *AT=wT+10*WSZ;

    cudaMemsetAsync(dacc, 0, 4*sizeof(double));
    cudaMemsetAsync(hist, 0, 16*sizeof(int));
    cudaMemsetAsync(cvv, 0, NS*sizeof(float));
    cudaMemsetAsync(esum, 0, NF*sizeof(float));
    cudaMemsetAsync(psum, 0, NF*sizeof(float));
    cudaMemcpyAsync(lab, labels_src, NS*sizeof(int), cudaMemcpyDeviceToDevice);
    cudaMemcpyAsync(lab+NS, labels_tgt, NS*sizeof(int), cudaMemcpyDeviceToDevice);

    cvt_in<<<NF, 256>>>(nodes_src, nodes_tgt, inb);
    P11 s11; s11.p[0]=w1; s11.p[1]=w2; s11.p[2]=wq; s11.p[3]=wk; s11.p[4]=wv;
    s11.p[5]=wo; s11.p[6]=cq; s11.p[7]=ck; s11.p[8]=cv; s11.p[9]=co; s11.p[10]=Am;
    cvtT11<<<dim3(DD, 11), 256>>>(s11, wT);

    auto TC = [&](dim3 g, const __nv_bfloat16* A, int lda, long long azs,
                  const __nv_bfloat16* B, int ldb, long long bzs,
                  int K, int epi, float sc, float* oF, __nv_bfloat16* oB,
                  int ldc, long long czs, int mzoff,
                  const float* bias_, const float* rs, float* rsW, const float* res){
        tc_nt<<<g, 256>>>(A, lda, azs, B, ldb, bzs, K, epi, sc, oF, oB, ldc, czs, mzoff,
                          bias_, rs, rsW, res, dacc, lab, esum, psum);
    };

    // head_in
    TC(dim3(2,32,1), inb,256,0, w1T,256,0, 256, 1, 1.f, tf, nullptr, 256,0,0, b1, nullptr,nullptr,nullptr);
    ln_kernel<<<NF,256>>>(tf, nullptr, h1b, 1);
    TC(dim3(2,32,1), h1b,256,0, w2T,256,0, 256, 1, 1.f, tf, nullptr, 256,0,0, b2, nullptr,nullptr,nullptr);
    ln_kernel<<<NF,256>>>(tf, x0, x0b, 0);

    // intra attention
    TC(dim3(2,32,1), x0b,256,0, wqT,256,0, 256, 0, 0.0625f, nullptr, qb, 256,0,0, nullptr,nullptr,nullptr,nullptr);
    TC(dim3(2,32,1), x0b,256,0, wkT,256,0, 256, 0, 1.f, nullptr, kb, 256,0,0, nullptr,nullptr,nullptr,nullptr);
    TC(dim3(2,32,1), x0b,256,0, wvT,256,0, 256, 0, 1.f, nullptr, vb, 256,0,0, nullptr,nullptr,nullptr,nullptr);
    TC(dim3(2,32,1), vb,256,0, woT,256,0, 256, 2, 1.f, nullptr, vwT, NF,0,0, nullptr,nullptr,nullptr,nullptr);
    cudaMemsetAsync(rsum, 0, NF*sizeof(float));
    TC(dim3(16,16,2), qb,256,HALF, kb,256,HALF, 256, 3, 1.f, nullptr, Pb, NS, NELEM, NS, nullptr,nullptr,rsum,nullptr);
    TC(dim3(2,16,2), Pb,NS,NELEM, vwT,NF,2048, NS, 4, 1.f, x1, x1b, 256,0, NS, nullptr,rsum,nullptr,x0);

    // cross attention
    TC(dim3(2,32,1), x1b,256,0, cqT,256,0, 256, 0, 0.0625f, nullptr, qb, 256,0,0, nullptr,nullptr,nullptr,nullptr);
    TC(dim3(2,32,1), x1b,256,0, ckT,256,0, 256, 0, 1.f, nullptr, kb, 256,0,0, nullptr,nullptr,nullptr,nullptr);
    TC(dim3(2,32,1), x1b,256,0, cvT,256,0, 256, 0, 1.f, nullptr, vb, 256,0,0, nullptr,nullptr,nullptr,nullptr);
    TC(dim3(2,32,1), vb,256,0, coT,256,0, 256, 2, 1.f, nullptr, vwT, NF,0,0, nullptr,nullptr,nullptr,nullptr);
    cudaMemsetAsync(rsum, 0, NF*sizeof(float));
    TC(dim3(16,16,2), qb,256,HALF, kb+HALF,256,-HALF, 256, 3, 1.f, nullptr, Pb, NS, NELEM, NS, nullptr,nullptr,rsum,nullptr);
    TC(dim3(2,16,2), Pb,NS,NELEM, vwT+2048,NF,-2048, NS, 4, 1.f, x2, x2b, 256,0, NS, nullptr,rsum,nullptr,x1);

    // affinity + stats
    TC(dim3(2,16,1), x2b,256,0, AT,256,0, 256, 0, 1.f, nullptr, qb, 256,0,0, nullptr,nullptr,nullptr,nullptr);
    TC(dim3(16,16,1), qb,256,0, x2b+HALF,256,0, 256, 5, 1.f, S0, nullptr, NS,0,0, nullptr,nullptr,nullptr,nullptr);
    finalize_stats<<<1,32>>>(dacc, stats);

    // Sinkhorn
    for (int it = 0; it < 10; it++){
        sink_row<<<NS,256>>>(S0, stats, cvv, rv);
        sink_col<<<NS/8, dim3(8,32)>>>(S0, stats, rv, cvv);
    }
    match_kernel<<<NS,256>>>(S0, rv, cvv, lab, stats, dacc);

    // SupCon
    fnorm_kernel<<<NF,256>>>(x2, fnb);
    hist_kernel<<<16,256>>>(lab, hist);
    TC(dim3(32,32,1), fnb,256,0, fnb,256,0, 256, 6, SUPCON_SCALE, nullptr, nullptr, 0,0,0, nullptr,nullptr,nullptr,nullptr);
    supcon_final<<<NF/256,256>>>(esum, psum, lab, hist, dacc);

    finalize_kernel<<<1,32>>>(dacc, (float*)d_out);
}

// round 6
// speedup vs baseline: 3.8477x; 1.2535x over previous
#include <cuda_runtime.h>
#include <cuda_bf16.h>
#include <math.h>
#include <stdint.h>

#define NS 2048
#define DD 256
#define NF 4096
#define HALF ((long long)NS*DD)
#define NELEM ((long long)NS*NS)
#define SUPCON_SCALE 14.285714285714286f

// ---------------- helpers ----------------
__device__ __forceinline__ uint32_t smem_to_u32(const void* p){
    uint32_t a;
    asm("{ .reg .u64 t; cvta.to.shared.u64 t, %1; cvt.u32.u64 %0, t; }" : "=r"(a) : "l"(p));
    return a;
}
__device__ __forceinline__ void ldsm_x4(uint32_t* r, uint32_t addr){
    asm volatile("ldmatrix.sync.aligned.m8n8.x4.shared.b16 {%0,%1,%2,%3}, [%4];"
        : "=r"(r[0]), "=r"(r[1]), "=r"(r[2]), "=r"(r[3]) : "r"(addr));
}
__device__ __forceinline__ void ldsm_x2(uint32_t* r, uint32_t addr){
    asm volatile("ldmatrix.sync.aligned.m8n8.x2.shared.b16 {%0,%1}, [%2];"
        : "=r"(r[0]), "=r"(r[1]) : "r"(addr));
}
__device__ __forceinline__ void mma16816(float* c, const uint32_t* a, const uint32_t* b){
    asm volatile("mma.sync.aligned.m16n8k16.row.col.f32.bf16.bf16.f32 "
        "{%0,%1,%2,%3}, {%4,%5,%6,%7}, {%8,%9}, {%0,%1,%2,%3};"
        : "+f"(c[0]), "+f"(c[1]), "+f"(c[2]), "+f"(c[3])
        : "r"(a[0]), "r"(a[1]), "r"(a[2]), "r"(a[3]), "r"(b[0]), "r"(b[1]));
}
__device__ __forceinline__ float fexp(float x){
    float t = x * 1.4426950408889634f;
    float r = rintf(t);
    float f = t - r;
    float p =            1.3333558146e-3f;
    p = fmaf(p, f, 9.6181291076e-3f);
    p = fmaf(p, f, 5.5504108664e-2f);
    p = fmaf(p, f, 2.4022650696e-1f);
    p = fmaf(p, f, 6.9314718056e-1f);
    p = fmaf(p, f, 1.0f);
    float res = __int_as_float(__float_as_int(p) + (((int)r) << 23));
    return (x < -87.0f) ? 0.0f : res;
}
__device__ __forceinline__ float bsum256(float v, float* red){
    int tid = threadIdx.x;
    red[tid] = v; __syncthreads();
    #pragma unroll
    for (int o = 128; o > 0; o >>= 1){
        if (tid < o) red[tid] += red[tid + o];
        __syncthreads();
    }
    float r = red[0]; __syncthreads();
    return r;
}
__device__ __forceinline__ float wsum(float v){
    #pragma unroll
    for (int o = 16; o > 0; o >>= 1) v += __shfl_xor_sync(0xffffffffu, v, o);
    return v;
}

// ---------------- scratch ----------------
__device__ __nv_bfloat16 g_inb[NF*DD], g_h1b[NF*DD], g_x0b[NF*DD], g_x1b[NF*DD], g_x2b[NF*DD];
__device__ __nv_bfloat16 g_qb[NF*DD], g_kb[NF*DD], g_vb[NF*DD], g_vwT[NF*DD], g_fnb[NF*DD];
__device__ __nv_bfloat16 g_Pb[2*NELEM];     // attention P, later E / E^T
__device__ __nv_bfloat16 g_wT[11*DD*DD];
__device__ float g_tf[NF*DD], g_x0[NF*DD], g_x1[NF*DD], g_x2[NF*DD];
__device__ float g_S0[NELEM];
__device__ float g_rsum[NF], g_r[NS], g_c[NS], g_esum[NF], g_psum[NF], g_stats[2];
__device__ double g_dacc[4];
__device__ int g_lab[NF], g_hist[16];

// ============================================================================
// Generic bf16 HMMA NT GEMM, 128x128 tile, 8 warps (2x4), 64x32 warp tiles.
// epi: 0 bf16*scale | 1 f32+bias | 2 transposed bf16 | 3 exp+rowsum+bf16
//      4 PV: f32+bf16 = acc/rsum + res | 5 f32 + stats | 6 supcon row-acc
// ============================================================================
__global__ __launch_bounds__(256)
void tc_nt(const __nv_bfloat16* A, int lda, long long azs,
           const __nv_bfloat16* B, int ldb, long long bzs,
           int K, int epi, float scale,
           float* outF, __nv_bfloat16* outB, int ldc, long long czs, int mzoff,
           const float* bias, const float* rsum, float* rsumW,
           const float* resF, double* dacc,
           const int* lab, float* esum, float* psum)
{
    __shared__ __nv_bfloat16 SA[128*72];
    __shared__ __nv_bfloat16 SB[128*72];
    __shared__ float red[256];

    int z = blockIdx.z;
    A += (long long)z * azs;
    B += (long long)z * bzs;
    if (outB) outB += (long long)z * czs;

    int tid = threadIdx.x, wid = tid >> 5, lane = tid & 31;
    int wr = wid >> 2, wc = wid & 3;
    int row0 = blockIdx.y * 128, col0 = blockIdx.x * 128;

    uint32_t sA = smem_to_u32(SA), sB = smem_to_u32(SB);

    float acc[4][4][4];
    #pragma unroll
    for (int mi = 0; mi < 4; mi++)
        #pragma unroll
        for (int ni = 0; ni < 4; ni++)
            #pragma unroll
            for (int q = 0; q < 4; q++) acc[mi][ni][q] = 0.f;

    int aRow  = wr*64 + (lane & 7) + ((lane >> 3) & 1)*8;
    int aKoff = (lane >> 4)*8;
    int l16   = lane & 15;
    int bRow  = wc*32 + (l16 & 7);
    int bKoff = (l16 >> 3)*8;

    int nch = K >> 6;
    for (int c = 0; c < nch; c++){
        int kc = c << 6;
        __syncthreads();
        #pragma unroll
        for (int i = 0; i < 4; i++){
            int lin = i*256 + tid;
            int r = lin >> 3, c8 = (lin & 7) << 3;
            *(uint4*)&SA[r*72 + c8] = *(const uint4*)(A + (size_t)(row0+r)*lda + kc + c8);
            *(uint4*)&SB[r*72 + c8] = *(const uint4*)(B + (size_t)(col0+r)*ldb + kc + c8);
        }
        __syncthreads();
        #pragma unroll
        for (int ks = 0; ks < 4; ks++){
            uint32_t af[4][4], bf[4][2];
            #pragma unroll
            for (int mi = 0; mi < 4; mi++)
                ldsm_x4(af[mi], sA + (uint32_t)(((aRow + mi*16)*72 + ks*16 + aKoff) * 2));
            #pragma unroll
            for (int ni = 0; ni < 4; ni++)
                ldsm_x2(bf[ni], sB + (uint32_t)(((bRow + ni*8)*72 + ks*16 + bKoff) * 2));
            #pragma unroll
            for (int mi = 0; mi < 4; mi++)
                #pragma unroll
                for (int ni = 0; ni < 4; ni++)
                    mma16816(acc[mi][ni], af[mi], bf[ni]);
        }
    }

    int lr = lane >> 2, lc2 = (lane & 3) << 1;
    int colB = col0 + wc*32;
    float s1 = 0.f, s2 = 0.f;

    #pragma unroll
    for (int mi = 0; mi < 4; mi++){
        #pragma unroll
        for (int h = 0; h < 2; h++){
            int r = row0 + wr*64 + mi*16 + lr + h*8;
            if (epi == 0){
                #pragma unroll
                for (int ni = 0; ni < 4; ni++){
                    int cc = colB + ni*8 + lc2;
                    float v0 = acc[mi][ni][h*2+0]*scale, v1 = acc[mi][ni][h*2+1]*scale;
                    *(__nv_bfloat162*)(outB + (size_t)r*ldc + cc) = __floats2bfloat162_rn(v0, v1);
                }
            } else if (epi == 1){
                #pragma unroll
                for (int ni = 0; ni < 4; ni++){
                    int cc = colB + ni*8 + lc2;
                    float2 o = make_float2(acc[mi][ni][h*2+0] + bias[cc],
                                           acc[mi][ni][h*2+1] + bias[cc+1]);
                    *(float2*)(outF + (size_t)r*ldc + cc) = o;
                }
            } else if (epi == 2){
                #pragma unroll
                for (int ni = 0; ni < 4; ni++){
                    int cc = colB + ni*8 + lc2;
                    outB[(size_t)cc*ldc + r]     = __float2bfloat16(acc[mi][ni][h*2+0]);
                    outB[(size_t)(cc+1)*ldc + r] = __float2bfloat16(acc[mi][ni][h*2+1]);
                }
            } else if (epi == 3){
                float part = 0.f;
                #pragma unroll
                for (int ni = 0; ni < 4; ni++){
                    int cc = colB + ni*8 + lc2;
                    float e0 = fexp(acc[mi][ni][h*2+0]), e1 = fexp(acc[mi][ni][h*2+1]);
                    part += e0 + e1;
                    *(__nv_bfloat162*)(outB + (size_t)r*ldc + cc) = __floats2bfloat162_rn(e0, e1);
                }
                part += __shfl_xor_sync(0xffffffffu, part, 1);
                part += __shfl_xor_sync(0xffffffffu, part, 2);
                if ((lane & 3) == 0) atomicAdd(&rsumW[z*mzoff + r], part);
            } else if (epi == 4){
                int mg = z*mzoff + r;
                float rinv = 1.0f / rsum[mg];
                #pragma unroll
                for (int ni = 0; ni < 4; ni++){
                    int cc = colB + ni*8 + lc2;
                    float v0 = fmaf(acc[mi][ni][h*2+0], rinv, resF[(size_t)mg*ldc + cc]);
                    float v1 = fmaf(acc[mi][ni][h*2+1], rinv, resF[(size_t)mg*ldc + cc+1]);
                    *(float2*)(outF + (size_t)mg*ldc + cc) = make_float2(v0, v1);
                    *(__nv_bfloat162*)(outB + (size_t)mg*ldc + cc) = __floats2bfloat162_rn(v0, v1);
                }
            } else if (epi == 5){
                #pragma unroll
                for (int ni = 0; ni < 4; ni++){
                    int cc = colB + ni*8 + lc2;
                    float v0 = acc[mi][ni][h*2+0], v1 = acc[mi][ni][h*2+1];
                    *(float2*)(outF + (size_t)r*ldc + cc) = make_float2(v0, v1);
                    s1 += v0 + v1; s2 += v0*v0 + v1*v1;
                }
            } else {
                int rlab = lab[r];
                float pe = 0.f, ps = 0.f;
                #pragma unroll
                for (int ni = 0; ni < 4; ni++){
                    int cc = colB + ni*8 + lc2;
                    float l0 = acc[mi][ni][h*2+0]*scale, l1 = acc[mi][ni][h*2+1]*scale;
                    if (cc != r){
                        pe += fexp(l0);
                        if (lab[cc] == rlab) ps += l0;
                    }
                    if (cc+1 != r){
                        pe += fexp(l1);
                        if (lab[cc+1] == rlab) ps += l1;
                    }
                }
                pe += __shfl_xor_sync(0xffffffffu, pe, 1);
                pe += __shfl_xor_sync(0xffffffffu, pe, 2);
                ps += __shfl_xor_sync(0xffffffffu, ps, 1);
                ps += __shfl_xor_sync(0xffffffffu, ps, 2);
                if ((lane & 3) == 0){
                    atomicAdd(&esum[r], pe);
                    atomicAdd(&psum[r], ps);
                }
            }
        }
    }
    if (epi == 5){
        float bs = bsum256(s1, red), bss = bsum256(s2, red);
        if (tid == 0){ atomicAdd(dacc, (double)bs); atomicAdd(dacc+1, (double)bss); }
    }
}

// ---------------- small kernels ----------------
__global__ __launch_bounds__(256)
void cvt_in(const float* __restrict__ a, const float* __restrict__ b, __nv_bfloat16* __restrict__ o){
    int i = blockIdx.x, t = threadIdx.x;
    const float* src = (i < NS) ? a + (size_t)i*DD : b + (size_t)(i-NS)*DD;
    o[(size_t)i*DD + t] = __float2bfloat16(src[t]);
}
struct P11 { const float* p[11]; };
__global__ __launch_bounds__(256)
void cvtT11(P11 s, __nv_bfloat16* __restrict__ o){
    int w = blockIdx.y, n = blockIdx.x, k = threadIdx.x;
    o[(size_t)w*DD*DD + (size_t)n*DD + k] = __float2bfloat16(s.p[w][(size_t)k*DD + n]);
}
// warp-per-row LayerNorm (8 rows/block)
__global__ __launch_bounds__(256)
void ln_fast(const float* __restrict__ X, float* __restrict__ outF,
             __nv_bfloat16* __restrict__ outB, int relu){
    int wid = threadIdx.x >> 5, lane = threadIdx.x & 31;
    int i = blockIdx.x*8 + wid;
    const float* xp = X + (size_t)i*DD + lane*8;
    float4 a = *(const float4*)xp;
    float4 b = *(const float4*)(xp + 4);
    float s  = a.x+a.y+a.z+a.w + b.x+b.y+b.z+b.w;
    float ss = a.x*a.x+a.y*a.y+a.z*a.z+a.w*a.w + b.x*b.x+b.y*b.y+b.z*b.z+b.w*b.w;
    s = wsum(s); ss = wsum(ss);
    float m = s*(1.f/DD);
    float k = rsqrtf(ss*(1.f/DD) - m*m + 1e-5f);
    float v[8] = {a.x,a.y,a.z,a.w,b.x,b.y,b.z,b.w};
    __nv_bfloat162 ob[4];
    #pragma unroll
    for (int q = 0; q < 4; q++){
        float o0 = (v[2*q]   - m)*k;
        float o1 = (v[2*q+1] - m)*k;
        if (relu){ o0 = fmaxf(o0, 0.f); o1 = fmaxf(o1, 0.f); }
        if (outF) *(float2*)(outF + (size_t)i*DD + lane*8 + 2*q) = make_float2(o0, o1);
        ob[q] = __floats2bfloat162_rn(o0, o1);
    }
    *(uint4*)(outB + (size_t)i*DD + lane*8) = *(uint4*)ob;
}
__global__ __launch_bounds__(256)
void fnorm_fast(const float* __restrict__ X, __nv_bfloat16* __restrict__ F){
    int wid = threadIdx.x >> 5, lane = threadIdx.x & 31;
    int i = blockIdx.x*8 + wid;
    const float* xp = X + (size_t)i*DD + lane*8;
    float4 a = *(const float4*)xp;
    float4 b = *(const float4*)(xp + 4);
    float ss = a.x*a.x+a.y*a.y+a.z*a.z+a.w*a.w + b.x*b.x+b.y*b.y+b.z*b.z+b.w*b.w;
    ss = wsum(ss);
    float k = 1.0f / (sqrtf(ss) + 1e-8f);
    float v[8] = {a.x,a.y,a.z,a.w,b.x,b.y,b.z,b.w};
    __nv_bfloat162 ob[4];
    #pragma unroll
    for (int q = 0; q < 4; q++)
        ob[q] = __floats2bfloat162_rn(v[2*q]*k, v[2*q+1]*k);
    *(uint4*)(F + (size_t)i*DD + lane*8) = *(uint4*)ob;
}
__global__ void finalize_stats(const double* acc, float* st){
    if (threadIdx.x == 0 && blockIdx.x == 0){
        double n = (double)NELEM;
        double mu = acc[0] / n;
        double var = acc[1] / n - mu*mu;
        st[0] = (float)mu;
        st[1] = (float)(1.0 / (sqrt(var) + 1e-5));
    }
}
// E = exp((S0-mu)*inv) as bf16, plus transpose. 64x64 tiles.
__global__ __launch_bounds__(256)
void expT_kernel(const float* __restrict__ S0, const float* __restrict__ st,
                 __nv_bfloat16* __restrict__ E, __nv_bfloat16* __restrict__ ET){
    __shared__ float sm[64][68];
    float inv = st[1], muinv = st[0]*st[1];
    int tid = threadIdx.x;
    int r0 = blockIdx.y*64, c0 = blockIdx.x*64;
    #pragma unroll
    for (int i = 0; i < 4; i++){
        int lin = i*256 + tid;
        int r = lin >> 4, c4 = (lin & 15) << 2;
        float4 v = *(const float4*)(S0 + (size_t)(r0+r)*NS + c0 + c4);
        sm[r][c4+0] = fexp(fmaf(v.x, inv, -muinv));
        sm[r][c4+1] = fexp(fmaf(v.y, inv, -muinv));
        sm[r][c4+2] = fexp(fmaf(v.z, inv, -muinv));
        sm[r][c4+3] = fexp(fmaf(v.w, inv, -muinv));
    }
    __syncthreads();
    #pragma unroll
    for (int i = 0; i < 2; i++){
        int lin = i*256 + tid;
        int r = lin >> 3, g8 = (lin & 7) << 3;
        __nv_bfloat162 ob[4];
        #pragma unroll
        for (int q = 0; q < 4; q++)
            ob[q] = __floats2bfloat162_rn(sm[r][g8+2*q], sm[r][g8+2*q+1]);
        *(uint4*)(E + (size_t)(r0+r)*NS + c0 + g8) = *(uint4*)ob;
        #pragma unroll
        for (int q = 0; q < 4; q++)
            ob[q] = __floats2bfloat162_rn(sm[g8+2*q][r], sm[g8+2*q+1][r]);
        *(uint4*)(ET + (size_t)(c0+r)*NS + r0 + g8) = *(uint4*)ob;
    }
}
__global__ void init_ones(float* p, int n){
    int i = blockIdx.x*256 + threadIdx.x;
    if (i < n) p[i] = 1.0f;
}
// out[i] = 1 / sum_j E[i][j]*in[j]   (factorized Sinkhorn half-step)
__global__ __launch_bounds__(256)
void sink_pass(const __nv_bfloat16* __restrict__ E, const float* __restrict__ in,
               float* __restrict__ out){
    __shared__ float red[256];
    int i = blockIdx.x, t = threadIdx.x;
    int j = t*8;
    uint4 u = *(const uint4*)(E + (size_t)i*NS + j);
    float4 c0 = *(const float4*)(in + j);
    float4 c1 = *(const float4*)(in + j + 4);
    float2 e0 = __bfloat1622float2(*(__nv_bfloat162*)&u.x);
    float2 e1 = __bfloat1622float2(*(__nv_bfloat162*)&u.y);
    float2 e2 = __bfloat1622float2(*(__nv_bfloat162*)&u.z);
    float2 e3 = __bfloat1622float2(*(__nv_bfloat162*)&u.w);
    float s = e0.x*c0.x + e0.y*c0.y + e1.x*c0.z + e1.y*c0.w
            + e2.x*c1.x + e2.y*c1.y + e3.x*c1.z + e3.y*c1.w;
    s = bsum256(s, red);
    if (t == 0) out[i] = 1.0f / s;
}
// match loss: sum |E_ij * er_i * ec_j - gt|
__global__ __launch_bounds__(256)
void match2(const __nv_bfloat16* __restrict__ E, const float* __restrict__ er,
            const float* __restrict__ ec, const int* __restrict__ lab, double* acc){
    __shared__ float red[256];
    int i = blockIdx.x, t = threadIdx.x;
    float eri = er[i];
    int li = lab[i];
    int j = t*8;
    uint4 u = *(const uint4*)(E + (size_t)i*NS + j);
    float2 e0 = __bfloat1622float2(*(__nv_bfloat162*)&u.x);
    float2 e1 = __bfloat1622float2(*(__nv_bfloat162*)&u.y);
    float2 e2 = __bfloat1622float2(*(__nv_bfloat162*)&u.z);
    float2 e3 = __bfloat1622float2(*(__nv_bfloat162*)&u.w);
    float ev[8] = {e0.x,e0.y,e1.x,e1.y,e2.x,e2.y,e3.x,e3.y};
    float s = 0.f;
    #pragma unroll
    for (int q = 0; q < 8; q++){
        float p = ev[q] * eri * ec[j+q];
        float gt = (li == lab[NS + j + q]) ? 1.f : 0.f;
        s += fabsf(p - gt);
    }
    s = bsum256(s, red);
    if (t == 0) atomicAdd(acc + 2, (double)s);
}
__global__ void hist_kernel(const int* __restrict__ lab, int* h){
    int i = blockIdx.x*blockDim.x + threadIdx.x;
    if (i < NF) atomicAdd(&h[lab[i]], 1);
}
__global__ __launch_bounds__(256)
void supcon_final(const float* __restrict__ es, const float* __restrict__ ps,
                  const int* __restrict__ lab, const int* __restrict__ h, double* acc){
    __shared__ float red[256];
    int i = blockIdx.x*256 + threadIdx.x;
    float cnt = (float)(h[lab[i]] - 1);
    float v = ps[i]/cnt - logf(es[i]);
    float s = bsum256(v, red);
    if (threadIdx.x == 0) atomicAdd(acc + 3, (double)s);
}
__global__ void finalize_kernel(const double* acc, float* out){
    if (threadIdx.x == 0 && blockIdx.x == 0)
        out[0] = (float)(acc[2] + 0.1 * (-(acc[3] / (double)NF)));
}

// ---------------- host ----------------
extern "C" void kernel_launch(void* const* d_in, const int* in_sizes, int n_in,
                              void* d_out, int out_size){
    const float *nodes_src=(const float*)d_in[0], *nodes_tgt=(const float*)d_in[1];
    const int *labels_src=(const int*)d_in[2], *labels_tgt=(const int*)d_in[3];
    const float *w1=(const float*)d_in[4], *b1=(const float*)d_in[5];
    const float *w2=(const float*)d_in[6], *b2=(const float*)d_in[7];
    const float *wq=(const float*)d_in[8], *wk=(const float*)d_in[9];
    const float *wv=(const float*)d_in[10], *wo=(const float*)d_in[11];
    const float *cq=(const float*)d_in[12], *ck=(const float*)d_in[13];
    const float *cv=(const float*)d_in[14], *co=(const float*)d_in[15];
    const float *Am=(const float*)d_in[16];

    __nv_bfloat16 *inb,*h1b,*x0b,*x1b,*x2b,*qb,*kb,*vb,*vwT,*fnb,*Pb,*wT;
    float *tf,*x0,*x1,*x2,*S0,*rsum,*rv,*cvv,*esum,*psum,*stats;
    double* dacc; int *lab,*hist;
    cudaGetSymbolAddress((void**)&inb,g_inb); cudaGetSymbolAddress((void**)&h1b,g_h1b);
    cudaGetSymbolAddress((void**)&x0b,g_x0b); cudaGetSymbolAddress((void**)&x1b,g_x1b);
    cudaGetSymbolAddress((void**)&x2b,g_x2b); cudaGetSymbolAddress((void**)&qb,g_qb);
    cudaGetSymbolAddress((void**)&kb,g_kb);   cudaGetSymbolAddress((void**)&vb,g_vb);
    cudaGetSymbolAddress((void**)&vwT,g_vwT); cudaGetSymbolAddress((void**)&fnb,g_fnb);
    cudaGetSymbolAddress((void**)&Pb,g_Pb);   cudaGetSymbolAddress((void**)&wT,g_wT);
    cudaGetSymbolAddress((void**)&tf,g_tf);   cudaGetSymbolAddress((void**)&x0,g_x0);
    cudaGetSymbolAddress((void**)&x1,g_x1);   cudaGetSymbolAddress((void**)&x2,g_x2);
    cudaGetSymbolAddress((void**)&S0,g_S0);   cudaGetSymbolAddress((void**)&rsum,g_rsum);
    cudaGetSymbolAddress((void**)&rv,g_r);    cudaGetSymbolAddress((void**)&cvv,g_c);
    cudaGetSymbolAddress((void**)&esum,g_esum); cudaGetSymbolAddress((void**)&psum,g_psum);
    cudaGetSymbolAddress((void**)&stats,g_stats); cudaGetSymbolAddress((void**)&dacc,g_dacc);
    cudaGetSymbolAddress((void**)&lab,g_lab); cudaGetSymbolAddress((void**)&hist,g_hist);

    const int WSZ = DD*DD;
    __nv_bfloat16 *w1T=wT, *w2T=wT+WSZ, *wqT=wT+2*WSZ, *wkT=wT+3*WSZ, *wvT=wT+4*WSZ,
                  *woT=wT+5*WSZ, *cqT=wT+6*WSZ, *ckT=wT+7*WSZ, *cvT=wT+8*WSZ,
                  *coT=wT+9*WSZ, *AT=wT+10*WSZ;
    __nv_bfloat16 *Eb = Pb, *EbT = Pb + NELEM;

    cudaMemsetAsync(dacc, 0, 4*sizeof(double));
    cudaMemsetAsync(hist, 0, 16*sizeof(int));
    cudaMemsetAsync(esum, 0, NF*sizeof(float));
    cudaMemsetAsync(psum, 0, NF*sizeof(float));
    cudaMemcpyAsync(lab, labels_src, NS*sizeof(int), cudaMemcpyDeviceToDevice);
    cudaMemcpyAsync(lab+NS, labels_tgt, NS*sizeof(int), cudaMemcpyDeviceToDevice);

    cvt_in<<<NF, 256>>>(nodes_src, nodes_tgt, inb);
    P11 s11; s11.p[0]=w1; s11.p[1]=w2; s11.p[2]=wq; s11.p[3]=wk; s11.p[4]=wv;
    s11.p[5]=wo; s11.p[6]=cq; s11.p[7]=ck; s11.p[8]=cv; s11.p[9]=co; s11.p[10]=Am;
    cvtT11<<<dim3(DD, 11), 256>>>(s11, wT);

    auto TC = [&](dim3 g, const __nv_bfloat16* A, int lda, long long azs,
                  const __nv_bfloat16* B, int ldb, long long bzs,
                  int K, int epi, float sc, float* oF, __nv_bfloat16* oB,
                  int ldc, long long czs, int mzoff,
                  const float* bias_, const float* rs, float* rsW, const float* res){
        tc_nt<<<g, 256>>>(A, lda, azs, B, ldb, bzs, K, epi, sc, oF, oB, ldc, czs, mzoff,
                          bias_, rs, rsW, res, dacc, lab, esum, psum);
    };

    // head_in
    TC(dim3(2,32,1), inb,256,0, w1T,256,0, 256, 1, 1.f, tf, nullptr, 256,0,0, b1, nullptr,nullptr,nullptr);
    ln_fast<<<NF/8,256>>>(tf, nullptr, h1b, 1);
    TC(dim3(2,32,1), h1b,256,0, w2T,256,0, 256, 1, 1.f, tf, nullptr, 256,0,0, b2, nullptr,nullptr,nullptr);
    ln_fast<<<NF/8,256>>>(tf, x0, x0b, 0);

    // intra attention
    TC(dim3(2,32,1), x0b,256,0, wqT,256,0, 256, 0, 0.0625f, nullptr, qb, 256,0,0, nullptr,nullptr,nullptr,nullptr);
    TC(dim3(2,32,1), x0b,256,0, wkT,256,0, 256, 0, 1.f, nullptr, kb, 256,0,0, nullptr,nullptr,nullptr,nullptr);
    TC(dim3(2,32,1), x0b,256,0, wvT,256,0, 256, 0, 1.f, nullptr, vb, 256,0,0, nullptr,nullptr,nullptr,nullptr);
    TC(dim3(2,32,1), vb,256,0, woT,256,0, 256, 2, 1.f, nullptr, vwT, NF,0,0, nullptr,nullptr,nullptr,nullptr);
    cudaMemsetAsync(rsum, 0, NF*sizeof(float));
    TC(dim3(16,16,2), qb,256,HALF, kb,256,HALF, 256, 3, 1.f, nullptr, Pb, NS, NELEM, NS, nullptr,nullptr,rsum,nullptr);
    TC(dim3(2,16,2), Pb,NS,NELEM, vwT,NF,2048, NS, 4, 1.f, x1, x1b, 256,0, NS, nullptr,rsum,nullptr,x0);

    // cross attention
    TC(dim3(2,32,1), x1b,256,0, cqT,256,0, 256, 0, 0.0625f, nullptr, qb, 256,0,0, nullptr,nullptr,nullptr,nullptr);
    TC(dim3(2,32,1), x1b,256,0, ckT,256,0, 256, 0, 1.f, nullptr, kb, 256,0,0, nullptr,nullptr,nullptr,nullptr);
    TC(dim3(2,32,1), x1b,256,0, cvT,256,0, 256, 0, 1.f, nullptr, vb, 256,0,0, nullptr,nullptr,nullptr,nullptr);
    TC(dim3(2,32,1), vb,256,0, coT,256,0, 256, 2, 1.f, nullptr, vwT, NF,0,0, nullptr,nullptr,nullptr,nullptr);
    cudaMemsetAsync(rsum, 0, NF*sizeof(float));
    TC(dim3(16,16,2), qb,256,HALF, kb+HALF,256,-HALF, 256, 3, 1.f, nullptr, Pb, NS, NELEM, NS, nullptr,nullptr,rsum,nullptr);
    TC(dim3(2,16,2), Pb,NS,NELEM, vwT+2048,NF,-2048, NS, 4, 1.f, x2, x2b, 256,0, NS, nullptr,rsum,nullptr,x1);

    // affinity + stats
    TC(dim3(2,16,1), x2b,256,0, AT,256,0, 256, 0, 1.f, nullptr, qb, 256,0,0, nullptr,nullptr,nullptr,nullptr);
    TC(dim3(16,16,1), qb,256,0, x2b+HALF,256,0, 256, 5, 1.f, S0, nullptr, NS,0,0, nullptr,nullptr,nullptr,nullptr);
    finalize_stats<<<1,32>>>(dacc, stats);

    // E = exp((M-mu)/sigma), plus transpose (both bf16, L2-resident)
    expT_kernel<<<dim3(32,32),256>>>(S0, stats, Eb, EbT);

    // Sinkhorn: pure dot-product + reciprocal half-steps
    init_ones<<<NS/256,256>>>(cvv, NS);
    for (int it = 0; it < 10; it++){
        sink_pass<<<NS,256>>>(Eb, cvv, rv);
        sink_pass<<<NS,256>>>(EbT, rv, cvv);
    }
    match2<<<NS,256>>>(Eb, rv, cvv, lab, dacc);

    // SupCon
    fnorm_fast<<<NF/8,256>>>(x2, fnb);
    hist_kernel<<<16,256>>>(lab, hist);
    TC(dim3(32,32,1), fnb,256,0, fnb,256,0, 256, 6, SUPCON_SCALE, nullptr, nullptr, 0,0,0, nullptr,nullptr,nullptr,nullptr);
    supcon_final<<<NF/256,256>>>(esum, psum, lab, hist, dacc);

    finalize_kernel<<<1,32>>>(dacc, (float*)d_out);
}

// round 7
// speedup vs baseline: 4.7910x; 1.2451x over previous
#include <cuda_runtime.h>
#include <cuda_bf16.h>
#include <math.h>
#include <stdint.h>

#define NS 2048
#define DD 256
#define NF 4096
#define HALF ((long long)NS*DD)
#define LL3  ((long long)NS*768)
#define NELEM ((long long)NS*NS)
#define NFDD ((long long)NF*DD)
#define SUPCON_SCALE 14.285714285714286f

// ---------------- helpers ----------------
__device__ __forceinline__ uint32_t smem_to_u32(const void* p){
    uint32_t a;
    asm("{ .reg .u64 t; cvta.to.shared.u64 t, %1; cvt.u32.u64 %0, t; }" : "=r"(a) : "l"(p));
    return a;
}
__device__ __forceinline__ void ldsm_x4(uint32_t* r, uint32_t addr){
    asm volatile("ldmatrix.sync.aligned.m8n8.x4.shared.b16 {%0,%1,%2,%3}, [%4];"
        : "=r"(r[0]), "=r"(r[1]), "=r"(r[2]), "=r"(r[3]) : "r"(addr));
}
__device__ __forceinline__ void ldsm_x2(uint32_t* r, uint32_t addr){
    asm volatile("ldmatrix.sync.aligned.m8n8.x2.shared.b16 {%0,%1}, [%2];"
        : "=r"(r[0]), "=r"(r[1]) : "r"(addr));
}
__device__ __forceinline__ void ldsm_x2t(uint32_t* r, uint32_t addr){
    asm volatile("ldmatrix.sync.aligned.m8n8.x2.trans.shared.b16 {%0,%1}, [%2];"
        : "=r"(r[0]), "=r"(r[1]) : "r"(addr));
}
__device__ __forceinline__ void mma16816(float* c, const uint32_t* a, const uint32_t* b){
    asm volatile("mma.sync.aligned.m16n8k16.row.col.f32.bf16.bf16.f32 "
        "{%0,%1,%2,%3}, {%4,%5,%6,%7}, {%8,%9}, {%0,%1,%2,%3};"
        : "+f"(c[0]), "+f"(c[1]), "+f"(c[2]), "+f"(c[3])
        : "r"(a[0]), "r"(a[1]), "r"(a[2]), "r"(a[3]), "r"(b[0]), "r"(b[1]));
}
__device__ __forceinline__ float fexp(float x){
    float t = x * 1.4426950408889634f;
    float r = rintf(t);
    float f = t - r;
    float p =            1.3333558146e-3f;
    p = fmaf(p, f, 9.6181291076e-3f);
    p = fmaf(p, f, 5.5504108664e-2f);
    p = fmaf(p, f, 2.4022650696e-1f);
    p = fmaf(p, f, 6.9314718056e-1f);
    p = fmaf(p, f, 1.0f);
    float res = __int_as_float(__float_as_int(p) + (((int)r) << 23));
    return (x < -87.0f) ? 0.0f : res;
}
__device__ __forceinline__ float bsum256(float v, float* red){
    int tid = threadIdx.x;
    red[tid] = v; __syncthreads();
    #pragma unroll
    for (int o = 128; o > 0; o >>= 1){
        if (tid < o) red[tid] += red[tid + o];
        __syncthreads();
    }
    float r = red[0]; __syncthreads();
    return r;
}
__device__ __forceinline__ float wsum(float v){
    #pragma unroll
    for (int o = 16; o > 0; o >>= 1) v += __shfl_xor_sync(0xffffffffu, v, o);
    return v;
}

// ---------------- scratch ----------------
__device__ __nv_bfloat16 g_inb[NF*DD], g_h1b[NF*DD], g_x0b[NF*DD], g_x1b[NF*DD], g_x2b[NF*DD];
__device__ __nv_bfloat16 g_qb[NF*DD], g_fnb[NF*DD];
__device__ __nv_bfloat16 g_qkv[(long long)NF*768];
__device__ __nv_bfloat16 g_Pb[2*NELEM];
__device__ __nv_bfloat16 g_wT[13*DD*DD];
__device__ float g_tf[NF*DD], g_x0[NF*DD], g_x1[NF*DD], g_x2[NF*DD];
__device__ float g_S0[NELEM];
__device__ float g_rsum[NF], g_r[NS], g_c[NS], g_esum[NF], g_psum[NF], g_stats[2];
__device__ double g_dacc[4];
__device__ int g_lab[NF], g_hist[16];
__device__ int g_cnt;
__device__ volatile int g_epoch;

// ============================================================================
// Generic bf16 HMMA NT/NN GEMM, 128x128 tile, 8 warps (2x4), 64x32 warp tiles.
// epi: 0 bf16 (scale applied when cc<scaleN) | 1 f32+bias | 3 exp+rowsum+bf16
//      4 split-K f32 slice store into outF[kk*NFDD + ...] | 5 f32+stats | 6 supcon
// ============================================================================
__global__ __launch_bounds__(256)
void tc_nt(const __nv_bfloat16* A, int lda, long long azs,
           const __nv_bfloat16* B, int ldb, long long bzs, int transB,
           int K, int ksl, int epi, float scale, int scaleN,
           float* outF, __nv_bfloat16* outB, int ldc, long long czs, int mzoff,
           const float* bias, float* rsumW, double* dacc,
           const int* lab, float* esum, float* psum)
{
    __shared__ __nv_bfloat16 SA[128*72];
    __shared__ __nv_bfloat16 SB[128*72];
    __shared__ float red[256];

    int z = blockIdx.z;
    int dom = z / ksl, kk = z - dom*ksl;
    A += (long long)dom * azs;
    B += (long long)dom * bzs;
    if (outB) outB += (long long)dom * czs;

    int tid = threadIdx.x, wid = tid >> 5, lane = tid & 31;
    int wr = wid >> 2, wc = wid & 3;
    int row0 = blockIdx.y * 128, col0 = blockIdx.x * 128;

    uint32_t sA = smem_to_u32(SA), sB = smem_to_u32(SB);

    float acc[4][4][4];
    #pragma unroll
    for (int mi = 0; mi < 4; mi++)
        #pragma unroll
        for (int ni = 0; ni < 4; ni++)
            #pragma unroll
            for (int q = 0; q < 4; q++) acc[mi][ni][q] = 0.f;

    int aRow  = wr*64 + (lane & 7) + ((lane >> 3) & 1)*8;
    int aKoff = (lane >> 4)*8;
    int l16   = lane & 15;
    int bRow  = wc*32 + (l16 & 7);
    int bKoff = (l16 >> 3)*8;

    int nch = K >> 6;
    int c0ch = kk * nch / ksl, c1ch = (kk+1) * nch / ksl;
    for (int c = c0ch; c < c1ch; c++){
        int kc = c << 6;
        __syncthreads();
        #pragma unroll
        for (int i = 0; i < 4; i++){
            int lin = i*256 + tid;
            int r = lin >> 3, c8 = (lin & 7) << 3;
            *(uint4*)&SA[r*72 + c8] = *(const uint4*)(A + (size_t)(row0+r)*lda + kc + c8);
        }
        if (!transB){
            #pragma unroll
            for (int i = 0; i < 4; i++){
                int lin = i*256 + tid;
                int r = lin >> 3, c8 = (lin & 7) << 3;
                *(uint4*)&SB[r*72 + c8] = *(const uint4*)(B + (size_t)(col0+r)*ldb + kc + c8);
            }
        } else {
            #pragma unroll
            for (int i = 0; i < 4; i++){
                int lin = i*256 + tid;
                int r = lin >> 4, c8 = (lin & 15) << 3;   // r: 0..63 k-rows, c8: 0..120 n
                *(uint4*)&SB[r*136 + c8] = *(const uint4*)(B + (size_t)(kc+r)*ldb + col0 + c8);
            }
        }
        __syncthreads();
        #pragma unroll
        for (int ks = 0; ks < 4; ks++){
            uint32_t af[4][4], bf[4][2];
            #pragma unroll
            for (int mi = 0; mi < 4; mi++)
                ldsm_x4(af[mi], sA + (uint32_t)(((aRow + mi*16)*72 + ks*16 + aKoff) * 2));
            if (!transB){
                #pragma unroll
                for (int ni = 0; ni < 4; ni++)
                    ldsm_x2(bf[ni], sB + (uint32_t)(((bRow + ni*8)*72 + ks*16 + bKoff) * 2));
            } else {
                #pragma unroll
                for (int ni = 0; ni < 4; ni++)
                    ldsm_x2t(bf[ni], sB + (uint32_t)(((ks*16 + l16)*136 + wc*32 + ni*8) * 2));
            }
            #pragma unroll
            for (int mi = 0; mi < 4; mi++)
                #pragma unroll
                for (int ni = 0; ni < 4; ni++)
                    mma16816(acc[mi][ni], af[mi], bf[ni]);
        }
    }

    int lr = lane >> 2, lc2 = (lane & 3) << 1;
    int colB = col0 + wc*32;
    float s1 = 0.f, s2 = 0.f;

    #pragma unroll
    for (int mi = 0; mi < 4; mi++){
        #pragma unroll
        for (int h = 0; h < 2; h++){
            int r = row0 + wr*64 + mi*16 + lr + h*8;
            if (epi == 0){
                #pragma unroll
                for (int ni = 0; ni < 4; ni++){
                    int cc = colB + ni*8 + lc2;
                    float m0 = (cc   < scaleN) ? scale : 1.0f;
                    float m1 = (cc+1 < scaleN) ? scale : 1.0f;
                    float v0 = acc[mi][ni][h*2+0]*m0, v1 = acc[mi][ni][h*2+1]*m1;
                    *(__nv_bfloat162*)(outB + (size_t)r*ldc + cc) = __floats2bfloat162_rn(v0, v1);
                }
            } else if (epi == 1){
                #pragma unroll
                for (int ni = 0; ni < 4; ni++){
                    int cc = colB + ni*8 + lc2;
                    float2 o = make_float2(acc[mi][ni][h*2+0] + bias[cc],
                                           acc[mi][ni][h*2+1] + bias[cc+1]);
                    *(float2*)(outF + (size_t)r*ldc + cc) = o;
                }
            } else if (epi == 3){
                float part = 0.f;
                #pragma unroll
                for (int ni = 0; ni < 4; ni++){
                    int cc = colB + ni*8 + lc2;
                    float e0 = fexp(acc[mi][ni][h*2+0]), e1 = fexp(acc[mi][ni][h*2+1]);
                    part += e0 + e1;
                    *(__nv_bfloat162*)(outB + (size_t)r*ldc + cc) = __floats2bfloat162_rn(e0, e1);
                }
                part += __shfl_xor_sync(0xffffffffu, part, 1);
                part += __shfl_xor_sync(0xffffffffu, part, 2);
                if ((lane & 3) == 0) atomicAdd(&rsumW[dom*mzoff + r], part);
            } else if (epi == 4){
                int mg = dom*mzoff + r;
                #pragma unroll
                for (int ni = 0; ni < 4; ni++){
                    int cc = colB + ni*8 + lc2;
                    *(float2*)(outF + (long long)kk*NFDD + (size_t)mg*ldc + cc) =
                        make_float2(acc[mi][ni][h*2+0], acc[mi][ni][h*2+1]);
                }
            } else if (epi == 5){
                #pragma unroll
                for (int ni = 0; ni < 4; ni++){
                    int cc = colB + ni*8 + lc2;
                    float v0 = acc[mi][ni][h*2+0], v1 = acc[mi][ni][h*2+1];
                    *(float2*)(outF + (size_t)r*ldc + cc) = make_float2(v0, v1);
                    s1 += v0 + v1; s2 += v0*v0 + v1*v1;
                }
            } else {
                int rlab = lab[r];
                float pe = 0.f, ps = 0.f;
                #pragma unroll
                for (int ni = 0; ni < 4; ni++){
                    int cc = colB + ni*8 + lc2;
                    float l0 = acc[mi][ni][h*2+0]*scale, l1 = acc[mi][ni][h*2+1]*scale;
                    if (cc != r){ pe += fexp(l0); if (lab[cc] == rlab) ps += l0; }
                    if (cc+1 != r){ pe += fexp(l1); if (lab[cc+1] == rlab) ps += l1; }
                }
                pe += __shfl_xor_sync(0xffffffffu, pe, 1);
                pe += __shfl_xor_sync(0xffffffffu, pe, 2);
                ps += __shfl_xor_sync(0xffffffffu, ps, 1);
                ps += __shfl_xor_sync(0xffffffffu, ps, 2);
                if ((lane & 3) == 0){
                    atomicAdd(&esum[r], pe);
                    atomicAdd(&psum[r], ps);
                }
            }
        }
    }
    if (epi == 5){
        float bs = bsum256(s1, red), bss = bsum256(s2, red);
        if (tid == 0){ atomicAdd(dacc, (double)bs); atomicAdd(dacc+1, (double)bss); }
    }
}

// ---------------- small kernels ----------------
__global__ __launch_bounds__(256)
void cvt_in(const float* __restrict__ a, const float* __restrict__ b, __nv_bfloat16* __restrict__ o){
    int i = blockIdx.x, t = threadIdx.x;
    const float* src = (i < NS) ? a + (size_t)i*DD : b + (size_t)(i-NS)*DD;
    o[(size_t)i*DD + t] = __float2bfloat16(src[t]);
}
struct P13 { const float* p[13]; int tr[13]; };
__global__ __launch_bounds__(256)
void cvtT13(P13 s, __nv_bfloat16* __restrict__ o){
    int w = blockIdx.y, n = blockIdx.x, k = threadIdx.x;
    const float* src = s.p[w];
    if (!src) return;
    float v = s.tr[w] ? src[(size_t)k*DD + n] : src[(size_t)n*DD + k];
    o[(size_t)w*DD*DD + (size_t)n*DD + k] = __float2bfloat16(v);
}
__global__ __launch_bounds__(256)
void ln_fast(const float* __restrict__ X, float* __restrict__ outF,
             __nv_bfloat16* __restrict__ outB, int relu){
    int wid = threadIdx.x >> 5, lane = threadIdx.x & 31;
    int i = blockIdx.x*8 + wid;
    const float* xp = X + (size_t)i*DD + lane*8;
    float4 a = *(const float4*)xp;
    float4 b = *(const float4*)(xp + 4);
    float s  = a.x+a.y+a.z+a.w + b.x+b.y+b.z+b.w;
    float ss = a.x*a.x+a.y*a.y+a.z*a.z+a.w*a.w + b.x*b.x+b.y*b.y+b.z*b.z+b.w*b.w;
    s = wsum(s); ss = wsum(ss);
    float m = s*(1.f/DD);
    float k = rsqrtf(ss*(1.f/DD) - m*m + 1e-5f);
    float v[8] = {a.x,a.y,a.z,a.w,b.x,b.y,b.z,b.w};
    __nv_bfloat162 ob[4];
    #pragma unroll
    for (int q = 0; q < 4; q++){
        float o0 = (v[2*q]   - m)*k;
        float o1 = (v[2*q+1] - m)*k;
        if (relu){ o0 = fmaxf(o0, 0.f); o1 = fmaxf(o1, 0.f); }
        if (outF) *(float2*)(outF + (size_t)i*DD + lane*8 + 2*q) = make_float2(o0, o1);
        ob[q] = __floats2bfloat162_rn(o0, o1);
    }
    *(uint4*)(outB + (size_t)i*DD + lane*8) = *(uint4*)ob;
}
__global__ __launch_bounds__(256)
void fnorm_fast(const float* __restrict__ X, __nv_bfloat16* __restrict__ F){
    int wid = threadIdx.x >> 5, lane = threadIdx.x & 31;
    int i = blockIdx.x*8 + wid;
    const float* xp = X + (size_t)i*DD + lane*8;
    float4 a = *(const float4*)xp;
    float4 b = *(const float4*)(xp + 4);
    float ss = a.x*a.x+a.y*a.y+a.z*a.z+a.w*a.w + b.x*b.x+b.y*b.y+b.z*b.z+b.w*b.w;
    ss = wsum(ss);
    float k = 1.0f / (sqrtf(ss) + 1e-8f);
    float v[8] = {a.x,a.y,a.z,a.w,b.x,b.y,b.z,b.w};
    __nv_bfloat162 ob[4];
    #pragma unroll
    for (int q = 0; q < 4; q++)
        ob[q] = __floats2bfloat162_rn(v[2*q]*k, v[2*q+1]*k);
    *(uint4*)(F + (size_t)i*DD + lane*8) = *(uint4*)ob;
}
// PV finalize: x = (sum of 4 K-slices)/rsum + res  → f32 + bf16
__global__ __launch_bounds__(256)
void pv_fin(const float* __restrict__ acc4, const float* __restrict__ rsum,
            const float* __restrict__ res, float* __restrict__ outF,
            __nv_bfloat16* __restrict__ outB){
    int wid = threadIdx.x >> 5, lane = threadIdx.x & 31;
    int i = blockIdx.x*8 + wid;
    float rinv = 1.0f / rsum[i];
    size_t off = (size_t)i*DD + lane*8;
    float v[8];
    #pragma unroll
    for (int q = 0; q < 8; q++) v[q] = 0.f;
    #pragma unroll
    for (int sl = 0; sl < 4; sl++){
        const float* p = acc4 + (long long)sl*NFDD + off;
        float4 a = *(const float4*)p;
        float4 b = *(const float4*)(p + 4);
        v[0]+=a.x; v[1]+=a.y; v[2]+=a.z; v[3]+=a.w;
        v[4]+=b.x; v[5]+=b.y; v[6]+=b.z; v[7]+=b.w;
    }
    const float* rp = res + off;
    float4 ra = *(const float4*)rp;
    float4 rb = *(const float4*)(rp + 4);
    float rr[8] = {ra.x,ra.y,ra.z,ra.w,rb.x,rb.y,rb.z,rb.w};
    __nv_bfloat162 ob[4];
    #pragma unroll
    for (int q = 0; q < 4; q++){
        float o0 = fmaf(v[2*q],   rinv, rr[2*q]);
        float o1 = fmaf(v[2*q+1], rinv, rr[2*q+1]);
        *(float2*)(outF + off + 2*q) = make_float2(o0, o1);
        ob[q] = __floats2bfloat162_rn(o0, o1);
    }
    *(uint4*)(outB + off) = *(uint4*)ob;
}
__global__ void finalize_stats(const double* acc, float* st){
    if (threadIdx.x == 0 && blockIdx.x == 0){
        double n = (double)NELEM;
        double mu = acc[0] / n;
        double var = acc[1] / n - mu*mu;
        st[0] = (float)mu;
        st[1] = (float)(1.0 / (sqrt(var) + 1e-5));
    }
}
__global__ __launch_bounds__(256)
void expT_kernel(const float* __restrict__ S0, const float* __restrict__ st,
                 __nv_bfloat16* __restrict__ E, __nv_bfloat16* __restrict__ ET){
    __shared__ float sm[64][68];
    float inv = st[1], muinv = st[0]*st[1];
    int tid = threadIdx.x;
    int r0 = blockIdx.y*64, c0 = blockIdx.x*64;
    #pragma unroll
    for (int i = 0; i < 4; i++){
        int lin = i*256 + tid;
        int r = lin >> 4, c4 = (lin & 15) << 2;
        float4 v = *(const float4*)(S0 + (size_t)(r0+r)*NS + c0 + c4);
        sm[r][c4+0] = fexp(fmaf(v.x, inv, -muinv));
        sm[r][c4+1] = fexp(fmaf(v.y, inv, -muinv));
        sm[r][c4+2] = fexp(fmaf(v.z, inv, -muinv));
        sm[r][c4+3] = fexp(fmaf(v.w, inv, -muinv));
    }
    __syncthreads();
    #pragma unroll
    for (int i = 0; i < 2; i++){
        int lin = i*256 + tid;
        int r = lin >> 3, g8 = (lin & 7) << 3;
        __nv_bfloat162 ob[4];
        #pragma unroll
        for (int q = 0; q < 4; q++)
            ob[q] = __floats2bfloat162_rn(sm[r][g8+2*q], sm[r][g8+2*q+1]);
        *(uint4*)(E + (size_t)(r0+r)*NS + c0 + g8) = *(uint4*)ob;
        #pragma unroll
        for (int q = 0; q < 4; q++)
            ob[q] = __floats2bfloat162_rn(sm[g8+2*q][r], sm[g8+2*q+1][r]);
        *(uint4*)(ET + (size_t)(c0+r)*NS + r0 + g8) = *(uint4*)ob;
    }
}
// Persistent Sinkhorn: 20 half-steps + match loss, one launch, 256 blocks.
__global__ __launch_bounds__(256)
void sinkhorn_all(const __nv_bfloat16* __restrict__ E, const __nv_bfloat16* __restrict__ ET,
                  float* __restrict__ rv, float* __restrict__ cvv,
                  const int* __restrict__ lab, double* acc){
    int tid = threadIdx.x, wid = tid >> 5, lane = tid & 31;
    int row = blockIdx.x*8 + wid;
    int nb = gridDim.x;
    for (int pass = 0; pass < 20; pass++){
        const __nv_bfloat16* M = (pass & 1) ? ET : E;
        const float* in = (pass & 1) ? rv : cvv;
        float* out = (pass & 1) ? cvv : rv;
        float s = 0.f;
        #pragma unroll
        for (int b = 0; b < 8; b++){
            int j = (b*32 + lane)*8;
            uint4 u = *(const uint4*)(M + (size_t)row*NS + j);
            float2 e0 = __bfloat1622float2(*(__nv_bfloat162*)&u.x);
            float2 e1 = __bfloat1622float2(*(__nv_bfloat162*)&u.y);
            float2 e2 = __bfloat1622float2(*(__nv_bfloat162*)&u.z);
            float2 e3 = __bfloat1622float2(*(__nv_bfloat162*)&u.w);
            if (pass == 0){
                s += e0.x+e0.y+e1.x+e1.y+e2.x+e2.y+e3.x+e3.y;
            } else {
                float4 c0 = *(const float4*)(in + j);
                float4 c1 = *(const float4*)(in + j + 4);
                s += e0.x*c0.x + e0.y*c0.y + e1.x*c0.z + e1.y*c0.w
                   + e2.x*c1.x + e2.y*c1.y + e3.x*c1.z + e3.y*c1.w;
            }
        }
        s = wsum(s);
        if (lane == 0) out[row] = 1.0f / s;
        // grid barrier (epoch-based)
        __threadfence();
        __syncthreads();
        if (tid == 0){
            int e = g_epoch;
            if (atomicAdd(&g_cnt, 1) == nb - 1){
                g_cnt = 0;
                __threadfence();
                g_epoch = e + 1;
            } else {
                while (g_epoch == e) { }
            }
            __threadfence();
        }
        __syncthreads();
    }
    // match loss
    float eri = rv[row];
    int li = lab[row];
    float s = 0.f;
    #pragma unroll
    for (int b = 0; b < 8; b++){
        int j = (b*32 + lane)*8;
        uint4 u = *(const uint4*)(E + (size_t)row*NS + j);
        float2 e0 = __bfloat1622float2(*(__nv_bfloat162*)&u.x);
        float2 e1 = __bfloat1622float2(*(__nv_bfloat162*)&u.y);
        float2 e2 = __bfloat1622float2(*(__nv_bfloat162*)&u.z);
        float2 e3 = __bfloat1622float2(*(__nv_bfloat162*)&u.w);
        float ev[8] = {e0.x,e0.y,e1.x,e1.y,e2.x,e2.y,e3.x,e3.y};
        float4 c0 = *(const float4*)(cvv + j);
        float4 c1 = *(const float4*)(cvv + j + 4);
        float cv8[8] = {c0.x,c0.y,c0.z,c0.w,c1.x,c1.y,c1.z,c1.w};
        #pragma unroll
        for (int q = 0; q < 8; q++){
            float p = ev[q] * eri * cv8[q];
            float gt = (li == lab[NS + j + q]) ? 1.f : 0.f;
            s += fabsf(p - gt);
        }
    }
    s = wsum(s);
    if (lane == 0) atomicAdd(acc + 2, (double)s);
}
__global__ void hist_kernel(const int* __restrict__ lab, int* h){
    int i = blockIdx.x*blockDim.x + threadIdx.x;
    if (i < NF) atomicAdd(&h[lab[i]], 1);
}
__global__ __launch_bounds__(256)
void supcon_final(const float* __restrict__ es, const float* __restrict__ ps,
                  const int* __restrict__ lab, const int* __restrict__ h, double* acc){
    __shared__ float red[256];
    int i = blockIdx.x*256 + threadIdx.x;
    float cnt = (float)(h[lab[i]] - 1);
    float v = ps[i]/cnt - logf(es[i]);
    float s = bsum256(v, red);
    if (threadIdx.x == 0) atomicAdd(acc + 3, (double)s);
}
__global__ void finalize_kernel(const double* acc, float* out){
    if (threadIdx.x == 0 && blockIdx.x == 0)
        out[0] = (float)(acc[2] + 0.1 * (-(acc[3] / (double)NF)));
}

// ---------------- host ----------------
extern "C" void kernel_launch(void* const* d_in, const int* in_sizes, int n_in,
                              void* d_out, int out_size){
    const float *nodes_src=(const float*)d_in[0], *nodes_tgt=(const float*)d_in[1];
    const int *labels_src=(const int*)d_in[2], *labels_tgt=(const int*)d_in[3];
    const float *w1=(const float*)d_in[4], *b1=(const float*)d_in[5];
    const float *w2=(const float*)d_in[6], *b2=(const float*)d_in[7];
    const float *wq=(const float*)d_in[8], *wk=(const float*)d_in[9];
    const float *wv=(const float*)d_in[10], *wo=(const float*)d_in[11];
    const float *cq=(const float*)d_in[12], *ck=(const float*)d_in[13];
    const float *cv=(const float*)d_in[14], *co=(const float*)d_in[15];
    const float *Am=(const float*)d_in[16];

    __nv_bfloat16 *inb,*h1b,*x0b,*x1b,*x2b,*qb,*fnb,*qkv,*Pb,*wT;
    float *tf,*x0,*x1,*x2,*S0,*rsum,*rv,*cvv,*esum,*psum,*stats;
    double* dacc; int *lab,*hist;
    cudaGetSymbolAddress((void**)&inb,g_inb); cudaGetSymbolAddress((void**)&h1b,g_h1b);
    cudaGetSymbolAddress((void**)&x0b,g_x0b); cudaGetSymbolAddress((void**)&x1b,g_x1b);
    cudaGetSymbolAddress((void**)&x2b,g_x2b); cudaGetSymbolAddress((void**)&qb,g_qb);
    cudaGetSymbolAddress((void**)&fnb,g_fnb); cudaGetSymbolAddress((void**)&qkv,g_qkv);
    cudaGetSymbolAddress((void**)&Pb,g_Pb);   cudaGetSymbolAddress((void**)&wT,g_wT);
    cudaGetSymbolAddress((void**)&tf,g_tf);   cudaGetSymbolAddress((void**)&x0,g_x0);
    cudaGetSymbolAddress((void**)&x1,g_x1);   cudaGetSymbolAddress((void**)&x2,g_x2);
    cudaGetSymbolAddress((void**)&S0,g_S0);   cudaGetSymbolAddress((void**)&rsum,g_rsum);
    cudaGetSymbolAddress((void**)&rv,g_r);    cudaGetSymbolAddress((void**)&cvv,g_c);
    cudaGetSymbolAddress((void**)&esum,g_esum); cudaGetSymbolAddress((void**)&psum,g_psum);
    cudaGetSymbolAddress((void**)&stats,g_stats); cudaGetSymbolAddress((void**)&dacc,g_dacc);
    cudaGetSymbolAddress((void**)&lab,g_lab); cudaGetSymbolAddress((void**)&hist,g_hist);

    const int WSZ = DD*DD;
    // slots: 0 w1T, 1 w2T, 2 wqT, 3 wkT, 4 WvoT*, 5 cqT, 6 ckT, 7 WcoT*, 8 AT,
    //        9 woT, 10 coT, 11 wv(plain), 12 cv(plain)   (* computed on device)
    __nv_bfloat16 *Eb = Pb, *EbT = Pb + NELEM;

    cudaMemsetAsync(dacc, 0, 4*sizeof(double));
    cudaMemsetAsync(hist, 0, 16*sizeof(int));
    cudaMemsetAsync(esum, 0, NF*sizeof(float));
    cudaMemsetAsync(psum, 0, NF*sizeof(float));
    cudaMemcpyAsync(lab, labels_src, NS*sizeof(int), cudaMemcpyDeviceToDevice);
    cudaMemcpyAsync(lab+NS, labels_tgt, NS*sizeof(int), cudaMemcpyDeviceToDevice);

    cvt_in<<<NF, 256>>>(nodes_src, nodes_tgt, inb);
    P13 s13;
    s13.p[0]=w1; s13.p[1]=w2; s13.p[2]=wq; s13.p[3]=wk; s13.p[4]=nullptr;
    s13.p[5]=cq; s13.p[6]=ck; s13.p[7]=nullptr; s13.p[8]=Am;
    s13.p[9]=wo; s13.p[10]=co; s13.p[11]=wv; s13.p[12]=cv;
    for (int i = 0; i < 13; i++) s13.tr[i] = 1;
    s13.tr[11] = 0; s13.tr[12] = 0;
    cvtT13<<<dim3(DD, 13), 256>>>(s13, wT);

    auto TC = [&](dim3 g, const __nv_bfloat16* A, int lda, long long azs,
                  const __nv_bfloat16* B, int ldb, long long bzs, int transB,
                  int K, int ksl, int epi, float sc, int scaleN,
                  float* oF, __nv_bfloat16* oB, int ldc, long long czs, int mzoff,
                  const float* bias_, float* rsW){
        tc_nt<<<g, 256>>>(A, lda, azs, B, ldb, bzs, transB, K, ksl, epi, sc, scaleN,
                          oF, oB, ldc, czs, mzoff, bias_, rsW, dacc, lab, esum, psum);
    };

    // weight products: WvoT = woT @ wv^T(NT), WcoT similarly
    TC(dim3(2,2,1), wT+9*WSZ,256,0, wT+11*WSZ,256,0,0, 256,1, 0, 1.f,0, nullptr, wT+4*WSZ, 256,0,0, nullptr,nullptr);
    TC(dim3(2,2,1), wT+10*WSZ,256,0, wT+12*WSZ,256,0,0, 256,1, 0, 1.f,0, nullptr, wT+7*WSZ, 256,0,0, nullptr,nullptr);

    // head_in
    TC(dim3(2,32,1), inb,256,0, wT,256,0,0, 256,1, 1, 1.f,0, tf, nullptr, 256,0,0, b1, nullptr);
    ln_fast<<<NF/8,256>>>(tf, nullptr, h1b, 1);
    TC(dim3(2,32,1), h1b,256,0, wT+WSZ,256,0,0, 256,1, 1, 1.f,0, tf, nullptr, 256,0,0, b2, nullptr);
    ln_fast<<<NF/8,256>>>(tf, x0, x0b, 0);

    // ---- intra attention ----
    TC(dim3(6,32,1), x0b,256,0, wT+2*WSZ,256,0,0, 256,1, 0, 0.0625f,256, nullptr, qkv, 768,0,0, nullptr,nullptr);
    cudaMemsetAsync(rsum, 0, NF*sizeof(float));
    TC(dim3(16,16,2), qkv,768,LL3, qkv+256,768,LL3,0, 256,1, 3, 1.f,0, nullptr, Pb, NS, NELEM, NS, nullptr, rsum);
    TC(dim3(2,16,8), Pb,NS,NELEM, qkv+512,768,LL3,1, NS,4, 4, 1.f,0, S0, nullptr, 256,0, NS, nullptr,nullptr);
    pv_fin<<<NF/8,256>>>(S0, rsum, x0, x1, x1b);

    // ---- cross attention ----
    TC(dim3(6,32,1), x1b,256,0, wT+5*WSZ,256,0,0, 256,1, 0, 0.0625f,256, nullptr, qkv, 768,0,0, nullptr,nullptr);
    cudaMemsetAsync(rsum, 0, NF*sizeof(float));
    TC(dim3(16,16,2), qkv,768,LL3, qkv+256+LL3,768,-LL3,0, 256,1, 3, 1.f,0, nullptr, Pb, NS, NELEM, NS, nullptr, rsum);
    TC(dim3(2,16,8), Pb,NS,NELEM, qkv+512+LL3,768,-LL3,1, NS,4, 4, 1.f,0, S0, nullptr, 256,0, NS, nullptr,nullptr);
    pv_fin<<<NF/8,256>>>(S0, rsum, x1, x2, x2b);

    // ---- affinity + stats ----
    TC(dim3(2,16,1), x2b,256,0, wT+8*WSZ,256,0,0, 256,1, 0, 1.f,0, nullptr, qb, 256,0,0, nullptr,nullptr);
    TC(dim3(16,16,1), qb,256,0, x2b+HALF,256,0,0, 256,1, 5, 1.f,0, S0, nullptr, NS,0,0, nullptr,nullptr);
    finalize_stats<<<1,32>>>(dacc, stats);

    // E = exp((M-mu)/sigma) + transpose, then persistent Sinkhorn + match
    expT_kernel<<<dim3(32,32),256>>>(S0, stats, Eb, EbT);
    sinkhorn_all<<<256,256>>>(Eb, EbT, rv, cvv, lab, dacc);

    // SupCon
    fnorm_fast<<<NF/8,256>>>(x2, fnb);
    hist_kernel<<<16,256>>>(lab, hist);
    TC(dim3(32,32,1), fnb,256,0, fnb,256,0,0, 256,1, 6, SUPCON_SCALE,0, nullptr, nullptr, 0,0,0, nullptr,nullptr);
    supcon_final<<<NF/256,256>>>(esum, psum, lab, hist, dacc);

    finalize_kernel<<<1,32>>>(dacc, (float*)d_out);
}

// round 8
// speedup vs baseline: 5.0504x; 1.0542x over previous
#include <cuda_runtime.h>
#include <cuda_bf16.h>
#include <math.h>
#include <stdint.h>

#define NS 2048
#define DD 256
#define NF 4096
#define HALF ((long long)NS*DD)
#define LL3  ((long long)NS*768)
#define NELEM ((long long)NS*NS)
#define NFDD ((long long)NF*DD)
#define SUPCON_SCALE 14.285714285714286f

// ---------------- helpers ----------------
__device__ __forceinline__ uint32_t smem_to_u32(const void* p){
    uint32_t a;
    asm("{ .reg .u64 t; cvta.to.shared.u64 t, %1; cvt.u32.u64 %0, t; }" : "=r"(a) : "l"(p));
    return a;
}
__device__ __forceinline__ void ldsm_x4(uint32_t* r, uint32_t addr){
    asm volatile("ldmatrix.sync.aligned.m8n8.x4.shared.b16 {%0,%1,%2,%3}, [%4];"
        : "=r"(r[0]), "=r"(r[1]), "=r"(r[2]), "=r"(r[3]) : "r"(addr));
}
__device__ __forceinline__ void ldsm_x2(uint32_t* r, uint32_t addr){
    asm volatile("ldmatrix.sync.aligned.m8n8.x2.shared.b16 {%0,%1}, [%2];"
        : "=r"(r[0]), "=r"(r[1]) : "r"(addr));
}
__device__ __forceinline__ void ldsm_x2t(uint32_t* r, uint32_t addr){
    asm volatile("ldmatrix.sync.aligned.m8n8.x2.trans.shared.b16 {%0,%1}, [%2];"
        : "=r"(r[0]), "=r"(r[1]) : "r"(addr));
}
__device__ __forceinline__ void mma16816(float* c, const uint32_t* a, const uint32_t* b){
    asm volatile("mma.sync.aligned.m16n8k16.row.col.f32.bf16.bf16.f32 "
        "{%0,%1,%2,%3}, {%4,%5,%6,%7}, {%8,%9}, {%0,%1,%2,%3};"
        : "+f"(c[0]), "+f"(c[1]), "+f"(c[2]), "+f"(c[3])
        : "r"(a[0]), "r"(a[1]), "r"(a[2]), "r"(a[3]), "r"(b[0]), "r"(b[1]));
}
__device__ __forceinline__ float fexp(float x){
    float t = x * 1.4426950408889634f;
    float r = rintf(t);
    float f = t - r;
    float p =            1.3333558146e-3f;
    p = fmaf(p, f, 9.6181291076e-3f);
    p = fmaf(p, f, 5.5504108664e-2f);
    p = fmaf(p, f, 2.4022650696e-1f);
    p = fmaf(p, f, 6.9314718056e-1f);
    p = fmaf(p, f, 1.0f);
    float res = __int_as_float(__float_as_int(p) + (((int)r) << 23));
    return (x < -87.0f) ? 0.0f : res;
}
__device__ __forceinline__ float bsum256(float v, float* red){
    int tid = threadIdx.x;
    red[tid] = v; __syncthreads();
    #pragma unroll
    for (int o = 128; o > 0; o >>= 1){
        if (tid < o) red[tid] += red[tid + o];
        __syncthreads();
    }
    float r = red[0]; __syncthreads();
    return r;
}
__device__ __forceinline__ float wsum(float v){
    #pragma unroll
    for (int o = 16; o > 0; o >>= 1) v += __shfl_xor_sync(0xffffffffu, v, o);
    return v;
}

// ---------------- scratch ----------------
__device__ __nv_bfloat16 g_inb[NF*DD], g_h1b[NF*DD], g_x0b[NF*DD], g_x1b[NF*DD], g_x2b[NF*DD];
__device__ __nv_bfloat16 g_qb[NF*DD], g_fnb[NF*DD];
__device__ __nv_bfloat16 g_qkv[(long long)NF*768];
__device__ __nv_bfloat16 g_Pb[2*NELEM];
__device__ __nv_bfloat16 g_wT[13*DD*DD];
__device__ float g_tf[NF*DD], g_x0[NF*DD], g_x1[NF*DD], g_x2[NF*DD];
__device__ float g_S0[NELEM];
__device__ float g_rsum[NF], g_r[NS], g_c[NS], g_ep[2*NF];
__device__ double g_dacc[4];
__device__ int g_lab[NF], g_hist[16];
__device__ int g_cnt;
__device__ volatile int g_epoch;

// ============================================================================
// Generic bf16 HMMA NT/NN GEMM, 128x128 tile, 8 warps (2x4), 64x32 warp tiles.
// epi: 0 bf16 (scale when cc<scaleN) | 1 f32+bias | 3 exp+rowsum+bf16
//      4 split-K f32 slice | 5 f32+stats | 6 supcon triangular row+col
// ============================================================================
__global__ __launch_bounds__(256)
void tc_nt(const __nv_bfloat16* A, int lda, long long azs,
           const __nv_bfloat16* B, int ldb, long long bzs, int transB,
           int K, int ksl, int epi, float scale, int scaleN,
           float* outF, __nv_bfloat16* outB, int ldc, long long czs, int mzoff,
           const float* bias, float* rsumW, double* dacc,
           const int* lab, float* esum, float* psum)
{
    if (epi == 6 && blockIdx.x < blockIdx.y) return;
    __shared__ __nv_bfloat16 SA[128*72];
    __shared__ __nv_bfloat16 SB[128*72];
    __shared__ float red[256];

    int z = blockIdx.z;
    int dom = z / ksl, kk = z - dom*ksl;
    A += (long long)dom * azs;
    B += (long long)dom * bzs;
    if (outB) outB += (long long)dom * czs;

    int tid = threadIdx.x, wid = tid >> 5, lane = tid & 31;
    int wr = wid >> 2, wc = wid & 3;
    int row0 = blockIdx.y * 128, col0 = blockIdx.x * 128;

    uint32_t sA = smem_to_u32(SA), sB = smem_to_u32(SB);

    float acc[4][4][4];
    #pragma unroll
    for (int mi = 0; mi < 4; mi++)
        #pragma unroll
        for (int ni = 0; ni < 4; ni++)
            #pragma unroll
            for (int q = 0; q < 4; q++) acc[mi][ni][q] = 0.f;

    int aRow  = wr*64 + (lane & 7) + ((lane >> 3) & 1)*8;
    int aKoff = (lane >> 4)*8;
    int l16   = lane & 15;
    int bRow  = wc*32 + (l16 & 7);
    int bKoff = (l16 >> 3)*8;

    int nch = K >> 6;
    int c0ch = kk * nch / ksl, c1ch = (kk+1) * nch / ksl;
    for (int c = c0ch; c < c1ch; c++){
        int kc = c << 6;
        __syncthreads();
        #pragma unroll
        for (int i = 0; i < 4; i++){
            int lin = i*256 + tid;
            int r = lin >> 3, c8 = (lin & 7) << 3;
            *(uint4*)&SA[r*72 + c8] = *(const uint4*)(A + (size_t)(row0+r)*lda + kc + c8);
        }
        if (!transB){
            #pragma unroll
            for (int i = 0; i < 4; i++){
                int lin = i*256 + tid;
                int r = lin >> 3, c8 = (lin & 7) << 3;
                *(uint4*)&SB[r*72 + c8] = *(const uint4*)(B + (size_t)(col0+r)*ldb + kc + c8);
            }
        } else {
            #pragma unroll
            for (int i = 0; i < 4; i++){
                int lin = i*256 + tid;
                int r = lin >> 4, c8 = (lin & 15) << 3;
                *(uint4*)&SB[r*136 + c8] = *(const uint4*)(B + (size_t)(kc+r)*ldb + col0 + c8);
            }
        }
        __syncthreads();
        #pragma unroll
        for (int ks = 0; ks < 4; ks++){
            uint32_t af[4][4], bf[4][2];
            #pragma unroll
            for (int mi = 0; mi < 4; mi++)
                ldsm_x4(af[mi], sA + (uint32_t)(((aRow + mi*16)*72 + ks*16 + aKoff) * 2));
            if (!transB){
                #pragma unroll
                for (int ni = 0; ni < 4; ni++)
                    ldsm_x2(bf[ni], sB + (uint32_t)(((bRow + ni*8)*72 + ks*16 + bKoff) * 2));
            } else {
                #pragma unroll
                for (int ni = 0; ni < 4; ni++)
                    ldsm_x2t(bf[ni], sB + (uint32_t)(((ks*16 + l16)*136 + wc*32 + ni*8) * 2));
            }
            #pragma unroll
            for (int mi = 0; mi < 4; mi++)
                #pragma unroll
                for (int ni = 0; ni < 4; ni++)
                    mma16816(acc[mi][ni], af[mi], bf[ni]);
        }
    }

    int lr = lane >> 2, lc2 = (lane & 3) << 1;
    int colB = col0 + wc*32;
    float s1 = 0.f, s2 = 0.f;
    bool diag = (blockIdx.x == blockIdx.y);
    float colE[8], colS[8];
    #pragma unroll
    for (int q = 0; q < 8; q++){ colE[q] = 0.f; colS[q] = 0.f; }
    int labc[8];
    if (epi == 6){
        #pragma unroll
        for (int ni = 0; ni < 4; ni++){
            labc[ni*2]   = lab[colB + ni*8 + lc2];
            labc[ni*2+1] = lab[colB + ni*8 + lc2 + 1];
        }
    }

    #pragma unroll
    for (int mi = 0; mi < 4; mi++){
        #pragma unroll
        for (int h = 0; h < 2; h++){
            int r = row0 + wr*64 + mi*16 + lr + h*8;
            if (epi == 0){
                #pragma unroll
                for (int ni = 0; ni < 4; ni++){
                    int cc = colB + ni*8 + lc2;
                    float m0 = (cc   < scaleN) ? scale : 1.0f;
                    float m1 = (cc+1 < scaleN) ? scale : 1.0f;
                    float v0 = acc[mi][ni][h*2+0]*m0, v1 = acc[mi][ni][h*2+1]*m1;
                    *(__nv_bfloat162*)(outB + (size_t)r*ldc + cc) = __floats2bfloat162_rn(v0, v1);
                }
            } else if (epi == 1){
                #pragma unroll
                for (int ni = 0; ni < 4; ni++){
                    int cc = colB + ni*8 + lc2;
                    float2 o = make_float2(acc[mi][ni][h*2+0] + bias[cc],
                                           acc[mi][ni][h*2+1] + bias[cc+1]);
                    *(float2*)(outF + (size_t)r*ldc + cc) = o;
                }
            } else if (epi == 3){
                float part = 0.f;
                #pragma unroll
                for (int ni = 0; ni < 4; ni++){
                    int cc = colB + ni*8 + lc2;
                    float e0 = fexp(acc[mi][ni][h*2+0]), e1 = fexp(acc[mi][ni][h*2+1]);
                    part += e0 + e1;
                    *(__nv_bfloat162*)(outB + (size_t)r*ldc + cc) = __floats2bfloat162_rn(e0, e1);
                }
                part += __shfl_xor_sync(0xffffffffu, part, 1);
                part += __shfl_xor_sync(0xffffffffu, part, 2);
                if ((lane & 3) == 0) atomicAdd(&rsumW[dom*mzoff + r], part);
            } else if (epi == 4){
                int mg = dom*mzoff + r;
                #pragma unroll
                for (int ni = 0; ni < 4; ni++){
                    int cc = colB + ni*8 + lc2;
                    *(float2*)(outF + (long long)kk*NFDD + (size_t)mg*ldc + cc) =
                        make_float2(acc[mi][ni][h*2+0], acc[mi][ni][h*2+1]);
                }
            } else if (epi == 5){
                #pragma unroll
                for (int ni = 0; ni < 4; ni++){
                    int cc = colB + ni*8 + lc2;
                    float v0 = acc[mi][ni][h*2+0], v1 = acc[mi][ni][h*2+1];
                    *(float2*)(outF + (size_t)r*ldc + cc) = make_float2(v0, v1);
                    s1 += v0 + v1; s2 += v0*v0 + v1*v1;
                }
            } else {
                int rlab = lab[r];
                float pe = 0.f, ps = 0.f;
                #pragma unroll
                for (int ni = 0; ni < 4; ni++){
                    int cc = colB + ni*8 + lc2;
                    float l0 = acc[mi][ni][h*2+0]*scale, l1 = acc[mi][ni][h*2+1]*scale;
                    bool m0 = (labc[ni*2]   == rlab);
                    bool m1 = (labc[ni*2+1] == rlab);
                    if (cc != r){
                        float e = fexp(l0);
                        pe += e; if (m0) ps += l0;
                        if (!diag){ colE[ni*2] += e; if (m0) colS[ni*2] += l0; }
                    }
                    if (cc+1 != r){
                        float e = fexp(l1);
                        pe += e; if (m1) ps += l1;
                        if (!diag){ colE[ni*2+1] += e; if (m1) colS[ni*2+1] += l1; }
                    }
                }
                pe += __shfl_xor_sync(0xffffffffu, pe, 1);
                pe += __shfl_xor_sync(0xffffffffu, pe, 2);
                ps += __shfl_xor_sync(0xffffffffu, ps, 1);
                ps += __shfl_xor_sync(0xffffffffu, ps, 2);
                if ((lane & 3) == 0){
                    atomicAdd(&esum[r], pe);
                    atomicAdd(&psum[r], ps);
                }
            }
        }
    }
    if (epi == 6 && !diag){
        #pragma unroll
        for (int q = 0; q < 8; q++){
            #pragma unroll
            for (int o = 4; o <= 16; o <<= 1){
                colE[q] += __shfl_xor_sync(0xffffffffu, colE[q], o);
                colS[q] += __shfl_xor_sync(0xffffffffu, colS[q], o);
            }
        }
        if (lane < 4){
            #pragma unroll
            for (int ni = 0; ni < 4; ni++){
                int cc = col0 + wc*32 + ni*8 + lane*2;
                atomicAdd(&esum[cc],   colE[ni*2]);
                atomicAdd(&psum[cc],   colS[ni*2]);
                atomicAdd(&esum[cc+1], colE[ni*2+1]);
                atomicAdd(&psum[cc+1], colS[ni*2+1]);
            }
        }
    }
    if (epi == 5){
        float bs = bsum256(s1, red), bss = bsum256(s2, red);
        if (tid == 0){ atomicAdd(dacc, (double)bs); atomicAdd(dacc+1, (double)bss); }
    }
}

// ---------------- small kernels ----------------
__global__ __launch_bounds__(256)
void cvt_in(const float* __restrict__ a, const float* __restrict__ b,
            __nv_bfloat16* __restrict__ o, const int* __restrict__ lab, int* hist){
    int i = blockIdx.x, t = threadIdx.x;
    const float* src = (i < NS) ? a + (size_t)i*DD : b + (size_t)(i-NS)*DD;
    o[(size_t)i*DD + t] = __float2bfloat16(src[t]);
    if (t == 0) atomicAdd(&hist[lab[i]], 1);
}
struct P13 { const float* p[13]; int tr[13]; };
__global__ __launch_bounds__(256)
void cvtT13(P13 s, __nv_bfloat16* __restrict__ o){
    int w = blockIdx.y, n = blockIdx.x, k = threadIdx.x;
    const float* src = s.p[w];
    if (!src) return;
    float v = s.tr[w] ? src[(size_t)k*DD + n] : src[(size_t)n*DD + k];
    o[(size_t)w*DD*DD + (size_t)n*DD + k] = __float2bfloat16(v);
}
__global__ __launch_bounds__(256)
void ln_fast(const float* __restrict__ X, float* __restrict__ outF,
             __nv_bfloat16* __restrict__ outB, int relu){
    int wid = threadIdx.x >> 5, lane = threadIdx.x & 31;
    int i = blockIdx.x*8 + wid;
    const float* xp = X + (size_t)i*DD + lane*8;
    float4 a = *(const float4*)xp;
    float4 b = *(const float4*)(xp + 4);
    float s  = a.x+a.y+a.z+a.w + b.x+b.y+b.z+b.w;
    float ss = a.x*a.x+a.y*a.y+a.z*a.z+a.w*a.w + b.x*b.x+b.y*b.y+b.z*b.z+b.w*b.w;
    s = wsum(s); ss = wsum(ss);
    float m = s*(1.f/DD);
    float k = rsqrtf(ss*(1.f/DD) - m*m + 1e-5f);
    float v[8] = {a.x,a.y,a.z,a.w,b.x,b.y,b.z,b.w};
    __nv_bfloat162 ob[4];
    #pragma unroll
    for (int q = 0; q < 4; q++){
        float o0 = (v[2*q]   - m)*k;
        float o1 = (v[2*q+1] - m)*k;
        if (relu){ o0 = fmaxf(o0, 0.f); o1 = fmaxf(o1, 0.f); }
        if (outF) *(float2*)(outF + (size_t)i*DD + lane*8 + 2*q) = make_float2(o0, o1);
        ob[q] = __floats2bfloat162_rn(o0, o1);
    }
    *(uint4*)(outB + (size_t)i*DD + lane*8) = *(uint4*)ob;
}
__global__ __launch_bounds__(256)
void fnorm_fast(const float* __restrict__ X, __nv_bfloat16* __restrict__ F){
    int wid = threadIdx.x >> 5, lane = threadIdx.x & 31;
    int i = blockIdx.x*8 + wid;
    const float* xp = X + (size_t)i*DD + lane*8;
    float4 a = *(const float4*)xp;
    float4 b = *(const float4*)(xp + 4);
    float ss = a.x*a.x+a.y*a.y+a.z*a.z+a.w*a.w + b.x*b.x+b.y*b.y+b.z*b.z+b.w*b.w;
    ss = wsum(ss);
    float k = 1.0f / (sqrtf(ss) + 1e-8f);
    float v[8] = {a.x,a.y,a.z,a.w,b.x,b.y,b.z,b.w};
    __nv_bfloat162 ob[4];
    #pragma unroll
    for (int q = 0; q < 4; q++)
        ob[q] = __floats2bfloat162_rn(v[2*q]*k, v[2*q+1]*k);
    *(uint4*)(F + (size_t)i*DD + lane*8) = *(uint4*)ob;
}
__global__ __launch_bounds__(256)
void pv_fin(const float* __restrict__ acc4, const float* __restrict__ rsum,
            const float* __restrict__ res, float* __restrict__ outF,
            __nv_bfloat16* __restrict__ outB){
    int wid = threadIdx.x >> 5, lane = threadIdx.x & 31;
    int i = blockIdx.x*8 + wid;
    float rinv = 1.0f / rsum[i];
    size_t off = (size_t)i*DD + lane*8;
    float v[8];
    #pragma unroll
    for (int q = 0; q < 8; q++) v[q] = 0.f;
    #pragma unroll
    for (int sl = 0; sl < 4; sl++){
        const float* p = acc4 + (long long)sl*NFDD + off;
        float4 a = *(const float4*)p;
        float4 b = *(const float4*)(p + 4);
        v[0]+=a.x; v[1]+=a.y; v[2]+=a.z; v[3]+=a.w;
        v[4]+=b.x; v[5]+=b.y; v[6]+=b.z; v[7]+=b.w;
    }
    const float* rp = res + off;
    float4 ra = *(const float4*)rp;
    float4 rb = *(const float4*)(rp + 4);
    float rr[8] = {ra.x,ra.y,ra.z,ra.w,rb.x,rb.y,rb.z,rb.w};
    __nv_bfloat162 ob[4];
    #pragma unroll
    for (int q = 0; q < 4; q++){
        float o0 = fmaf(v[2*q],   rinv, rr[2*q]);
        float o1 = fmaf(v[2*q+1], rinv, rr[2*q+1]);
        *(float2*)(outF + off + 2*q) = make_float2(o0, o1);
        ob[q] = __floats2bfloat162_rn(o0, o1);
    }
    *(uint4*)(outB + off) = *(uint4*)ob;
}
// E = exp((S0-mu)*inv) bf16 + transpose; stats derived inline from dacc
__global__ __launch_bounds__(256)
void expT_kernel(const float* __restrict__ S0, const double* __restrict__ dacc,
                 __nv_bfloat16* __restrict__ E, __nv_bfloat16* __restrict__ ET){
    __shared__ float sm[64][68];
    double n = (double)NELEM;
    double mu_d = dacc[0] / n;
    double var = dacc[1] / n - mu_d*mu_d;
    float inv = (float)(1.0 / (sqrt(var) + 1e-5));
    float muinv = (float)mu_d * inv;
    int tid = threadIdx.x;
    int r0 = blockIdx.y*64, c0 = blockIdx.x*64;
    #pragma unroll
    for (int i = 0; i < 4; i++){
        int lin = i*256 + tid;
        int r = lin >> 4, c4 = (lin & 15) << 2;
        float4 v = *(const float4*)(S0 + (size_t)(r0+r)*NS + c0 + c4);
        sm[r][c4+0] = fexp(fmaf(v.x, inv, -muinv));
        sm[r][c4+1] = fexp(fmaf(v.y, inv, -muinv));
        sm[r][c4+2] = fexp(fmaf(v.z, inv, -muinv));
        sm[r][c4+3] = fexp(fmaf(v.w, inv, -muinv));
    }
    __syncthreads();
    #pragma unroll
    for (int i = 0; i < 2; i++){
        int lin = i*256 + tid;
        int r = lin >> 3, g8 = (lin & 7) << 3;
        __nv_bfloat162 ob[4];
        #pragma unroll
        for (int q = 0; q < 4; q++)
            ob[q] = __floats2bfloat162_rn(sm[r][g8+2*q], sm[r][g8+2*q+1]);
        *(uint4*)(E + (size_t)(r0+r)*NS + c0 + g8) = *(uint4*)ob;
        #pragma unroll
        for (int q = 0; q < 4; q++)
            ob[q] = __floats2bfloat162_rn(sm[g8+2*q][r], sm[g8+2*q+1][r]);
        *(uint4*)(ET + (size_t)(c0+r)*NS + r0 + g8) = *(uint4*)ob;
    }
}
// Persistent Sinkhorn: 20 half-steps + match loss, one launch, 256 blocks.
__global__ __launch_bounds__(256)
void sinkhorn_all(const __nv_bfloat16* __restrict__ E, const __nv_bfloat16* __restrict__ ET,
                  float* __restrict__ rv, float* __restrict__ cvv,
                  const int* __restrict__ lab, double* acc){
    int tid = threadIdx.x, wid = tid >> 5, lane = tid & 31;
    int row = blockIdx.x*8 + wid;
    int nb = gridDim.x;
    for (int pass = 0; pass < 20; pass++){
        const __nv_bfloat16* M = (pass & 1) ? ET : E;
        const float* in = (pass & 1) ? rv : cvv;
        float* out = (pass & 1) ? cvv : rv;
        float s = 0.f;
        #pragma unroll
        for (int b = 0; b < 8; b++){
            int j = (b*32 + lane)*8;
            uint4 u = *(const uint4*)(M + (size_t)row*NS + j);
            float2 e0 = __bfloat1622float2(*(__nv_bfloat162*)&u.x);
            float2 e1 = __bfloat1622float2(*(__nv_bfloat162*)&u.y);
            float2 e2 = __bfloat1622float2(*(__nv_bfloat162*)&u.z);
            float2 e3 = __bfloat1622float2(*(__nv_bfloat162*)&u.w);
            if (pass == 0){
                s += e0.x+e0.y+e1.x+e1.y+e2.x+e2.y+e3.x+e3.y;
            } else {
                float4 c0 = *(const float4*)(in + j);
                float4 c1 = *(const float4*)(in + j + 4);
                s += e0.x*c0.x + e0.y*c0.y + e1.x*c0.z + e1.y*c0.w
                   + e2.x*c1.x + e2.y*c1.y + e3.x*c1.z + e3.y*c1.w;
            }
        }
        s = wsum(s);
        if (lane == 0) out[row] = 1.0f / s;
        __threadfence();
        __syncthreads();
        if (tid == 0){
            int e = g_epoch;
            if (atomicAdd(&g_cnt, 1) == nb - 1){
                g_cnt = 0;
                __threadfence();
                g_epoch = e + 1;
            } else {
                while (g_epoch == e) { }
            }
            __threadfence();
        }
        __syncthreads();
    }
    float eri = rv[row];
    int li = lab[row];
    float s = 0.f;
    #pragma unroll
    for (int b = 0; b < 8; b++){
        int j = (b*32 + lane)*8;
        uint4 u = *(const uint4*)(E + (size_t)row*NS + j);
        float2 e0 = __bfloat1622float2(*(__nv_bfloat162*)&u.x);
        float2 e1 = __bfloat1622float2(*(__nv_bfloat162*)&u.y);
        float2 e2 = __bfloat1622float2(*(__nv_bfloat162*)&u.z);
        float2 e3 = __bfloat1622float2(*(__nv_bfloat162*)&u.w);
        float ev[8] = {e0.x,e0.y,e1.x,e1.y,e2.x,e2.y,e3.x,e3.y};
        float4 c0 = *(const float4*)(cvv + j);
        float4 c1 = *(const float4*)(cvv + j + 4);
        float cv8[8] = {c0.x,c0.y,c0.z,c0.w,c1.x,c1.y,c1.z,c1.w};
        #pragma unroll
        for (int q = 0; q < 8; q++){
            float p = ev[q] * eri * cv8[q];
            float gt = (li == lab[NS + j + q]) ? 1.f : 0.f;
            s += fabsf(p - gt);
        }
    }
    s = wsum(s);
    if (lane == 0) atomicAdd(acc + 2, (double)s);
}
__global__ __launch_bounds__(256)
void supcon_final(const float* __restrict__ es, const float* __restrict__ ps,
                  const int* __restrict__ lab, const int* __restrict__ h, double* acc){
    __shared__ float red[256];
    int i = blockIdx.x*256 + threadIdx.x;
    float cnt = (float)(h[lab[i]] - 1);
    float v = ps[i]/cnt - logf(es[i]);
    float s = bsum256(v, red);
    if (threadIdx.x == 0) atomicAdd(acc + 3, (double)s);
}
__global__ void finalize_kernel(const double* acc, float* out){
    if (threadIdx.x == 0 && blockIdx.x == 0)
        out[0] = (float)(acc[2] + 0.1 * (-(acc[3] / (double)NF)));
}

// ---------------- host ----------------
extern "C" void kernel_launch(void* const* d_in, const int* in_sizes, int n_in,
                              void* d_out, int out_size){
    const float *nodes_src=(const float*)d_in[0], *nodes_tgt=(const float*)d_in[1];
    const int *labels_src=(const int*)d_in[2], *labels_tgt=(const int*)d_in[3];
    const float *w1=(const float*)d_in[4], *b1=(const float*)d_in[5];
    const float *w2=(const float*)d_in[6], *b2=(const float*)d_in[7];
    const float *wq=(const float*)d_in[8], *wk=(const float*)d_in[9];
    const float *wv=(const float*)d_in[10], *wo=(const float*)d_in[11];
    const float *cq=(const float*)d_in[12], *ck=(const float*)d_in[13];
    const float *cv=(const float*)d_in[14], *co=(const float*)d_in[15];
    const float *Am=(const float*)d_in[16];

    __nv_bfloat16 *inb,*h1b,*x0b,*x1b,*x2b,*qb,*fnb,*qkv,*Pb,*wT;
    float *tf,*x0,*x1,*x2,*S0,*rsum,*rv,*cvv,*ep;
    double* dacc; int *lab,*hist;
    cudaGetSymbolAddress((void**)&inb,g_inb); cudaGetSymbolAddress((void**)&h1b,g_h1b);
    cudaGetSymbolAddress((void**)&x0b,g_x0b); cudaGetSymbolAddress((void**)&x1b,g_x1b);
    cudaGetSymbolAddress((void**)&x2b,g_x2b); cudaGetSymbolAddress((void**)&qb,g_qb);
    cudaGetSymbolAddress((void**)&fnb,g_fnb); cudaGetSymbolAddress((void**)&qkv,g_qkv);
    cudaGetSymbolAddress((void**)&Pb,g_Pb);   cudaGetSymbolAddress((void**)&wT,g_wT);
    cudaGetSymbolAddress((void**)&tf,g_tf);   cudaGetSymbolAddress((void**)&x0,g_x0);
    cudaGetSymbolAddress((void**)&x1,g_x1);   cudaGetSymbolAddress((void**)&x2,g_x2);
    cudaGetSymbolAddress((void**)&S0,g_S0);   cudaGetSymbolAddress((void**)&rsum,g_rsum);
    cudaGetSymbolAddress((void**)&rv,g_r);    cudaGetSymbolAddress((void**)&cvv,g_c);
    cudaGetSymbolAddress((void**)&ep,g_ep);   cudaGetSymbolAddress((void**)&dacc,g_dacc);
    cudaGetSymbolAddress((void**)&lab,g_lab); cudaGetSymbolAddress((void**)&hist,g_hist);
    float *esum = ep, *psum = ep + NF;

    const int WSZ = DD*DD;
    // slots: 0 w1T, 1 w2T, 2 wqT|wkT|WvoT, 5 cqT|ckT|WcoT, 8 AT, 9 woT, 10 coT, 11 wv, 12 cv
    __nv_bfloat16 *Eb = Pb, *EbT = Pb + NELEM;

    cudaMemsetAsync(dacc, 0, 4*sizeof(double));
    cudaMemsetAsync(hist, 0, 16*sizeof(int));
    cudaMemsetAsync(ep, 0, 2*NF*sizeof(float));
    cudaMemcpyAsync(lab, labels_src, NS*sizeof(int), cudaMemcpyDeviceToDevice);
    cudaMemcpyAsync(lab+NS, labels_tgt, NS*sizeof(int), cudaMemcpyDeviceToDevice);

    cvt_in<<<NF, 256>>>(nodes_src, nodes_tgt, inb, lab, hist);
    P13 s13;
    s13.p[0]=w1; s13.p[1]=w2; s13.p[2]=wq; s13.p[3]=wk; s13.p[4]=nullptr;
    s13.p[5]=cq; s13.p[6]=ck; s13.p[7]=nullptr; s13.p[8]=Am;
    s13.p[9]=wo; s13.p[10]=co; s13.p[11]=wv; s13.p[12]=cv;
    for (int i = 0; i < 13; i++) s13.tr[i] = 1;
    s13.tr[11] = 0; s13.tr[12] = 0;
    cvtT13<<<dim3(DD, 13), 256>>>(s13, wT);

    auto TC = [&](dim3 g, const __nv_bfloat16* A, int lda, long long azs,
                  const __nv_bfloat16* B, int ldb, long long bzs, int transB,
                  int K, int ksl, int epi, float sc, int scaleN,
                  float* oF, __nv_bfloat16* oB, int ldc, long long czs, int mzoff,
                  const float* bias_, float* rsW){
        tc_nt<<<g, 256>>>(A, lda, azs, B, ldb, bzs, transB, K, ksl, epi, sc, scaleN,
                          oF, oB, ldc, czs, mzoff, bias_, rsW, dacc, lab, esum, psum);
    };

    // merged weight products: z=0: WvoT = woT@wv^T → slot4;  z=1: WcoT = coT@cv^T → slot7
    TC(dim3(2,2,2), wT+9*WSZ,256,WSZ, wT+11*WSZ,256,WSZ,0, 256,1, 0, 1.f,0,
       nullptr, wT+4*WSZ, 256, 3ll*WSZ, 0, nullptr,nullptr);

    // head_in
    TC(dim3(2,32,1), inb,256,0, wT,256,0,0, 256,1, 1, 1.f,0, tf, nullptr, 256,0,0, b1, nullptr);
    ln_fast<<<NF/8,256>>>(tf, nullptr, h1b, 1);
    TC(dim3(2,32,1), h1b,256,0, wT+WSZ,256,0,0, 256,1, 1, 1.f,0, tf, nullptr, 256,0,0, b2, nullptr);
    ln_fast<<<NF/8,256>>>(tf, x0, x0b, 0);

    // ---- intra attention ----
    TC(dim3(6,32,1), x0b,256,0, wT+2*WSZ,256,0,0, 256,1, 0, 0.0625f,256, nullptr, qkv, 768,0,0, nullptr,nullptr);
    cudaMemsetAsync(rsum, 0, NF*sizeof(float));
    TC(dim3(16,16,2), qkv,768,LL3, qkv+256,768,LL3,0, 256,1, 3, 1.f,0, nullptr, Pb, NS, NELEM, NS, nullptr, rsum);
    TC(dim3(2,16,8), Pb,NS,NELEM, qkv+512,768,LL3,1, NS,4, 4, 1.f,0, S0, nullptr, 256,0, NS, nullptr,nullptr);
    pv_fin<<<NF/8,256>>>(S0, rsum, x0, x1, x1b);

    // ---- cross attention ----
    TC(dim3(6,32,1), x1b,256,0, wT+5*WSZ,256,0,0, 256,1, 0, 0.0625f,256, nullptr, qkv, 768,0,0, nullptr,nullptr);
    cudaMemsetAsync(rsum, 0, NF*sizeof(float));
    TC(dim3(16,16,2), qkv,768,LL3, qkv+256+LL3,768,-LL3,0, 256,1, 3, 1.f,0, nullptr, Pb, NS, NELEM, NS, nullptr, rsum);
    TC(dim3(2,16,8), Pb,NS,NELEM, qkv+512+LL3,768,-LL3,1, NS,4, 4, 1.f,0, S0, nullptr, 256,0, NS, nullptr,nullptr);
    pv_fin<<<NF/8,256>>>(S0, rsum, x1, x2, x2b);

    // ---- affinity + stats ----
    TC(dim3(2,16,1), x2b,256,0, wT+8*WSZ,256,0,0, 256,1, 0, 1.f,0, nullptr, qb, 256,0,0, nullptr,nullptr);
    TC(dim3(16,16,1), qb,256,0, x2b+HALF,256,0,0, 256,1, 5, 1.f,0, S0, nullptr, NS,0,0, nullptr,nullptr);

    // E = exp((M-mu)/sigma) + transpose (stats inline), persistent Sinkhorn + match
    expT_kernel<<<dim3(32,32),256>>>(S0, dacc, Eb, EbT);
    sinkhorn_all<<<256,256>>>(Eb, EbT, rv, cvv, lab, dacc);

    // SupCon (triangular)
    fnorm_fast<<<NF/8,256>>>(x2, fnb);
    TC(dim3(32,32,1), fnb,256,0, fnb,256,0,0, 256,1, 6, SUPCON_SCALE,0, nullptr, nullptr, 0,0,0, nullptr,nullptr);
    supcon_final<<<NF/256,256>>>(esum, psum, lab, hist, dacc);

    finalize_kernel<<<1,32>>>(dacc, (float*)d_out);
}

// round 9
// speedup vs baseline: 5.4185x; 1.0729x over previous
#include <cuda_runtime.h>
#include <cuda_bf16.h>
#include <math.h>
#include <stdint.h>

#define NS 2048
#define DD 256
#define NF 4096
#define HALF ((long long)NS*DD)
#define LL2  ((long long)NS*512)
#define NELEM ((long long)NS*NS)
#define NFDD ((long long)NF*DD)
#define SUPCON_SCALE 14.285714285714286f

// ---------------- helpers ----------------
__device__ __forceinline__ uint32_t smem_to_u32(const void* p){
    uint32_t a;
    asm("{ .reg .u64 t; cvta.to.shared.u64 t, %1; cvt.u32.u64 %0, t; }" : "=r"(a) : "l"(p));
    return a;
}
__device__ __forceinline__ void cp16(void* s, const void* g){
    uint32_t sa = smem_to_u32(s);
    asm volatile("cp.async.ca.shared.global [%0], [%1], 16;" :: "r"(sa), "l"(g) : "memory");
}
__device__ __forceinline__ void ldsm_x4(uint32_t* r, uint32_t addr){
    asm volatile("ldmatrix.sync.aligned.m8n8.x4.shared.b16 {%0,%1,%2,%3}, [%4];"
        : "=r"(r[0]), "=r"(r[1]), "=r"(r[2]), "=r"(r[3]) : "r"(addr));
}
__device__ __forceinline__ void ldsm_x2(uint32_t* r, uint32_t addr){
    asm volatile("ldmatrix.sync.aligned.m8n8.x2.shared.b16 {%0,%1}, [%2];"
        : "=r"(r[0]), "=r"(r[1]) : "r"(addr));
}
__device__ __forceinline__ void ldsm_x2t(uint32_t* r, uint32_t addr){
    asm volatile("ldmatrix.sync.aligned.m8n8.x2.trans.shared.b16 {%0,%1}, [%2];"
        : "=r"(r[0]), "=r"(r[1]) : "r"(addr));
}
__device__ __forceinline__ void mma16816(float* c, const uint32_t* a, const uint32_t* b){
    asm volatile("mma.sync.aligned.m16n8k16.row.col.f32.bf16.bf16.f32 "
        "{%0,%1,%2,%3}, {%4,%5,%6,%7}, {%8,%9}, {%0,%1,%2,%3};"
        : "+f"(c[0]), "+f"(c[1]), "+f"(c[2]), "+f"(c[3])
        : "r"(a[0]), "r"(a[1]), "r"(a[2]), "r"(a[3]), "r"(b[0]), "r"(b[1]));
}
__device__ __forceinline__ float fexp(float x){
    float t = x * 1.4426950408889634f;
    float r = rintf(t);
    float f = t - r;
    float p =            1.3333558146e-3f;
    p = fmaf(p, f, 9.6181291076e-3f);
    p = fmaf(p, f, 5.5504108664e-2f);
    p = fmaf(p, f, 2.4022650696e-1f);
    p = fmaf(p, f, 6.9314718056e-1f);
    p = fmaf(p, f, 1.0f);
    float res = __int_as_float(__float_as_int(p) + (((int)r) << 23));
    return (x < -87.0f) ? 0.0f : res;
}
__device__ __forceinline__ float bsum256(float v, float* red){
    int tid = threadIdx.x;
    red[tid] = v; __syncthreads();
    #pragma unroll
    for (int o = 128; o > 0; o >>= 1){
        if (tid < o) red[tid] += red[tid + o];
        __syncthreads();
    }
    float r = red[0]; __syncthreads();
    return r;
}
__device__ __forceinline__ float wsum(float v){
    #pragma unroll
    for (int o = 16; o > 0; o >>= 1) v += __shfl_xor_sync(0xffffffffu, v, o);
    return v;
}

// ---------------- scratch ----------------
__device__ __nv_bfloat16 g_inb[NF*DD], g_h1b[NF*DD], g_x0b[NF*DD], g_x1b[NF*DD], g_x2b[NF*DD];
__device__ __nv_bfloat16 g_qb[NF*DD], g_fnb[NF*DD];
__device__ __nv_bfloat16 g_qkv[(long long)NF*512];
__device__ __nv_bfloat16 g_Pb[2*NELEM];
__device__ __nv_bfloat16 g_wT[17*DD*DD];
__device__ float g_tf[NF*DD], g_x0[NF*DD], g_x1[NF*DD], g_x2[NF*DD];
__device__ float g_S0[NELEM];
__device__ float g_rsum[NF], g_r[NS], g_c[NS], g_ep[2*NF];
__device__ double g_dacc[4];
__device__ int g_lab[NF], g_hist[16];
__device__ int g_cnt;
__device__ volatile int g_epoch;

// ============================================================================
// Generic bf16 HMMA NT/NN GEMM, 128x128 tile, 8 warps (2x4), 64x32 warp tiles.
// Double-buffered smem with cp.async prefetch.
// epi: 0 bf16 | 1 f32+bias | 3 exp+rowsum+bf16 | 4 split-K f32 slice
//      5 f32+stats | 6 supcon triangular row+col
// ============================================================================
__global__ __launch_bounds__(256)
void tc_nt(const __nv_bfloat16* A, int lda, long long azs,
           const __nv_bfloat16* B, int ldb, long long bzs, int transB,
           int K, int ksl, int epi, float scale, int scaleN,
           float* outF, __nv_bfloat16* outB, int ldc, long long czs, int mzoff,
           const float* bias, float* rsumW, double* dacc,
           const int* lab, float* esum, float* psum)
{
    if (epi == 6 && blockIdx.x < blockIdx.y) return;
    __shared__ __nv_bfloat16 SA[2][128*72];
    __shared__ __nv_bfloat16 SB[2][128*72];
    __shared__ float red[256];

    int z = blockIdx.z;
    int dom = z / ksl, kk = z - dom*ksl;
    A += (long long)dom * azs;
    B += (long long)dom * bzs;
    if (outB) outB += (long long)dom * czs;

    int tid = threadIdx.x, wid = tid >> 5, lane = tid & 31;
    int wr = wid >> 2, wc = wid & 3;
    int row0 = blockIdx.y * 128, col0 = blockIdx.x * 128;

    float acc[4][4][4];
    #pragma unroll
    for (int mi = 0; mi < 4; mi++)
        #pragma unroll
        for (int ni = 0; ni < 4; ni++)
            #pragma unroll
            for (int q = 0; q < 4; q++) acc[mi][ni][q] = 0.f;

    int aRow  = wr*64 + (lane & 7) + ((lane >> 3) & 1)*8;
    int aKoff = (lane >> 4)*8;
    int l16   = lane & 15;
    int bRow  = wc*32 + (l16 & 7);
    int bKoff = (l16 >> 3)*8;

    int nch = K >> 6;
    int c0ch = kk * nch / ksl, c1ch = (kk+1) * nch / ksl;

    auto load_chunk = [&](int c, int buf){
        int kc = c << 6;
        #pragma unroll
        for (int i = 0; i < 4; i++){
            int lin = i*256 + tid;
            int r = lin >> 3, c8 = (lin & 7) << 3;
            cp16(&SA[buf][r*72 + c8], A + (size_t)(row0+r)*lda + kc + c8);
        }
        if (!transB){
            #pragma unroll
            for (int i = 0; i < 4; i++){
                int lin = i*256 + tid;
                int r = lin >> 3, c8 = (lin & 7) << 3;
                cp16(&SB[buf][r*72 + c8], B + (size_t)(col0+r)*ldb + kc + c8);
            }
        } else {
            #pragma unroll
            for (int i = 0; i < 4; i++){
                int lin = i*256 + tid;
                int r = lin >> 4, c8 = (lin & 15) << 3;
                cp16(&SB[buf][r*136 + c8], B + (size_t)(kc+r)*ldb + col0 + c8);
            }
        }
    };

    load_chunk(c0ch, 0);
    asm volatile("cp.async.commit_group;" ::: "memory");
    asm volatile("cp.async.wait_group 0;" ::: "memory");
    __syncthreads();

    for (int c = c0ch; c < c1ch; c++){
        int buf = (c - c0ch) & 1;
        if (c + 1 < c1ch){
            load_chunk(c+1, buf^1);
            asm volatile("cp.async.commit_group;" ::: "memory");
        }
        uint32_t sAb = smem_to_u32(SA[buf]);
        uint32_t sBb = smem_to_u32(SB[buf]);
        #pragma unroll
        for (int ks = 0; ks < 4; ks++){
            uint32_t af[4][4], bf[4][2];
            #pragma unroll
            for (int mi = 0; mi < 4; mi++)
                ldsm_x4(af[mi], sAb + (uint32_t)(((aRow + mi*16)*72 + ks*16 + aKoff) * 2));
            if (!transB){
                #pragma unroll
                for (int ni = 0; ni < 4; ni++)
                    ldsm_x2(bf[ni], sBb + (uint32_t)(((bRow + ni*8)*72 + ks*16 + bKoff) * 2));
            } else {
                #pragma unroll
                for (int ni = 0; ni < 4; ni++)
                    ldsm_x2t(bf[ni], sBb + (uint32_t)(((ks*16 + l16)*136 + wc*32 + ni*8) * 2));
            }
            #pragma unroll
            for (int mi = 0; mi < 4; mi++)
                #pragma unroll
                for (int ni = 0; ni < 4; ni++)
                    mma16816(acc[mi][ni], af[mi], bf[ni]);
        }
        if (c + 1 < c1ch)
            asm volatile("cp.async.wait_group 0;" ::: "memory");
        __syncthreads();
    }

    int lr = lane >> 2, lc2 = (lane & 3) << 1;
    int colB = col0 + wc*32;
    float s1 = 0.f, s2 = 0.f;
    bool diag = (blockIdx.x == blockIdx.y);
    float colE[8], colS[8];
    #pragma unroll
    for (int q = 0; q < 8; q++){ colE[q] = 0.f; colS[q] = 0.f; }
    int labc[8];
    if (epi == 6){
        #pragma unroll
        for (int ni = 0; ni < 4; ni++){
            labc[ni*2]   = lab[colB + ni*8 + lc2];
            labc[ni*2+1] = lab[colB + ni*8 + lc2 + 1];
        }
    }

    #pragma unroll
    for (int mi = 0; mi < 4; mi++){
        #pragma unroll
        for (int h = 0; h < 2; h++){
            int r = row0 + wr*64 + mi*16 + lr + h*8;
            if (epi == 0){
                #pragma unroll
                for (int ni = 0; ni < 4; ni++){
                    int cc = colB + ni*8 + lc2;
                    float m0 = (cc   < scaleN) ? scale : 1.0f;
                    float m1 = (cc+1 < scaleN) ? scale : 1.0f;
                    float v0 = acc[mi][ni][h*2+0]*m0, v1 = acc[mi][ni][h*2+1]*m1;
                    *(__nv_bfloat162*)(outB + (size_t)r*ldc + cc) = __floats2bfloat162_rn(v0, v1);
                }
            } else if (epi == 1){
                #pragma unroll
                for (int ni = 0; ni < 4; ni++){
                    int cc = colB + ni*8 + lc2;
                    float2 o = make_float2(acc[mi][ni][h*2+0] + bias[cc],
                                           acc[mi][ni][h*2+1] + bias[cc+1]);
                    *(float2*)(outF + (size_t)r*ldc + cc) = o;
                }
            } else if (epi == 3){
                float part = 0.f;
                #pragma unroll
                for (int ni = 0; ni < 4; ni++){
                    int cc = colB + ni*8 + lc2;
                    float e0 = fexp(acc[mi][ni][h*2+0]), e1 = fexp(acc[mi][ni][h*2+1]);
                    part += e0 + e1;
                    *(__nv_bfloat162*)(outB + (size_t)r*ldc + cc) = __floats2bfloat162_rn(e0, e1);
                }
                part += __shfl_xor_sync(0xffffffffu, part, 1);
                part += __shfl_xor_sync(0xffffffffu, part, 2);
                if ((lane & 3) == 0) atomicAdd(&rsumW[dom*mzoff + r], part);
            } else if (epi == 4){
                int mg = dom*mzoff + r;
                #pragma unroll
                for (int ni = 0; ni < 4; ni++){
                    int cc = colB + ni*8 + lc2;
                    *(float2*)(outF + (long long)kk*NFDD + (size_t)mg*ldc + cc) =
                        make_float2(acc[mi][ni][h*2+0], acc[mi][ni][h*2+1]);
                }
            } else if (epi == 5){
                #pragma unroll
                for (int ni = 0; ni < 4; ni++){
                    int cc = colB + ni*8 + lc2;
                    float v0 = acc[mi][ni][h*2+0], v1 = acc[mi][ni][h*2+1];
                    *(float2*)(outF + (size_t)r*ldc + cc) = make_float2(v0, v1);
                    s1 += v0 + v1; s2 += v0*v0 + v1*v1;
                }
            } else {
                int rlab = lab[r];
                float pe = 0.f, ps = 0.f;
                #pragma unroll
                for (int ni = 0; ni < 4; ni++){
                    int cc = colB + ni*8 + lc2;
                    float l0 = acc[mi][ni][h*2+0]*scale, l1 = acc[mi][ni][h*2+1]*scale;
                    bool m0 = (labc[ni*2]   == rlab);
                    bool m1 = (labc[ni*2+1] == rlab);
                    if (cc != r){
                        float e = fexp(l0);
                        pe += e; if (m0) ps += l0;
                        if (!diag){ colE[ni*2] += e; if (m0) colS[ni*2] += l0; }
                    }
                    if (cc+1 != r){
                        float e = fexp(l1);
                        pe += e; if (m1) ps += l1;
                        if (!diag){ colE[ni*2+1] += e; if (m1) colS[ni*2+1] += l1; }
                    }
                }
                pe += __shfl_xor_sync(0xffffffffu, pe, 1);
                pe += __shfl_xor_sync(0xffffffffu, pe, 2);
                ps += __shfl_xor_sync(0xffffffffu, ps, 1);
                ps += __shfl_xor_sync(0xffffffffu, ps, 2);
                if ((lane & 3) == 0){
                    atomicAdd(&esum[r], pe);
                    atomicAdd(&psum[r], ps);
                }
            }
        }
    }
    if (epi == 6 && !diag){
        #pragma unroll
        for (int q = 0; q < 8; q++){
            #pragma unroll
            for (int o = 4; o <= 16; o <<= 1){
                colE[q] += __shfl_xor_sync(0xffffffffu, colE[q], o);
                colS[q] += __shfl_xor_sync(0xffffffffu, colS[q], o);
            }
        }
        if (lane < 4){
            #pragma unroll
            for (int ni = 0; ni < 4; ni++){
                int cc = col0 + wc*32 + ni*8 + lane*2;
                atomicAdd(&esum[cc],   colE[ni*2]);
                atomicAdd(&psum[cc],   colS[ni*2]);
                atomicAdd(&esum[cc+1], colE[ni*2+1]);
                atomicAdd(&psum[cc+1], colS[ni*2+1]);
            }
        }
    }
    if (epi == 5){
        float bs = bsum256(s1, red), bss = bsum256(s2, red);
        if (tid == 0){ atomicAdd(dacc, (double)bs); atomicAdd(dacc+1, (double)bss); }
    }
}

// ---------------- small kernels ----------------
__global__ __launch_bounds__(256)
void cvt_in(const float* __restrict__ a, const float* __restrict__ b,
            __nv_bfloat16* __restrict__ o, const int* __restrict__ lab, int* hist){
    int i = blockIdx.x, t = threadIdx.x;
    const float* src = (i < NS) ? a + (size_t)i*DD : b + (size_t)(i-NS)*DD;
    o[(size_t)i*DD + t] = __float2bfloat16(src[t]);
    if (t == 0) atomicAdd(&hist[lab[i]], 1);
}
struct P17 { const float* p[17]; int tr[17]; float sc[17]; };
__global__ __launch_bounds__(256)
void cvtT17(P17 s, __nv_bfloat16* __restrict__ o){
    int w = blockIdx.y, n = blockIdx.x, k = threadIdx.x;
    const float* src = s.p[w];
    if (!src) return;
    float v = s.tr[w] ? src[(size_t)k*DD + n] : src[(size_t)n*DD + k];
    o[(size_t)w*DD*DD + (size_t)n*DD + k] = __float2bfloat16(v * s.sc[w]);
}
__global__ __launch_bounds__(256)
void ln_fast(const float* __restrict__ X, float* __restrict__ outF,
             __nv_bfloat16* __restrict__ outB, int relu){
    int wid = threadIdx.x >> 5, lane = threadIdx.x & 31;
    int i = blockIdx.x*8 + wid;
    const float* xp = X + (size_t)i*DD + lane*8;
    float4 a = *(const float4*)xp;
    float4 b = *(const float4*)(xp + 4);
    float s  = a.x+a.y+a.z+a.w + b.x+b.y+b.z+b.w;
    float ss = a.x*a.x+a.y*a.y+a.z*a.z+a.w*a.w + b.x*b.x+b.y*b.y+b.z*b.z+b.w*b.w;
    s = wsum(s); ss = wsum(ss);
    float m = s*(1.f/DD);
    float k = rsqrtf(ss*(1.f/DD) - m*m + 1e-5f);
    float v[8] = {a.x,a.y,a.z,a.w,b.x,b.y,b.z,b.w};
    __nv_bfloat162 ob[4];
    #pragma unroll
    for (int q = 0; q < 4; q++){
        float o0 = (v[2*q]   - m)*k;
        float o1 = (v[2*q+1] - m)*k;
        if (relu){ o0 = fmaxf(o0, 0.f); o1 = fmaxf(o1, 0.f); }
        if (outF) *(float2*)(outF + (size_t)i*DD + lane*8 + 2*q) = make_float2(o0, o1);
        ob[q] = __floats2bfloat162_rn(o0, o1);
    }
    *(uint4*)(outB + (size_t)i*DD + lane*8) = *(uint4*)ob;
}
__global__ __launch_bounds__(256)
void fnorm_fast(const float* __restrict__ X, __nv_bfloat16* __restrict__ F){
    int wid = threadIdx.x >> 5, lane = threadIdx.x & 31;
    int i = blockIdx.x*8 + wid;
    const float* xp = X + (size_t)i*DD + lane*8;
    float4 a = *(const float4*)xp;
    float4 b = *(const float4*)(xp + 4);
    float ss = a.x*a.x+a.y*a.y+a.z*a.z+a.w*a.w + b.x*b.x+b.y*b.y+b.z*b.z+b.w*b.w;
    ss = wsum(ss);
    float k = 1.0f / (sqrtf(ss) + 1e-8f);
    float v[8] = {a.x,a.y,a.z,a.w,b.x,b.y,b.z,b.w};
    __nv_bfloat162 ob[4];
    #pragma unroll
    for (int q = 0; q < 4; q++)
        ob[q] = __floats2bfloat162_rn(v[2*q]*k, v[2*q+1]*k);
    *(uint4*)(F + (size_t)i*DD + lane*8) = *(uint4*)ob;
}
__global__ __launch_bounds__(256)
void pv_fin(const float* __restrict__ acc4, const float* __restrict__ rsum,
            const float* __restrict__ res, float* __restrict__ outF,
            __nv_bfloat16* __restrict__ outB){
    int wid = threadIdx.x >> 5, lane = threadIdx.x & 31;
    int i = blockIdx.x*8 + wid;
    float rinv = 1.0f / rsum[i];
    size_t off = (size_t)i*DD + lane*8;
    float v[8];
    #pragma unroll
    for (int q = 0; q < 8; q++) v[q] = 0.f;
    #pragma unroll
    for (int sl = 0; sl < 4; sl++){
        const float* p = acc4 + (long long)sl*NFDD + off;
        float4 a = *(const float4*)p;
        float4 b = *(const float4*)(p + 4);
        v[0]+=a.x; v[1]+=a.y; v[2]+=a.z; v[3]+=a.w;
        v[4]+=b.x; v[5]+=b.y; v[6]+=b.z; v[7]+=b.w;
    }
    const float* rp = res + off;
    float4 ra = *(const float4*)rp;
    float4 rb = *(const float4*)(rp + 4);
    float rr[8] = {ra.x,ra.y,ra.z,ra.w,rb.x,rb.y,rb.z,rb.w};
    __nv_bfloat162 ob[4];
    #pragma unroll
    for (int q = 0; q < 4; q++){
        float o0 = fmaf(v[2*q],   rinv, rr[2*q]);
        float o1 = fmaf(v[2*q+1], rinv, rr[2*q+1]);
        *(float2*)(outF + off + 2*q) = make_float2(o0, o1);
        ob[q] = __floats2bfloat162_rn(o0, o1);
    }
    *(uint4*)(outB + off) = *(uint4*)ob;
}
__global__ __launch_bounds__(256)
void expT_kernel(const float* __restrict__ S0, const double* __restrict__ dacc,
                 __nv_bfloat16* __restrict__ E, __nv_bfloat16* __restrict__ ET){
    __shared__ float sm[64][68];
    double n = (double)NELEM;
    double mu_d = dacc[0] / n;
    double var = dacc[1] / n - mu_d*mu_d;
    float inv = (float)(1.0 / (sqrt(var) + 1e-5));
    float muinv = (float)mu_d * inv;
    int tid = threadIdx.x;
    int r0 = blockIdx.y*64, c0 = blockIdx.x*64;
    #pragma unroll
    for (int i = 0; i < 4; i++){
        int lin = i*256 + tid;
        int r = lin >> 4, c4 = (lin & 15) << 2;
        float4 v = *(const float4*)(S0 + (size_t)(r0+r)*NS + c0 + c4);
        sm[r][c4+0] = fexp(fmaf(v.x, inv, -muinv));
        sm[r][c4+1] = fexp(fmaf(v.y, inv, -muinv));
        sm[r][c4+2] = fexp(fmaf(v.z, inv, -muinv));
        sm[r][c4+3] = fexp(fmaf(v.w, inv, -muinv));
    }
    __syncthreads();
    #pragma unroll
    for (int i = 0; i < 2; i++){
        int lin = i*256 + tid;
        int r = lin >> 3, g8 = (lin & 7) << 3;
        __nv_bfloat162 ob[4];
        #pragma unroll
        for (int q = 0; q < 4; q++)
            ob[q] = __floats2bfloat162_rn(sm[r][g8+2*q], sm[r][g8+2*q+1]);
        *(uint4*)(E + (size_t)(r0+r)*NS + c0 + g8) = *(uint4*)ob;
        #pragma unroll
        for (int q = 0; q < 4; q++)
            ob[q] = __floats2bfloat162_rn(sm[g8+2*q][r], sm[g8+2*q+1][r]);
        *(uint4*)(ET + (size_t)(c0+r)*NS + r0 + g8) = *(uint4*)ob;
    }
}
__global__ __launch_bounds__(256)
void sinkhorn_all(const __nv_bfloat16* __restrict__ E, const __nv_bfloat16* __restrict__ ET,
                  float* __restrict__ rv, float* __restrict__ cvv,
                  const int* __restrict__ lab, double* acc){
    int tid = threadIdx.x, wid = tid >> 5, lane = tid & 31;
    int row = blockIdx.x*8 + wid;
    int nb = gridDim.x;
    for (int pass = 0; pass < 20; pass++){
        const __nv_bfloat16* M = (pass & 1) ? ET : E;
        const float* in = (pass & 1) ? rv : cvv;
        float* out = (pass & 1) ? cvv : rv;
        float s = 0.f;
        #pragma unroll
        for (int b = 0; b < 8; b++){
            int j = (b*32 + lane)*8;
            uint4 u = *(const uint4*)(M + (size_t)row*NS + j);
            float2 e0 = __bfloat1622float2(*(__nv_bfloat162*)&u.x);
            float2 e1 = __bfloat1622float2(*(__nv_bfloat162*)&u.y);
            float2 e2 = __bfloat1622float2(*(__nv_bfloat162*)&u.z);
            float2 e3 = __bfloat1622float2(*(__nv_bfloat162*)&u.w);
            if (pass == 0){
                s += e0.x+e0.y+e1.x+e1.y+e2.x+e2.y+e3.x+e3.y;
            } else {
                float4 c0 = *(const float4*)(in + j);
                float4 c1 = *(const float4*)(in + j + 4);
                s += e0.x*c0.x + e0.y*c0.y + e1.x*c0.z + e1.y*c0.w
                   + e2.x*c1.x + e2.y*c1.y + e3.x*c1.z + e3.y*c1.w;
            }
        }
        s = wsum(s);
        if (lane == 0) out[row] = 1.0f / s;
        __threadfence();
        __syncthreads();
        if (tid == 0){
            int e = g_epoch;
            if (atomicAdd(&g_cnt, 1) == nb - 1){
                g_cnt = 0;
                __threadfence();
                g_epoch = e + 1;
            } else {
                while (g_epoch == e) { }
            }
            __threadfence();
        }
        __syncthreads();
    }
    float eri = rv[row];
    int li = lab[row];
    float s = 0.f;
    #pragma unroll
    for (int b = 0; b < 8; b++){
        int j = (b*32 + lane)*8;
        uint4 u = *(const uint4*)(E + (size_t)row*NS + j);
        float2 e0 = __bfloat1622float2(*(__nv_bfloat162*)&u.x);
        float2 e1 = __bfloat1622float2(*(__nv_bfloat162*)&u.y);
        float2 e2 = __bfloat1622float2(*(__nv_bfloat162*)&u.z);
        float2 e3 = __bfloat1622float2(*(__nv_bfloat162*)&u.w);
        float ev[8] = {e0.x,e0.y,e1.x,e1.y,e2.x,e2.y,e3.x,e3.y};
        float4 c0 = *(const float4*)(cvv + j);
        float4 c1 = *(const float4*)(cvv + j + 4);
        float cv8[8] = {c0.x,c0.y,c0.z,c0.w,c1.x,c1.y,c1.z,c1.w};
        #pragma unroll
        for (int q = 0; q < 8; q++){
            float p = ev[q] * eri * cv8[q];
            float gt = (li == lab[NS + j + q]) ? 1.f : 0.f;
            s += fabsf(p - gt);
        }
    }
    s = wsum(s);
    if (lane == 0) atomicAdd(acc + 2, (double)s);
}
__global__ __launch_bounds__(256)
void supcon_final(const float* __restrict__ es, const float* __restrict__ ps,
                  const int* __restrict__ lab, const int* __restrict__ h, double* acc){
    __shared__ float red[256];
    int i = blockIdx.x*256 + threadIdx.x;
    float cnt = (float)(h[lab[i]] - 1);
    float v = ps[i]/cnt - logf(es[i]);
    float s = bsum256(v, red);
    if (threadIdx.x == 0) atomicAdd(acc + 3, (double)s);
}
__global__ void finalize_kernel(const double* acc, float* out){
    if (threadIdx.x == 0 && blockIdx.x == 0)
        out[0] = (float)(acc[2] + 0.1 * (-(acc[3] / (double)NF)));
}

// ---------------- host ----------------
extern "C" void kernel_launch(void* const* d_in, const int* in_sizes, int n_in,
                              void* d_out, int out_size){
    const float *nodes_src=(const float*)d_in[0], *nodes_tgt=(const float*)d_in[1];
    const int *labels_src=(const int*)d_in[2], *labels_tgt=(const int*)d_in[3];
    const float *w1=(const float*)d_in[4], *b1=(const float*)d_in[5];
    const float *w2=(const float*)d_in[6], *b2=(const float*)d_in[7];
    const float *wq=(const float*)d_in[8], *wk=(const float*)d_in[9];
    const float *wv=(const float*)d_in[10], *wo=(const float*)d_in[11];
    const float *cq=(const float*)d_in[12], *ck=(const float*)d_in[13];
    const float *cv=(const float*)d_in[14], *co=(const float*)d_in[15];
    const float *Am=(const float*)d_in[16];

    __nv_bfloat16 *inb,*h1b,*x0b,*x1b,*x2b,*qb,*fnb,*qkv,*Pb,*wT;
    float *tf,*x0,*x1,*x2,*S0,*rsum,*rv,*cvv,*ep;
    double* dacc; int *lab,*hist;
    cudaGetSymbolAddress((void**)&inb,g_inb); cudaGetSymbolAddress((void**)&h1b,g_h1b);
    cudaGetSymbolAddress((void**)&x0b,g_x0b); cudaGetSymbolAddress((void**)&x1b,g_x1b);
    cudaGetSymbolAddress((void**)&x2b,g_x2b); cudaGetSymbolAddress((void**)&qb,g_qb);
    cudaGetSymbolAddress((void**)&fnb,g_fnb); cudaGetSymbolAddress((void**)&qkv,g_qkv);
    cudaGetSymbolAddress((void**)&Pb,g_Pb);   cudaGetSymbolAddress((void**)&wT,g_wT);
    cudaGetSymbolAddress((void**)&tf,g_tf);   cudaGetSymbolAddress((void**)&x0,g_x0);
    cudaGetSymbolAddress((void**)&x1,g_x1);   cudaGetSymbolAddress((void**)&x2,g_x2);
    cudaGetSymbolAddress((void**)&S0,g_S0);   cudaGetSymbolAddress((void**)&rsum,g_rsum);
    cudaGetSymbolAddress((void**)&rv,g_r);    cudaGetSymbolAddress((void**)&cvv,g_c);
    cudaGetSymbolAddress((void**)&ep,g_ep);   cudaGetSymbolAddress((void**)&dacc,g_dacc);
    cudaGetSymbolAddress((void**)&lab,g_lab); cudaGetSymbolAddress((void**)&hist,g_hist);
    float *esum = ep, *psum = ep + NF;

    const int WSZ = DD*DD;
    // wT slots: 0 w1T, 1 w2T, 2 Wqk_iT*, 3 Wvo_iT*, 4 Wqk_cT*, 5 Wco_cT*, 8 AT,
    //           9 wk, 10 woT, 11 ck, 12 coT, 13 wq/16, 14 wv, 15 cq/16, 16 cv
    __nv_bfloat16 *Eb = Pb, *EbT = Pb + NELEM;

    cudaMemsetAsync(dacc, 0, 4*sizeof(double));
    cudaMemsetAsync(hist, 0, 16*sizeof(int));
    cudaMemsetAsync(ep, 0, 2*NF*sizeof(float));
    cudaMemcpyAsync(lab, labels_src, NS*sizeof(int), cudaMemcpyDeviceToDevice);
    cudaMemcpyAsync(lab+NS, labels_tgt, NS*sizeof(int), cudaMemcpyDeviceToDevice);

    cvt_in<<<NF, 256>>>(nodes_src, nodes_tgt, inb, lab, hist);
    P17 s17;
    for (int i = 0; i < 17; i++){ s17.p[i] = nullptr; s17.tr[i] = 1; s17.sc[i] = 1.0f; }
    s17.p[0]=w1; s17.p[1]=w2; s17.p[8]=Am;
    s17.p[9]=wk;  s17.tr[9]=0;
    s17.p[10]=wo;
    s17.p[11]=ck; s17.tr[11]=0;
    s17.p[12]=co;
    s17.p[13]=wq; s17.tr[13]=0; s17.sc[13]=0.0625f;
    s17.p[14]=wv; s17.tr[14]=0;
    s17.p[15]=cq; s17.tr[15]=0; s17.sc[15]=0.0625f;
    s17.p[16]=cv; s17.tr[16]=0;
    cvtT17<<<dim3(DD, 17), 256>>>(s17, wT);

    auto TC = [&](dim3 g, const __nv_bfloat16* A, int lda, long long azs,
                  const __nv_bfloat16* B, int ldb, long long bzs, int transB,
                  int K, int ksl, int epi, float sc, int scaleN,
                  float* oF, __nv_bfloat16* oB, int ldc, long long czs, int mzoff,
                  const float* bias_, float* rsW){
        tc_nt<<<g, 256>>>(A, lda, azs, B, ldb, bzs, transB, K, ksl, epi, sc, scaleN,
                          oF, oB, ldc, czs, mzoff, bias_, rsW, dacc, lab, esum, psum);
    };

    // weight products, z=4:
    //  z0: wk @ (wq/16)^T = Wqk_i^T → slot2 ;  z1: woT @ wv^T = Wvo_i^T → slot3
    //  z2: ck @ (cq/16)^T = Wqk_c^T → slot4 ;  z3: coT @ cv^T = Wco_c^T → slot5
    TC(dim3(2,2,4), wT+9*WSZ,256,WSZ, wT+13*WSZ,256,WSZ,0, 256,1, 0, 1.f,0,
       nullptr, wT+2*WSZ, 256, (long long)WSZ, 0, nullptr,nullptr);

    // head_in
    TC(dim3(2,32,1), inb,256,0, wT,256,0,0, 256,1, 1, 1.f,0, tf, nullptr, 256,0,0, b1, nullptr);
    ln_fast<<<NF/8,256>>>(tf, nullptr, h1b, 1);
    TC(dim3(2,32,1), h1b,256,0, wT+WSZ,256,0,0, 256,1, 1, 1.f,0, tf, nullptr, 256,0,0, b2, nullptr);
    ln_fast<<<NF/8,256>>>(tf, x0, x0b, 0);

    // ---- intra attention:  [y|vw] = x0 @ [Wqk_i | Wvo_i];  S = y @ x0^T ----
    TC(dim3(4,32,1), x0b,256,0, wT+2*WSZ,256,0,0, 256,1, 0, 1.f,0, nullptr, qkv, 512,0,0, nullptr,nullptr);
    cudaMemsetAsync(rsum, 0, NF*sizeof(float));
    TC(dim3(16,16,2), qkv,512,LL2, x0b,256,HALF,0, 256,1, 3, 1.f,0, nullptr, Pb, NS, NELEM, NS, nullptr, rsum);
    TC(dim3(2,16,8), Pb,NS,NELEM, qkv+256,512,LL2,1, NS,4, 4, 1.f,0, S0, nullptr, 256,0, NS, nullptr,nullptr);
    pv_fin<<<NF/8,256>>>(S0, rsum, x0, x1, x1b);

    // ---- cross attention ----
    TC(dim3(4,32,1), x1b,256,0, wT+4*WSZ,256,0,0, 256,1, 0, 1.f,0, nullptr, qkv, 512,0,0, nullptr,nullptr);
    cudaMemsetAsync(rsum, 0, NF*sizeof(float));
    TC(dim3(16,16,2), qkv,512,LL2, x1b+HALF,256,-HALF,0, 256,1, 3, 1.f,0, nullptr, Pb, NS, NELEM, NS, nullptr, rsum);
    TC(dim3(2,16,8), Pb,NS,NELEM, qkv+256+LL2,512,-LL2,1, NS,4, 4, 1.f,0, S0, nullptr, 256,0, NS, nullptr,nullptr);
    pv_fin<<<NF/8,256>>>(S0, rsum, x1, x2, x2b);

    // ---- affinity + stats ----
    TC(dim3(2,16,1), x2b,256,0, wT+8*WSZ,256,0,0, 256,1, 0, 1.f,0, nullptr, qb, 256,0,0, nullptr,nullptr);
    TC(dim3(16,16,1), qb,256,0, x2b+HALF,256,0,0, 256,1, 5, 1.f,0, S0, nullptr, NS,0,0, nullptr,nullptr);

    // E + transpose, persistent Sinkhorn + match
    expT_kernel<<<dim3(32,32),256>>>(S0, dacc, Eb, EbT);
    sinkhorn_all<<<256,256>>>(Eb, EbT, rv, cvv, lab, dacc);

    // SupCon (triangular)
    fnorm_fast<<<NF/8,256>>>(x2, fnb);
    TC(dim3(32,32,1), fnb,256,0, fnb,256,0,0, 256,1, 6, SUPCON_SCALE,0, nullptr, nullptr, 0,0,0, nullptr,nullptr);
    supcon_final<<<NF/256,256>>>(esum, psum, lab, hist, dacc);

    finalize_kernel<<<1,32>>>(dacc, (float*)d_out);
}

// round 11
// speedup vs baseline: 5.7675x; 1.0644x over previous
#include <cuda_runtime.h>
#include <cuda_bf16.h>
#include <math.h>
#include <stdint.h>

#define NS 2048
#define DD 256
#define NF 4096
#define HALF ((long long)NS*DD)
#define LL2  ((long long)NS*512)
#define NELEM ((long long)NS*NS)
#define NFDD ((long long)NF*DD)
#define SUPCON_SCALE 14.285714285714286f

// ---------------- persistent streams/events (host objects, created at load) ----
struct StreamInit {
    cudaStream_t s;
    cudaEvent_t ev[4];
    StreamInit(){
        cudaStreamCreateWithFlags(&s, cudaStreamNonBlocking);
        for (int i = 0; i < 4; i++) cudaEventCreateWithFlags(&ev[i], cudaEventDisableTiming);
    }
};
static StreamInit g_si;

// ---------------- helpers ----------------
__device__ __forceinline__ uint32_t smem_to_u32(const void* p){
    uint32_t a;
    asm("{ .reg .u64 t; cvta.to.shared.u64 t, %1; cvt.u32.u64 %0, t; }" : "=r"(a) : "l"(p));
    return a;
}
__device__ __forceinline__ void cp16(void* s, const void* g){
    uint32_t sa = smem_to_u32(s);
    asm volatile("cp.async.ca.shared.global [%0], [%1], 16;" :: "r"(sa), "l"(g) : "memory");
}
__device__ __forceinline__ void ldsm_x4(uint32_t* r, uint32_t addr){
    asm volatile("ldmatrix.sync.aligned.m8n8.x4.shared.b16 {%0,%1,%2,%3}, [%4];"
        : "=r"(r[0]), "=r"(r[1]), "=r"(r[2]), "=r"(r[3]) : "r"(addr));
}
__device__ __forceinline__ void ldsm_x2(uint32_t* r, uint32_t addr){
    asm volatile("ldmatrix.sync.aligned.m8n8.x2.shared.b16 {%0,%1}, [%2];"
        : "=r"(r[0]), "=r"(r[1]) : "r"(addr));
}
__device__ __forceinline__ void ldsm_x2t(uint32_t* r, uint32_t addr){
    asm volatile("ldmatrix.sync.aligned.m8n8.x2.trans.shared.b16 {%0,%1}, [%2];"
        : "=r"(r[0]), "=r"(r[1]) : "r"(addr));
}
__device__ __forceinline__ void mma16816(float* c, const uint32_t* a, const uint32_t* b){
    asm volatile("mma.sync.aligned.m16n8k16.row.col.f32.bf16.bf16.f32 "
        "{%0,%1,%2,%3}, {%4,%5,%6,%7}, {%8,%9}, {%0,%1,%2,%3};"
        : "+f"(c[0]), "+f"(c[1]), "+f"(c[2]), "+f"(c[3])
        : "r"(a[0]), "r"(a[1]), "r"(a[2]), "r"(a[3]), "r"(b[0]), "r"(b[1]));
}
__device__ __forceinline__ float fexp(float x){
    float t = x * 1.4426950408889634f;
    float r = rintf(t);
    float f = t - r;
    float p =            1.3333558146e-3f;
    p = fmaf(p, f, 9.6181291076e-3f);
    p = fmaf(p, f, 5.5504108664e-2f);
    p = fmaf(p, f, 2.4022650696e-1f);
    p = fmaf(p, f, 6.9314718056e-1f);
    p = fmaf(p, f, 1.0f);
    float res = __int_as_float(__float_as_int(p) + (((int)r) << 23));
    return (x < -87.0f) ? 0.0f : res;
}
__device__ __forceinline__ float bsum256(float v, float* red){
    int tid = threadIdx.x;
    red[tid] = v; __syncthreads();
    #pragma unroll
    for (int o = 128; o > 0; o >>= 1){
        if (tid < o) red[tid] += red[tid + o];
        __syncthreads();
    }
    float r = red[0]; __syncthreads();
    return r;
}
__device__ __forceinline__ float wsum(float v){
    #pragma unroll
    for (int o = 16; o > 0; o >>= 1) v += __shfl_xor_sync(0xffffffffu, v, o);
    return v;
}

// ---------------- scratch ----------------
__device__ __nv_bfloat16 g_inb[NF*DD], g_h1b[NF*DD], g_x0b[NF*DD], g_x1b[NF*DD], g_x2b[NF*DD];
__device__ __nv_bfloat16 g_qb[NF*DD], g_fnb[NF*DD];
__device__ __nv_bfloat16 g_qkv[(long long)NF*512];
__device__ __nv_bfloat16 g_Pb[2*NELEM];
__device__ __nv_bfloat16 g_wT[17*DD*DD];
__device__ float g_tf[NF*DD], g_x0[NF*DD], g_x1[NF*DD], g_x2[NF*DD];
__device__ float g_S0[NELEM];
__device__ float g_rsum[2*NF], g_r[NS], g_c[NS], g_ep[2*NF];
__device__ double g_dacc[4];
__device__ int g_lab[NF], g_hist[16];
__device__ int g_cnt;
__device__ volatile int g_epoch;

// ============================================================================
// Generic bf16 HMMA NT/NN GEMM, 128x128 tile, 8 warps (2x4), 64x32 warp tiles.
// Double-buffered smem with cp.async prefetch.
// epi: 0 bf16 | 1 f32+bias | 3 exp+rowsum+bf16 | 4 split-K f32 slice
//      5 f32+stats | 6 supcon triangular row+col
// ============================================================================
__global__ __launch_bounds__(256)
void tc_nt(const __nv_bfloat16* A, int lda, long long azs,
           const __nv_bfloat16* B, int ldb, long long bzs, int transB,
           int K, int ksl, int epi, float scale, int scaleN,
           float* outF, __nv_bfloat16* outB, int ldc, long long czs, int mzoff,
           const float* bias, float* rsumW, double* dacc,
           const int* lab, float* esum, float* psum)
{
    if (epi == 6 && blockIdx.x < blockIdx.y) return;
    __shared__ __nv_bfloat16 SA[2][128*72];
    __shared__ __nv_bfloat16 SB[2][128*72];
    __shared__ float red[256];

    int z = blockIdx.z;
    int dom = z / ksl, kk = z - dom*ksl;
    A += (long long)dom * azs;
    B += (long long)dom * bzs;
    if (outB) outB += (long long)dom * czs;

    int tid = threadIdx.x, wid = tid >> 5, lane = tid & 31;
    int wr = wid >> 2, wc = wid & 3;
    int row0 = blockIdx.y * 128, col0 = blockIdx.x * 128;

    float acc[4][4][4];
    #pragma unroll
    for (int mi = 0; mi < 4; mi++)
        #pragma unroll
        for (int ni = 0; ni < 4; ni++)
            #pragma unroll
            for (int q = 0; q < 4; q++) acc[mi][ni][q] = 0.f;

    int aRow  = wr*64 + (lane & 7) + ((lane >> 3) & 1)*8;
    int aKoff = (lane >> 4)*8;
    int l16   = lane & 15;
    int bRow  = wc*32 + (l16 & 7);
    int bKoff = (l16 >> 3)*8;

    int nch = K >> 6;
    int c0ch = kk * nch / ksl, c1ch = (kk+1) * nch / ksl;

    auto load_chunk = [&](int c, int buf){
        int kc = c << 6;
        #pragma unroll
        for (int i = 0; i < 4; i++){
            int lin = i*256 + tid;
            int r = lin >> 3, c8 = (lin & 7) << 3;
            cp16(&SA[buf][r*72 + c8], A + (size_t)(row0+r)*lda + kc + c8);
        }
        if (!transB){
            #pragma unroll
            for (int i = 0; i < 4; i++){
                int lin = i*256 + tid;
                int r = lin >> 3, c8 = (lin & 7) << 3;
                cp16(&SB[buf][r*72 + c8], B + (size_t)(col0+r)*ldb + kc + c8);
            }
        } else {
            #pragma unroll
            for (int i = 0; i < 4; i++){
                int lin = i*256 + tid;
                int r = lin >> 4, c8 = (lin & 15) << 3;
                cp16(&SB[buf][r*136 + c8], B + (size_t)(kc+r)*ldb + col0 + c8);
            }
        }
    };

    load_chunk(c0ch, 0);
    asm volatile("cp.async.commit_group;" ::: "memory");
    asm volatile("cp.async.wait_group 0;" ::: "memory");
    __syncthreads();

    for (int c = c0ch; c < c1ch; c++){
        int buf = (c - c0ch) & 1;
        if (c + 1 < c1ch){
            load_chunk(c+1, buf^1);
            asm volatile("cp.async.commit_group;" ::: "memory");
        }
        uint32_t sAb = smem_to_u32(SA[buf]);
        uint32_t sBb = smem_to_u32(SB[buf]);
        #pragma unroll
        for (int ks = 0; ks < 4; ks++){
            uint32_t af[4][4], bf[4][2];
            #pragma unroll
            for (int mi = 0; mi < 4; mi++)
                ldsm_x4(af[mi], sAb + (uint32_t)(((aRow + mi*16)*72 + ks*16 + aKoff) * 2));
            if (!transB){
                #pragma unroll
                for (int ni = 0; ni < 4; ni++)
                    ldsm_x2(bf[ni], sBb + (uint32_t)(((bRow + ni*8)*72 + ks*16 + bKoff) * 2));
            } else {
                #pragma unroll
                for (int ni = 0; ni < 4; ni++)
                    ldsm_x2t(bf[ni], sBb + (uint32_t)(((ks*16 + l16)*136 + wc*32 + ni*8) * 2));
            }
            #pragma unroll
            for (int mi = 0; mi < 4; mi++)
                #pragma unroll
                for (int ni = 0; ni < 4; ni++)
                    mma16816(acc[mi][ni], af[mi], bf[ni]);
        }
        if (c + 1 < c1ch)
            asm volatile("cp.async.wait_group 0;" ::: "memory");
        __syncthreads();
    }

    int lr = lane >> 2, lc2 = (lane & 3) << 1;
    int colB = col0 + wc*32;
    float s1 = 0.f, s2 = 0.f;
    bool diag = (blockIdx.x == blockIdx.y);
    float colE[8], colS[8];
    #pragma unroll
    for (int q = 0; q < 8; q++){ colE[q] = 0.f; colS[q] = 0.f; }
    int labc[8];
    if (epi == 6){
        #pragma unroll
        for (int ni = 0; ni < 4; ni++){
            labc[ni*2]   = lab[colB + ni*8 + lc2];
            labc[ni*2+1] = lab[colB + ni*8 + lc2 + 1];
        }
    }

    #pragma unroll
    for (int mi = 0; mi < 4; mi++){
        #pragma unroll
        for (int h = 0; h < 2; h++){
            int r = row0 + wr*64 + mi*16 + lr + h*8;
            if (epi == 0){
                #pragma unroll
                for (int ni = 0; ni < 4; ni++){
                    int cc = colB + ni*8 + lc2;
                    float m0 = (cc   < scaleN) ? scale : 1.0f;
                    float m1 = (cc+1 < scaleN) ? scale : 1.0f;
                    float v0 = acc[mi][ni][h*2+0]*m0, v1 = acc[mi][ni][h*2+1]*m1;
                    *(__nv_bfloat162*)(outB + (size_t)r*ldc + cc) = __floats2bfloat162_rn(v0, v1);
                }
            } else if (epi == 1){
                #pragma unroll
                for (int ni = 0; ni < 4; ni++){
                    int cc = colB + ni*8 + lc2;
                    float2 o = make_float2(acc[mi][ni][h*2+0] + bias[cc],
                                           acc[mi][ni][h*2+1] + bias[cc+1]);
                    *(float2*)(outF + (size_t)r*ldc + cc) = o;
                }
            } else if (epi == 3){
                float part = 0.f;
                #pragma unroll
                for (int ni = 0; ni < 4; ni++){
                    int cc = colB + ni*8 + lc2;
                    float e0 = fexp(acc[mi][ni][h*2+0]), e1 = fexp(acc[mi][ni][h*2+1]);
                    part += e0 + e1;
                    *(__nv_bfloat162*)(outB + (size_t)r*ldc + cc) = __floats2bfloat162_rn(e0, e1);
                }
                part += __shfl_xor_sync(0xffffffffu, part, 1);
                part += __shfl_xor_sync(0xffffffffu, part, 2);
                if ((lane & 3) == 0) atomicAdd(&rsumW[dom*mzoff + r], part);
            } else if (epi == 4){
                int mg = dom*mzoff + r;
                #pragma unroll
                for (int ni = 0; ni < 4; ni++){
                    int cc = colB + ni*8 + lc2;
                    *(float2*)(outF + (long long)kk*NFDD + (size_t)mg*ldc + cc) =
                        make_float2(acc[mi][ni][h*2+0], acc[mi][ni][h*2+1]);
                }
            } else if (epi == 5){
                #pragma unroll
                for (int ni = 0; ni < 4; ni++){
                    int cc = colB + ni*8 + lc2;
                    float v0 = acc[mi][ni][h*2+0], v1 = acc[mi][ni][h*2+1];
                    *(float2*)(outF + (size_t)r*ldc + cc) = make_float2(v0, v1);
                    s1 += v0 + v1; s2 += v0*v0 + v1*v1;
                }
            } else {
                int rlab = lab[r];
                float pe = 0.f, ps = 0.f;
                #pragma unroll
                for (int ni = 0; ni < 4; ni++){
                    int cc = colB + ni*8 + lc2;
                    float l0 = acc[mi][ni][h*2+0]*scale, l1 = acc[mi][ni][h*2+1]*scale;
                    bool m0 = (labc[ni*2]   == rlab);
                    bool m1 = (labc[ni*2+1] == rlab);
                    if (cc != r){
                        float e = fexp(l0);
                        pe += e; if (m0) ps += l0;
                        if (!diag){ colE[ni*2] += e; if (m0) colS[ni*2] += l0; }
                    }
                    if (cc+1 != r){
                        float e = fexp(l1);
                        pe += e; if (m1) ps += l1;
                        if (!diag){ colE[ni*2+1] += e; if (m1) colS[ni*2+1] += l1; }
                    }
                }
                pe += __shfl_xor_sync(0xffffffffu, pe, 1);
                pe += __shfl_xor_sync(0xffffffffu, pe, 2);
                ps += __shfl_xor_sync(0xffffffffu, ps, 1);
                ps += __shfl_xor_sync(0xffffffffu, ps, 2);
                if ((lane & 3) == 0){
                    atomicAdd(&esum[r], pe);
                    atomicAdd(&psum[r], ps);
                }
            }
        }
    }
    if (epi == 6 && !diag){
        #pragma unroll
        for (int q = 0; q < 8; q++){
            #pragma unroll
            for (int o = 4; o <= 16; o <<= 1){
                colE[q] += __shfl_xor_sync(0xffffffffu, colE[q], o);
                colS[q] += __shfl_xor_sync(0xffffffffu, colS[q], o);
            }
        }
        if (lane < 4){
            #pragma unroll
            for (int ni = 0; ni < 4; ni++){
                int cc = col0 + wc*32 + ni*8 + lane*2;
                atomicAdd(&esum[cc],   colE[ni*2]);
                atomicAdd(&psum[cc],   colS[ni*2]);
                atomicAdd(&esum[cc+1], colE[ni*2+1]);
                atomicAdd(&psum[cc+1], colS[ni*2+1]);
            }
        }
    }
    if (epi == 5){
        float bs = bsum256(s1, red), bss = bsum256(s2, red);
        if (tid == 0){ atomicAdd(dacc, (double)bs); atomicAdd(dacc+1, (double)bss); }
    }
}

// ---------------- small kernels ----------------
__global__ __launch_bounds__(256)
void cvt_in(const float* __restrict__ a, const float* __restrict__ b,
            __nv_bfloat16* __restrict__ o, const int* __restrict__ lab, int* hist){
    int i = blockIdx.x, t = threadIdx.x;
    const float* src = (i < NS) ? a + (size_t)i*DD : b + (size_t)(i-NS)*DD;
    o[(size_t)i*DD + t] = __float2bfloat16(src[t]);
    if (t == 0) atomicAdd(&hist[lab[i]], 1);
}
struct P17 { const float* p[17]; int tr[17]; float sc[17]; };
__global__ __launch_bounds__(256)
void cvtT17(P17 s, __nv_bfloat16* __restrict__ o){
    int w = blockIdx.y, n = blockIdx.x, k = threadIdx.x;
    const float* src = s.p[w];
    if (!src) return;
    float v = s.tr[w] ? src[(size_t)k*DD + n] : src[(size_t)n*DD + k];
    o[(size_t)w*DD*DD + (size_t)n*DD + k] = __float2bfloat16(v * s.sc[w]);
}
__global__ __launch_bounds__(256)
void ln_fast(const float* __restrict__ X, float* __restrict__ outF,
             __nv_bfloat16* __restrict__ outB, int relu){
    int wid = threadIdx.x >> 5, lane = threadIdx.x & 31;
    int i = blockIdx.x*8 + wid;
    const float* xp = X + (size_t)i*DD + lane*8;
    float4 a = *(const float4*)xp;
    float4 b = *(const float4*)(xp + 4);
    float s  = a.x+a.y+a.z+a.w + b.x+b.y+b.z+b.w;
    float ss = a.x*a.x+a.y*a.y+a.z*a.z+a.w*a.w + b.x*b.x+b.y*b.y+b.z*b.z+b.w*b.w;
    s = wsum(s); ss = wsum(ss);
    float m = s*(1.f/DD);
    float k = rsqrtf(ss*(1.f/DD) - m*m + 1e-5f);
    float v[8] = {a.x,a.y,a.z,a.w,b.x,b.y,b.z,b.w};
    __nv_bfloat162 ob[4];
    #pragma unroll
    for (int q = 0; q < 4; q++){
        float o0 = (v[2*q]   - m)*k;
        float o1 = (v[2*q+1] - m)*k;
        if (relu){ o0 = fmaxf(o0, 0.f); o1 = fmaxf(o1, 0.f); }
        if (outF) *(float2*)(outF + (size_t)i*DD + lane*8 + 2*q) = make_float2(o0, o1);
        ob[q] = __floats2bfloat162_rn(o0, o1);
    }
    *(uint4*)(outB + (size_t)i*DD + lane*8) = *(uint4*)ob;
}
__global__ __launch_bounds__(256)
void fnorm_fast(const float* __restrict__ X, __nv_bfloat16* __restrict__ F){
    int wid = threadIdx.x >> 5, lane = threadIdx.x & 31;
    int i = blockIdx.x*8 + wid;
    const float* xp = X + (size_t)i*DD + lane*8;
    float4 a = *(const float4*)xp;
    float4 b = *(const float4*)(xp + 4);
    float ss = a.x*a.x+a.y*a.y+a.z*a.z+a.w*a.w + b.x*b.x+b.y*b.y+b.z*b.z+b.w*b.w;
    ss = wsum(ss);
    float k = 1.0f / (sqrtf(ss) + 1e-8f);
    float v[8] = {a.x,a.y,a.z,a.w,b.x,b.y,b.z,b.w};
    __nv_bfloat162 ob[4];
    #pragma unroll
    for (int q = 0; q < 4; q++)
        ob[q] = __floats2bfloat162_rn(v[2*q]*k, v[2*q+1]*k);
    *(uint4*)(F + (size_t)i*DD + lane*8) = *(uint4*)ob;
}
__global__ __launch_bounds__(256)
void pv_fin(const float* __restrict__ acc4, const float* __restrict__ rsum,
            const float* __restrict__ res, float* __restrict__ outF,
            __nv_bfloat16* __restrict__ outB){
    int wid = threadIdx.x >> 5, lane = threadIdx.x & 31;
    int i = blockIdx.x*8 + wid;
    float rinv = 1.0f / rsum[i];
    size_t off = (size_t)i*DD + lane*8;
    float v[8];
    #pragma unroll
    for (int q = 0; q < 8; q++) v[q] = 0.f;
    #pragma unroll
    for (int sl = 0; sl < 4; sl++){
        const float* p = acc4 + (long long)sl*NFDD + off;
        float4 a = *(const float4*)p;
        float4 b = *(const float4*)(p + 4);
        v[0]+=a.x; v[1]+=a.y; v[2]+=a.z; v[3]+=a.w;
        v[4]+=b.x; v[5]+=b.y; v[6]+=b.z; v[7]+=b.w;
    }
    const float* rp = res + off;
    float4 ra = *(const float4*)rp;
    float4 rb = *(const float4*)(rp + 4);
    float rr[8] = {ra.x,ra.y,ra.z,ra.w,rb.x,rb.y,rb.z,rb.w};
    __nv_bfloat162 ob[4];
    #pragma unroll
    for (int q = 0; q < 4; q++){
        float o0 = fmaf(v[2*q],   rinv, rr[2*q]);
        float o1 = fmaf(v[2*q+1], rinv, rr[2*q+1]);
        *(float2*)(outF + off + 2*q) = make_float2(o0, o1);
        ob[q] = __floats2bfloat162_rn(o0, o1);
    }
    *(uint4*)(outB + off) = *(uint4*)ob;
}
__global__ __launch_bounds__(256)
void expT_kernel(const float* __restrict__ S0, const double* __restrict__ dacc,
                 __nv_bfloat16* __restrict__ E, __nv_bfloat16* __restrict__ ET){
    __shared__ float sm[64][68];
    double n = (double)NELEM;
    double mu_d = dacc[0] / n;
    double var = dacc[1] / n - mu_d*mu_d;
    float inv = (float)(1.0 / (sqrt(var) + 1e-5));
    float muinv = (float)mu_d * inv;
    int tid = threadIdx.x;
    int r0 = blockIdx.y*64, c0 = blockIdx.x*64;
    #pragma unroll
    for (int i = 0; i < 4; i++){
        int lin = i*256 + tid;
        int r = lin >> 4, c4 = (lin & 15) << 2;
        float4 v = *(const float4*)(S0 + (size_t)(r0+r)*NS + c0 + c4);
        sm[r][c4+0] = fexp(fmaf(v.x, inv, -muinv));
        sm[r][c4+1] = fexp(fmaf(v.y, inv, -muinv));
        sm[r][c4+2] = fexp(fmaf(v.z, inv, -muinv));
        sm[r][c4+3] = fexp(fmaf(v.w, inv, -muinv));
    }
    __syncthreads();
    #pragma unroll
    for (int i = 0; i < 2; i++){
        int lin = i*256 + tid;
        int r = lin >> 3, g8 = (lin & 7) << 3;
        __nv_bfloat162 ob[4];
        #pragma unroll
        for (int q = 0; q < 4; q++)
            ob[q] = __floats2bfloat162_rn(sm[r][g8+2*q], sm[r][g8+2*q+1]);
        *(uint4*)(E + (size_t)(r0+r)*NS + c0 + g8) = *(uint4*)ob;
        #pragma unroll
        for (int q = 0; q < 4; q++)
            ob[q] = __floats2bfloat162_rn(sm[g8+2*q][r], sm[g8+2*q+1][r]);
        *(uint4*)(ET + (size_t)(c0+r)*NS + r0 + g8) = *(uint4*)ob;
    }
}
__global__ __launch_bounds__(256)
void sinkhorn_all(const __nv_bfloat16* __restrict__ E, const __nv_bfloat16* __restrict__ ET,
                  float* __restrict__ rv, float* __restrict__ cvv,
                  const int* __restrict__ lab, double* acc){
    int tid = threadIdx.x, wid = tid >> 5, lane = tid & 31;
    int row = blockIdx.x*8 + wid;
    int nb = gridDim.x;
    for (int pass = 0; pass < 20; pass++){
        const __nv_bfloat16* M = (pass & 1) ? ET : E;
        const float* in = (pass & 1) ? rv : cvv;
        float* out = (pass & 1) ? cvv : rv;
        float s = 0.f;
        #pragma unroll
        for (int b = 0; b < 8; b++){
            int j = (b*32 + lane)*8;
            uint4 u = *(const uint4*)(M + (size_t)row*NS + j);
            float2 e0 = __bfloat1622float2(*(__nv_bfloat162*)&u.x);
            float2 e1 = __bfloat1622float2(*(__nv_bfloat162*)&u.y);
            float2 e2 = __bfloat1622float2(*(__nv_bfloat162*)&u.z);
            float2 e3 = __bfloat1622float2(*(__nv_bfloat162*)&u.w);
            if (pass == 0){
                s += e0.x+e0.y+e1.x+e1.y+e2.x+e2.y+e3.x+e3.y;
            } else {
                float4 c0 = *(const float4*)(in + j);
                float4 c1 = *(const float4*)(in + j + 4);
                s += e0.x*c0.x + e0.y*c0.y + e1.x*c0.z + e1.y*c0.w
                   + e2.x*c1.x + e2.y*c1.y + e3.x*c1.z + e3.y*c1.w;
            }
        }
        s = wsum(s);
        if (lane == 0) out[row] = 1.0f / s;
        __threadfence();
        __syncthreads();
        if (tid == 0){
            int e = g_epoch;
            if (atomicAdd(&g_cnt, 1) == nb - 1){
                g_cnt = 0;
                __threadfence();
                g_epoch = e + 1;
            } else {
                while (g_epoch == e) { }
            }
            __threadfence();
        }
        __syncthreads();
    }
    float eri = rv[row];
    int li = lab[row];
    float s = 0.f;
    #pragma unroll
    for (int b = 0; b < 8; b++){
        int j = (b*32 + lane)*8;
        uint4 u = *(const uint4*)(E + (size_t)row*NS + j);
        float2 e0 = __bfloat1622float2(*(__nv_bfloat162*)&u.x);
        float2 e1 = __bfloat1622float2(*(__nv_bfloat162*)&u.y);
        float2 e2 = __bfloat1622float2(*(__nv_bfloat162*)&u.z);
        float2 e3 = __bfloat1622float2(*(__nv_bfloat162*)&u.w);
        float ev[8] = {e0.x,e0.y,e1.x,e1.y,e2.x,e2.y,e3.x,e3.y};
        float4 c0 = *(const float4*)(cvv + j);
        float4 c1 = *(const float4*)(cvv + j + 4);
        float cv8[8] = {c0.x,c0.y,c0.z,c0.w,c1.x,c1.y,c1.z,c1.w};
        #pragma unroll
        for (int q = 0; q < 8; q++){
            float p = ev[q] * eri * cv8[q];
            float gt = (li == lab[NS + j + q]) ? 1.f : 0.f;
            s += fabsf(p - gt);
        }
    }
    s = wsum(s);
    if (lane == 0) atomicAdd(acc + 2, (double)s);
}
__global__ __launch_bounds__(256)
void supcon_final(const float* __restrict__ es, const float* __restrict__ ps,
                  const int* __restrict__ lab, const int* __restrict__ h, double* acc){
    __shared__ float red[256];
    int i = blockIdx.x*256 + threadIdx.x;
    float cnt = (float)(h[lab[i]] - 1);
    float v = ps[i]/cnt - logf(es[i]);
    float s = bsum256(v, red);
    if (threadIdx.x == 0) atomicAdd(acc + 3, (double)s);
}
__global__ void finalize_kernel(const double* acc, float* out){
    if (threadIdx.x == 0 && blockIdx.x == 0)
        out[0] = (float)(acc[2] + 0.1 * (-(acc[3] / (double)NF)));
}

// ---------------- host ----------------
extern "C" void kernel_launch(void* const* d_in, const int* in_sizes, int n_in,
                              void* d_out, int out_size){
    const float *nodes_src=(const float*)d_in[0], *nodes_tgt=(const float*)d_in[1];
    const int *labels_src=(const int*)d_in[2], *labels_tgt=(const int*)d_in[3];
    const float *w1=(const float*)d_in[4], *b1=(const float*)d_in[5];
    const float *w2=(const float*)d_in[6], *b2=(const float*)d_in[7];
    const float *wq=(const float*)d_in[8], *wk=(const float*)d_in[9];
    const float *wv=(const float*)d_in[10], *wo=(const float*)d_in[11];
    const float *cq=(const float*)d_in[12], *ck=(const float*)d_in[13];
    const float *cv=(const float*)d_in[14], *co=(const float*)d_in[15];
    const float *Am=(const float*)d_in[16];

    __nv_bfloat16 *inb,*h1b,*x0b,*x1b,*x2b,*qb,*fnb,*qkv,*Pb,*wT;
    float *tf,*x0,*x1,*x2,*S0,*rsum,*rv,*cvv,*ep;
    double* dacc; int *lab,*hist;
    cudaGetSymbolAddress((void**)&inb,g_inb); cudaGetSymbolAddress((void**)&h1b,g_h1b);
    cudaGetSymbolAddress((void**)&x0b,g_x0b); cudaGetSymbolAddress((void**)&x1b,g_x1b);
    cudaGetSymbolAddress((void**)&x2b,g_x2b); cudaGetSymbolAddress((void**)&qb,g_qb);
    cudaGetSymbolAddress((void**)&fnb,g_fnb); cudaGetSymbolAddress((void**)&qkv,g_qkv);
    cudaGetSymbolAddress((void**)&Pb,g_Pb);   cudaGetSymbolAddress((void**)&wT,g_wT);
    cudaGetSymbolAddress((void**)&tf,g_tf);   cudaGetSymbolAddress((void**)&x0,g_x0);
    cudaGetSymbolAddress((void**)&x1,g_x1);   cudaGetSymbolAddress((void**)&x2,g_x2);
    cudaGetSymbolAddress((void**)&S0,g_S0);   cudaGetSymbolAddress((void**)&rsum,g_rsum);
    cudaGetSymbolAddress((void**)&rv,g_r);    cudaGetSymbolAddress((void**)&cvv,g_c);
    cudaGetSymbolAddress((void**)&ep,g_ep);   cudaGetSymbolAddress((void**)&dacc,g_dacc);
    cudaGetSymbolAddress((void**)&lab,g_lab); cudaGetSymbolAddress((void**)&hist,g_hist);
    float *esum = ep, *psum = ep + NF;
    float *rsum2 = rsum + NF;

    const int WSZ = DD*DD;
    __nv_bfloat16 *Eb = Pb, *EbT = Pb + NELEM;
    cudaStream_t sB = g_si.s;

    cudaMemsetAsync(dacc, 0, 4*sizeof(double));
    cudaMemsetAsync(hist, 0, 16*sizeof(int));
    cudaMemsetAsync(ep, 0, 2*NF*sizeof(float));
    cudaMemsetAsync(rsum, 0, 2*NF*sizeof(float));
    cudaMemcpyAsync(lab, labels_src, NS*sizeof(int), cudaMemcpyDeviceToDevice);
    cudaMemcpyAsync(lab+NS, labels_tgt, NS*sizeof(int), cudaMemcpyDeviceToDevice);

    cvt_in<<<NF, 256>>>(nodes_src, nodes_tgt, inb, lab, hist);
    P17 s17;
    for (int i = 0; i < 17; i++){ s17.p[i] = nullptr; s17.tr[i] = 1; s17.sc[i] = 1.0f; }
    s17.p[0]=w1; s17.p[1]=w2; s17.p[8]=Am;
    s17.p[9]=wk;  s17.tr[9]=0;
    s17.p[10]=wo;
    s17.p[11]=ck; s17.tr[11]=0;
    s17.p[12]=co;
    s17.p[13]=wq; s17.tr[13]=0; s17.sc[13]=0.0625f;
    s17.p[14]=wv; s17.tr[14]=0;
    s17.p[15]=cq; s17.tr[15]=0; s17.sc[15]=0.0625f;
    s17.p[16]=cv; s17.tr[16]=0;
    cvtT17<<<dim3(DD, 17), 256>>>(s17, wT);

    auto TC = [&](cudaStream_t st, dim3 g, const __nv_bfloat16* A, int lda, long long azs,
                  const __nv_bfloat16* B, int ldb, long long bzs, int transB,
                  int K, int ksl, int epi, float sc, int scaleN,
                  float* oF, __nv_bfloat16* oB, int ldc, long long czs, int mzoff,
                  const float* bias_, float* rsW){
        tc_nt<<<g, 256, 0, st>>>(A, lda, azs, B, ldb, bzs, transB, K, ksl, epi, sc, scaleN,
                                 oF, oB, ldc, czs, mzoff, bias_, rsW, dacc, lab, esum, psum);
    };

    // ---- fork 1: weight products on sB, concurrent with head chain ----
    cudaEventRecord(g_si.ev[0], 0);
    cudaStreamWaitEvent(sB, g_si.ev[0], 0);
    TC(sB, dim3(2,2,4), wT+9*WSZ,256,WSZ, wT+13*WSZ,256,WSZ,0, 256,1, 0, 1.f,0,
       nullptr, wT+2*WSZ, 256, (long long)WSZ, 0, nullptr,nullptr);
    cudaEventRecord(g_si.ev[1], sB);

    // head_in (stream 0)
    TC(0, dim3(2,32,1), inb,256,0, wT,256,0,0, 256,1, 1, 1.f,0, tf, nullptr, 256,0,0, b1, nullptr);
    ln_fast<<<NF/8,256>>>(tf, nullptr, h1b, 1);
    TC(0, dim3(2,32,1), h1b,256,0, wT+WSZ,256,0,0, 256,1, 1, 1.f,0, tf, nullptr, 256,0,0, b2, nullptr);
    ln_fast<<<NF/8,256>>>(tf, x0, x0b, 0);
    cudaStreamWaitEvent(0, g_si.ev[1], 0);   // join: products ready

    // ---- intra attention ----
    TC(0, dim3(4,32,1), x0b,256,0, wT+2*WSZ,256,0,0, 256,1, 0, 1.f,0, nullptr, qkv, 512,0,0, nullptr,nullptr);
    TC(0, dim3(16,16,2), qkv,512,LL2, x0b,256,HALF,0, 256,1, 3, 1.f,0, nullptr, Pb, NS, NELEM, NS, nullptr, rsum);
    TC(0, dim3(2,16,8), Pb,NS,NELEM, qkv+256,512,LL2,1, NS,4, 4, 1.f,0, S0, nullptr, 256,0, NS, nullptr,nullptr);
    pv_fin<<<NF/8,256>>>(S0, rsum, x0, x1, x1b);

    // ---- cross attention ----
    TC(0, dim3(4,32,1), x1b,256,0, wT+4*WSZ,256,0,0, 256,1, 0, 1.f,0, nullptr, qkv, 512,0,0, nullptr,nullptr);
    TC(0, dim3(16,16,2), qkv,512,LL2, x1b+HALF,256,-HALF,0, 256,1, 3, 1.f,0, nullptr, Pb, NS, NELEM, NS, nullptr, rsum2);
    TC(0, dim3(2,16,8), Pb,NS,NELEM, qkv+256+LL2,512,-LL2,1, NS,4, 4, 1.f,0, S0, nullptr, 256,0, NS, nullptr,nullptr);
    pv_fin<<<NF/8,256>>>(S0, rsum2, x1, x2, x2b);

    // ---- fork 2: SupCon branch on sB, concurrent with affinity+Sinkhorn ----
    cudaEventRecord(g_si.ev[2], 0);
    cudaStreamWaitEvent(sB, g_si.ev[2], 0);
    fnorm_fast<<<NF/8,256,0,sB>>>(x2, fnb);
    TC(sB, dim3(32,32,1), fnb,256,0, fnb,256,0,0, 256,1, 6, SUPCON_SCALE,0, nullptr, nullptr, 0,0,0, nullptr,nullptr);
    supcon_final<<<NF/256,256,0,sB>>>(esum, psum, lab, hist, dacc);
    cudaEventRecord(g_si.ev[3], sB);

    // ---- affinity + stats + Sinkhorn (stream 0) ----
    TC(0, dim3(2,16,1), x2b,256,0, wT+8*WSZ,256,0,0, 256,1, 0, 1.f,0, nullptr, qb, 256,0,0, nullptr,nullptr);
    TC(0, dim3(16,16,1), qb,256,0, x2b+HALF,256,0,0, 256,1, 5, 1.f,0, S0, nullptr, NS,0,0, nullptr,nullptr);
    expT_kernel<<<dim3(32,32),256>>>(S0, dacc, Eb, EbT);
    sinkhorn_all<<<256,256>>>(Eb, EbT, rv, cvv, lab, dacc);

    cudaStreamWaitEvent(0, g_si.ev[3], 0);   // join: supcon done
    finalize_kernel<<<1,32>>>(dacc, (float*)d_out);
}